// round 1
// baseline (speedup 1.0000x reference)
#include <cuda_runtime.h>
#include <cstdint>

#define B 2
#define T 2048
#define C 1024
#define H 16
#define HD 64
#define BH (B * H)

// ---- scratch (device globals; no runtime allocation allowed) ----
__device__ float g_q[(size_t)BH * T * HD];   // [B,H,T,HD]
__device__ float g_k[(size_t)BH * T * HD];
__device__ float g_v[(size_t)BH * T * HD];
__device__ float g_o[(size_t)B * T * C];     // attention out, [B,T,H*HD]
__device__ float g_wot[(size_t)C * C];       // Wo transposed: g_wot[k][n] = Wo[n][k]

// ---------------------------------------------------------------------------
// Kernel 0: transpose Wo [C,C] -> g_wot so the projection GEMM is coalesced.
// ---------------------------------------------------------------------------
__global__ void transpose_wo_kernel(const float* __restrict__ Wo) {
    __shared__ float tile[32][33];
    int x0 = blockIdx.x * 32;
    int y0 = blockIdx.y * 32;
    int tx = threadIdx.x, ty = threadIdx.y;
#pragma unroll
    for (int i = 0; i < 32; i += 8)
        tile[ty + i][tx] = Wo[(size_t)(y0 + ty + i) * C + x0 + tx];
    __syncthreads();
#pragma unroll
    for (int i = 0; i < 32; i += 8)
        g_wot[(size_t)(x0 + ty + i) * C + y0 + tx] = tile[tx][ty + i];
}

// ---------------------------------------------------------------------------
// Kernel 1: QKV projection.
// q[b,h,t,d] = sum_c x[b,t,c] * Wq[h,c,d]   (same for k, v)
// 64x64 output tile per block, K-chunks of 16, 16x16 threads, 4x4 micro-tile.
// X tile staged transposed in SMEM so the inner loop is 2x LDS.128 + 16 FFMA.
// ---------------------------------------------------------------------------
__global__ void __launch_bounds__(256) qkv_kernel(
    const float* __restrict__ x,
    const float* __restrict__ Wq,
    const float* __restrict__ Wk,
    const float* __restrict__ Wv)
{
    __shared__ float XsT[16][68];   // [k][row] (padded: 2-way max on store)
    __shared__ float Ws[16][64];    // [k][col]

    int bh = blockIdx.z;
    int b  = bh >> 4;
    int h  = bh & 15;
    int t0 = blockIdx.x * 64;

    const float* W;
    float* out;
    if (blockIdx.y == 0)      { W = Wq; out = g_q; }
    else if (blockIdx.y == 1) { W = Wk; out = g_k; }
    else                      { W = Wv; out = g_v; }
    W += (size_t)h * C * HD;
    out += ((size_t)bh * T + t0) * HD;
    const float* X = x + ((size_t)b * T + t0) * C;

    int tx = threadIdx.x, ty = threadIdx.y;
    int tid = ty * 16 + tx;

    float acc[4][4] = {};

    for (int k0 = 0; k0 < C; k0 += 16) {
        // load X tile 64x16 (transposed into XsT)
#pragma unroll
        for (int it = 0; it < 4; it++) {
            int i = tid + it * 256;
            int r = i >> 4, c = i & 15;
            XsT[c][r] = X[(size_t)r * C + k0 + c];
        }
        // load W tile 16x64
#pragma unroll
        for (int it = 0; it < 4; it++) {
            int i = tid + it * 256;
            int r = i >> 6, c = i & 63;
            Ws[r][c] = W[(size_t)(k0 + r) * HD + c];
        }
        __syncthreads();
#pragma unroll
        for (int kk = 0; kk < 16; kk++) {
            float4 a4 = *(const float4*)&XsT[kk][ty * 4];
            float4 b4 = *(const float4*)&Ws[kk][tx * 4];
            float a[4] = {a4.x, a4.y, a4.z, a4.w};
            float bb[4] = {b4.x, b4.y, b4.z, b4.w};
#pragma unroll
            for (int i = 0; i < 4; i++)
#pragma unroll
                for (int j = 0; j < 4; j++)
                    acc[i][j] += a[i] * bb[j];
        }
        __syncthreads();
    }

#pragma unroll
    for (int i = 0; i < 4; i++) {
        float4 o = make_float4(acc[i][0], acc[i][1], acc[i][2], acc[i][3]);
        *(float4*)&out[(size_t)(ty * 4 + i) * HD + tx * 4] = o;
    }
}

// ---------------------------------------------------------------------------
// Kernel 2: causal flash attention.
// One block = (128 query rows, one (b,h)). One thread = one query row.
// K/V tiles of 64 rows staged in SMEM; online softmax in 16-key chunks
// (scores live in 16 registers; acc rescale overhead = 64 mults / 2048 FMA).
// Writes directly into [B,T,H*HD] layout for the output projection.
// ---------------------------------------------------------------------------
#define BQ 128
#define BK 64

__global__ void __launch_bounds__(128) attn_kernel() {
    __shared__ float Ks[BK][HD];
    __shared__ float Vs[BK][HD];

    int bh = blockIdx.y;
    int t0 = blockIdx.x * BQ;
    int tid = threadIdx.x;
    int t = t0 + tid;

    const float* qptr = g_q + ((size_t)bh * T + t) * HD;
    const float* kbase = g_k + (size_t)bh * T * HD;
    const float* vbase = g_v + (size_t)bh * T * HD;

    float q[HD];
#pragma unroll
    for (int d4 = 0; d4 < HD / 4; d4++) {
        float4 v = *(const float4*)&qptr[d4 * 4];
        q[d4 * 4 + 0] = v.x; q[d4 * 4 + 1] = v.y;
        q[d4 * 4 + 2] = v.z; q[d4 * 4 + 3] = v.w;
    }

    const float scale = 0.125f;  // 1/sqrt(64)
    float acc[HD] = {};
    float m = -1e30f, l = 0.f;

    for (int s0 = 0; s0 <= t0 + BQ - BK; s0 += BK) {
        __syncthreads();  // protect previous tile reads before overwrite
        // cooperative K/V tile load: 64 rows x 16 float4 = 1024 float4 / 128 thr
#pragma unroll
        for (int it = 0; it < 8; it++) {
            int f = tid + it * 128;
            int r = f >> 4, c4 = f & 15;
            ((float4*)&Ks[r][0])[c4] = ((const float4*)&kbase[(size_t)(s0 + r) * HD])[c4];
            ((float4*)&Vs[r][0])[c4] = ((const float4*)&vbase[(size_t)(s0 + r) * HD])[c4];
        }
        __syncthreads();

#pragma unroll
        for (int jc = 0; jc < BK; jc += 16) {
            if (s0 + jc > t) break;  // per-thread skip (no syncs inside)
            float sc[16];
#pragma unroll
            for (int j = 0; j < 16; j++) {
                float s = 0.f;
#pragma unroll
                for (int d4 = 0; d4 < 16; d4++) {
                    float4 k4 = *(const float4*)&Ks[jc + j][d4 * 4];
                    s += q[d4 * 4 + 0] * k4.x + q[d4 * 4 + 1] * k4.y
                       + q[d4 * 4 + 2] * k4.z + q[d4 * 4 + 3] * k4.w;
                }
                s *= scale;
                sc[j] = (s0 + jc + j <= t) ? s : -1e30f;
            }
            float cmax = sc[0];
#pragma unroll
            for (int j = 1; j < 16; j++) cmax = fmaxf(cmax, sc[j]);
            float m_new = fmaxf(m, cmax);
            float corr = __expf(m - m_new);
            l *= corr;
#pragma unroll
            for (int d = 0; d < HD; d++) acc[d] *= corr;
            m = m_new;
#pragma unroll
            for (int j = 0; j < 16; j++) {
                float p = __expf(sc[j] - m_new);
                l += p;
#pragma unroll
                for (int d4 = 0; d4 < 16; d4++) {
                    float4 v4 = *(const float4*)&Vs[jc + j][d4 * 4];
                    acc[d4 * 4 + 0] += p * v4.x;
                    acc[d4 * 4 + 1] += p * v4.y;
                    acc[d4 * 4 + 2] += p * v4.z;
                    acc[d4 * 4 + 3] += p * v4.w;
                }
            }
        }
    }

    float inv = 1.f / l;
    float* optr = g_o + ((size_t)(bh >> 4) * T + t) * C + (bh & 15) * HD;
#pragma unroll
    for (int d4 = 0; d4 < 16; d4++) {
        float4 o = make_float4(acc[4 * d4 + 0] * inv, acc[4 * d4 + 1] * inv,
                               acc[4 * d4 + 2] * inv, acc[4 * d4 + 3] * inv);
        *(float4*)&optr[d4 * 4] = o;
    }
}

// ---------------------------------------------------------------------------
// Kernel 3: output projection. y[m,n] = sum_k g_o[m,k] * g_wot[k,n] + bo[n]
// Same tiling as qkv_kernel; M = B*T = 4096, N = K = C = 1024.
// ---------------------------------------------------------------------------
__global__ void __launch_bounds__(256) proj_kernel(
    const float* __restrict__ bo, float* __restrict__ Y)
{
    __shared__ float XsT[16][68];
    __shared__ float Ws[16][64];

    int n0 = blockIdx.x * 64;
    int m0 = blockIdx.y * 64;

    int tx = threadIdx.x, ty = threadIdx.y;
    int tid = ty * 16 + tx;

    float acc[4][4] = {};

    for (int k0 = 0; k0 < C; k0 += 16) {
#pragma unroll
        for (int it = 0; it < 4; it++) {
            int i = tid + it * 256;
            int r = i >> 4, c = i & 15;
            XsT[c][r] = g_o[(size_t)(m0 + r) * C + k0 + c];
        }
#pragma unroll
        for (int it = 0; it < 4; it++) {
            int i = tid + it * 256;
            int r = i >> 6, c = i & 63;
            Ws[r][c] = g_wot[(size_t)(k0 + r) * C + n0 + c];
        }
        __syncthreads();
#pragma unroll
        for (int kk = 0; kk < 16; kk++) {
            float4 a4 = *(const float4*)&XsT[kk][ty * 4];
            float4 b4 = *(const float4*)&Ws[kk][tx * 4];
            float a[4] = {a4.x, a4.y, a4.z, a4.w};
            float bb[4] = {b4.x, b4.y, b4.z, b4.w};
#pragma unroll
            for (int i = 0; i < 4; i++)
#pragma unroll
                for (int j = 0; j < 4; j++)
                    acc[i][j] += a[i] * bb[j];
        }
        __syncthreads();
    }

#pragma unroll
    for (int i = 0; i < 4; i++) {
        int n = n0 + tx * 4;
        float4 o = make_float4(acc[i][0] + bo[n + 0], acc[i][1] + bo[n + 1],
                               acc[i][2] + bo[n + 2], acc[i][3] + bo[n + 3]);
        *(float4*)&Y[(size_t)(m0 + ty * 4 + i) * C + n] = o;
    }
}

// ---------------------------------------------------------------------------
extern "C" void kernel_launch(void* const* d_in, const int* in_sizes, int n_in,
                              void* d_out, int out_size)
{
    const float* x  = (const float*)d_in[0];
    const float* Wq = (const float*)d_in[1];
    const float* Wk = (const float*)d_in[2];
    const float* Wv = (const float*)d_in[3];
    const float* Wo = (const float*)d_in[4];
    const float* bo = (const float*)d_in[5];
    float* y = (float*)d_out;

    transpose_wo_kernel<<<dim3(C / 32, C / 32), dim3(32, 8)>>>(Wo);
    qkv_kernel<<<dim3(T / 64, 3, BH), dim3(16, 16)>>>(x, Wq, Wk, Wv);
    attn_kernel<<<dim3(T / BQ, BH), 128>>>();
    proj_kernel<<<dim3(C / 64, (B * T) / 64), dim3(16, 16)>>>(bo, y);
}

// round 2
// speedup vs baseline: 1.7264x; 1.7264x over previous
#include <cuda_runtime.h>
#include <cstdint>

#define B 2
#define T 2048
#define C 1024
#define H 16
#define HD 64
#define BH (B * H)

// ---- scratch (device globals; no runtime allocation allowed) ----
__device__ float g_q[(size_t)BH * T * HD];   // [B,H,T,HD]
__device__ float g_k[(size_t)BH * T * HD];
__device__ float g_v[(size_t)BH * T * HD];
__device__ float g_o[(size_t)B * T * C];     // attention out, [B,T,H*HD]
__device__ float g_wot[(size_t)C * C];       // Wo transposed

// ---------------------------------------------------------------------------
// Kernel 0: transpose Wo [C,C] -> g_wot so the projection GEMM is coalesced.
// ---------------------------------------------------------------------------
__global__ void transpose_wo_kernel(const float* __restrict__ Wo) {
    __shared__ float tile[32][33];
    int x0 = blockIdx.x * 32;
    int y0 = blockIdx.y * 32;
    int tx = threadIdx.x, ty = threadIdx.y;
#pragma unroll
    for (int i = 0; i < 32; i += 8)
        tile[ty + i][tx] = Wo[(size_t)(y0 + ty + i) * C + x0 + tx];
    __syncthreads();
#pragma unroll
    for (int i = 0; i < 32; i += 8)
        g_wot[(size_t)(x0 + ty + i) * C + y0 + tx] = tile[tx][ty + i];
}

// ---------------------------------------------------------------------------
// Kernel 1: QKV projection (at fp32 FFMA peak already).
// ---------------------------------------------------------------------------
__global__ void __launch_bounds__(256) qkv_kernel(
    const float* __restrict__ x,
    const float* __restrict__ Wq,
    const float* __restrict__ Wk,
    const float* __restrict__ Wv)
{
    __shared__ float XsT[16][68];
    __shared__ float Ws[16][64];

    int bh = blockIdx.z;
    int b  = bh >> 4;
    int h  = bh & 15;
    int t0 = blockIdx.x * 64;

    const float* W;
    float* out;
    if (blockIdx.y == 0)      { W = Wq; out = g_q; }
    else if (blockIdx.y == 1) { W = Wk; out = g_k; }
    else                      { W = Wv; out = g_v; }
    W += (size_t)h * C * HD;
    out += ((size_t)bh * T + t0) * HD;
    const float* X = x + ((size_t)b * T + t0) * C;

    int tx = threadIdx.x, ty = threadIdx.y;
    int tid = ty * 16 + tx;

    float acc[4][4] = {};

    for (int k0 = 0; k0 < C; k0 += 16) {
#pragma unroll
        for (int it = 0; it < 4; it++) {
            int i = tid + it * 256;
            int r = i >> 4, c = i & 15;
            XsT[c][r] = X[(size_t)r * C + k0 + c];
        }
#pragma unroll
        for (int it = 0; it < 4; it++) {
            int i = tid + it * 256;
            int r = i >> 6, c = i & 63;
            Ws[r][c] = W[(size_t)(k0 + r) * HD + c];
        }
        __syncthreads();
#pragma unroll
        for (int kk = 0; kk < 16; kk++) {
            float4 a4 = *(const float4*)&XsT[kk][ty * 4];
            float4 b4 = *(const float4*)&Ws[kk][tx * 4];
            float a[4] = {a4.x, a4.y, a4.z, a4.w};
            float bb[4] = {b4.x, b4.y, b4.z, b4.w};
#pragma unroll
            for (int i = 0; i < 4; i++)
#pragma unroll
                for (int j = 0; j < 4; j++)
                    acc[i][j] += a[i] * bb[j];
        }
        __syncthreads();
    }

#pragma unroll
    for (int i = 0; i < 4; i++) {
        float4 o = make_float4(acc[i][0], acc[i][1], acc[i][2], acc[i][3]);
        *(float4*)&out[(size_t)(ty * 4 + i) * HD + tx * 4] = o;
    }
}

// ---------------------------------------------------------------------------
// Kernel 2: causal flash attention, block-tiled two-GEMM version.
// Block = 256 threads, 64 query rows x full HD. Per KV tile (64 keys):
//   S = Q*K^T as register-tiled GEMM (4x4 micro-tile per thread),
//   online softmax with 16-lane shfl_xor row reductions,
//   P staged to SMEM, O += P*V as second register-tiled GEMM.
// Register state ~40 floats/thread (vs ~150 in the old row-per-thread kernel).
// ---------------------------------------------------------------------------
#define AQ 64
#define AK 64

__global__ void __launch_bounds__(256) attn_kernel() {
    __shared__ float QsT[HD][AQ + 4];   // [d][i]
    __shared__ float KsT[HD][AK + 4];   // [d][j]
    __shared__ float Vs[AK][HD + 4];    // [j][d]
    __shared__ float Ps[AK][AQ + 4];    // [j][i]

    int bh = blockIdx.y;
    int qt = gridDim.x - 1 - blockIdx.x;   // heavy (late) q-tiles scheduled first
    int t0 = qt * AQ;
    int tid = threadIdx.x;
    int tx = tid & 15, ty = tid >> 4;

    const float* qbase = g_q + ((size_t)bh * T + t0) * HD;
    const float* kbase = g_k + (size_t)bh * T * HD;
    const float* vbase = g_v + (size_t)bh * T * HD;

    // stage Q tile transposed (once per block): 64 rows x 64 dims
#pragma unroll
    for (int it = 0; it < 4; it++) {
        int f = tid + it * 256;
        int r = f >> 4, c4 = f & 15;
        float4 v = *(const float4*)&qbase[(size_t)r * HD + c4 * 4];
        QsT[c4 * 4 + 0][r] = v.x;
        QsT[c4 * 4 + 1][r] = v.y;
        QsT[c4 * 4 + 2][r] = v.z;
        QsT[c4 * 4 + 3][r] = v.w;
    }

    float m[4] = {-1e30f, -1e30f, -1e30f, -1e30f};
    float l[4] = {};
    float accO[4][4] = {};

    int ntiles = qt + 1;
    for (int itile = 0; itile < ntiles; itile++) {
        int s0 = itile * AK;
        __syncthreads();   // prior-iteration reads of KsT/Vs/Ps done
        // load K transposed, V natural
#pragma unroll
        for (int it = 0; it < 4; it++) {
            int f = tid + it * 256;
            int r = f >> 4, c4 = f & 15;
            float4 kv = *(const float4*)&kbase[(size_t)(s0 + r) * HD + c4 * 4];
            KsT[c4 * 4 + 0][r] = kv.x;
            KsT[c4 * 4 + 1][r] = kv.y;
            KsT[c4 * 4 + 2][r] = kv.z;
            KsT[c4 * 4 + 3][r] = kv.w;
            *(float4*)&Vs[r][c4 * 4] = *(const float4*)&vbase[(size_t)(s0 + r) * HD + c4 * 4];
        }
        __syncthreads();

        // S GEMM: s[i][j] = sum_d Q[i][d] K[j][d]
        float s[4][4] = {};
#pragma unroll
        for (int d = 0; d < HD; d++) {
            float4 a4 = *(const float4*)&QsT[d][ty * 4];
            float4 b4 = *(const float4*)&KsT[d][tx * 4];
            float a[4] = {a4.x, a4.y, a4.z, a4.w};
            float bb[4] = {b4.x, b4.y, b4.z, b4.w};
#pragma unroll
            for (int i = 0; i < 4; i++)
#pragma unroll
                for (int j = 0; j < 4; j++)
                    s[i][j] += a[i] * bb[j];
        }

        // scale + causal mask (only the diagonal tile needs masking)
        bool diag = (s0 == t0);
#pragma unroll
        for (int i = 0; i < 4; i++)
#pragma unroll
            for (int j = 0; j < 4; j++) {
                float sv = s[i][j] * 0.125f;
                if (diag && (tx * 4 + j > ty * 4 + i)) sv = -1e30f;
                s[i][j] = sv;
            }

        // online softmax: row groups are the 16 lanes sharing ty (lane&15 == tx)
#pragma unroll
        for (int i = 0; i < 4; i++) {
            float rmax = fmaxf(fmaxf(s[i][0], s[i][1]), fmaxf(s[i][2], s[i][3]));
#pragma unroll
            for (int ofs = 1; ofs < 16; ofs <<= 1)
                rmax = fmaxf(rmax, __shfl_xor_sync(0xffffffffu, rmax, ofs));
            float mn = fmaxf(m[i], rmax);
            float corr = __expf(m[i] - mn);
            m[i] = mn;
            float rs = 0.f;
#pragma unroll
            for (int j = 0; j < 4; j++) {
                float p = __expf(s[i][j] - mn);
                s[i][j] = p;
                rs += p;
            }
#pragma unroll
            for (int ofs = 1; ofs < 16; ofs <<= 1)
                rs += __shfl_xor_sync(0xffffffffu, rs, ofs);
            l[i] = l[i] * corr + rs;
#pragma unroll
            for (int d = 0; d < 4; d++) accO[i][d] *= corr;
        }

        // stage P (k-major: Ps[j][i]) for the PV GEMM
#pragma unroll
        for (int i = 0; i < 4; i++)
#pragma unroll
            for (int j = 0; j < 4; j++)
                Ps[tx * 4 + j][ty * 4 + i] = s[i][j];
        __syncthreads();

        // PV GEMM: O[i][d] += sum_j P[i][j] V[j][d]
#pragma unroll
        for (int j = 0; j < AK; j++) {
            float4 p4 = *(const float4*)&Ps[j][ty * 4];
            float4 v4 = *(const float4*)&Vs[j][tx * 4];
            float p[4] = {p4.x, p4.y, p4.z, p4.w};
            float vv[4] = {v4.x, v4.y, v4.z, v4.w};
#pragma unroll
            for (int i = 0; i < 4; i++)
#pragma unroll
                for (int d = 0; d < 4; d++)
                    accO[i][d] += p[i] * vv[d];
        }
    }

    // epilogue: normalize and write in [B,T,H*HD] layout
    int b = bh >> 4, h = bh & 15;
#pragma unroll
    for (int i = 0; i < 4; i++) {
        float inv = 1.f / l[i];
        float4 o = make_float4(accO[i][0] * inv, accO[i][1] * inv,
                               accO[i][2] * inv, accO[i][3] * inv);
        *(float4*)&g_o[((size_t)b * T + t0 + ty * 4 + i) * C + h * HD + tx * 4] = o;
    }
}

// ---------------------------------------------------------------------------
// Kernel 3: output projection (at fp32 FFMA peak already).
// ---------------------------------------------------------------------------
__global__ void __launch_bounds__(256) proj_kernel(
    const float* __restrict__ bo, float* __restrict__ Y)
{
    __shared__ float XsT[16][68];
    __shared__ float Ws[16][64];

    int n0 = blockIdx.x * 64;
    int m0 = blockIdx.y * 64;

    int tx = threadIdx.x, ty = threadIdx.y;
    int tid = ty * 16 + tx;

    float acc[4][4] = {};

    for (int k0 = 0; k0 < C; k0 += 16) {
#pragma unroll
        for (int it = 0; it < 4; it++) {
            int i = tid + it * 256;
            int r = i >> 4, c = i & 15;
            XsT[c][r] = g_o[(size_t)(m0 + r) * C + k0 + c];
        }
#pragma unroll
        for (int it = 0; it < 4; it++) {
            int i = tid + it * 256;
            int r = i >> 6, c = i & 63;
            Ws[r][c] = g_wot[(size_t)(k0 + r) * C + n0 + c];
        }
        __syncthreads();
#pragma unroll
        for (int kk = 0; kk < 16; kk++) {
            float4 a4 = *(const float4*)&XsT[kk][ty * 4];
            float4 b4 = *(const float4*)&Ws[kk][tx * 4];
            float a[4] = {a4.x, a4.y, a4.z, a4.w};
            float bb[4] = {b4.x, b4.y, b4.z, b4.w};
#pragma unroll
            for (int i = 0; i < 4; i++)
#pragma unroll
                for (int j = 0; j < 4; j++)
                    acc[i][j] += a[i] * bb[j];
        }
        __syncthreads();
    }

#pragma unroll
    for (int i = 0; i < 4; i++) {
        int n = n0 + tx * 4;
        float4 o = make_float4(acc[i][0] + bo[n + 0], acc[i][1] + bo[n + 1],
                               acc[i][2] + bo[n + 2], acc[i][3] + bo[n + 3]);
        *(float4*)&Y[(size_t)(m0 + ty * 4 + i) * C + n] = o;
    }
}

// ---------------------------------------------------------------------------
extern "C" void kernel_launch(void* const* d_in, const int* in_sizes, int n_in,
                              void* d_out, int out_size)
{
    const float* x  = (const float*)d_in[0];
    const float* Wq = (const float*)d_in[1];
    const float* Wk = (const float*)d_in[2];
    const float* Wv = (const float*)d_in[3];
    const float* Wo = (const float*)d_in[4];
    const float* bo = (const float*)d_in[5];
    float* y = (float*)d_out;

    transpose_wo_kernel<<<dim3(C / 32, C / 32), dim3(32, 8)>>>(Wo);
    qkv_kernel<<<dim3(T / 64, 3, BH), dim3(16, 16)>>>(x, Wq, Wk, Wv);
    attn_kernel<<<dim3(T / AQ, BH), 256>>>();
    proj_kernel<<<dim3(C / 64, (B * T) / 64), dim3(16, 16)>>>(bo, y);
}

// round 3
// speedup vs baseline: 2.6821x; 1.5536x over previous
#include <cuda_runtime.h>
#include <cstdint>

#define B 2
#define T 2048
#define C 1024
#define H 16
#define HD 64
#define BH (B * H)

// ---- scratch (device globals; no runtime allocation allowed) ----
__device__ float g_q[(size_t)BH * T * HD];   // [B,H,T,HD]
__device__ float g_k[(size_t)BH * T * HD];
__device__ float g_v[(size_t)BH * T * HD];
__device__ float g_o[(size_t)B * T * C];     // attention out, [B,T,H*HD]
__device__ float g_wot[(size_t)C * C];       // Wo transposed

// ---------------------------------------------------------------------------
// helpers: tf32 convert + m16n8k8 tf32 mma
// ---------------------------------------------------------------------------
__device__ __forceinline__ unsigned f2tf32(float x) {
    unsigned r;
    asm("cvt.rna.tf32.f32 %0, %1;" : "=r"(r) : "f"(x));
    return r;
}

__device__ __forceinline__ void mma_tf32(float c[4], const unsigned a[4], const unsigned b[2]) {
    asm("mma.sync.aligned.m16n8k8.row.col.f32.tf32.tf32.f32 "
        "{%0,%1,%2,%3},{%4,%5,%6,%7},{%8,%9},{%0,%1,%2,%3};"
        : "+f"(c[0]), "+f"(c[1]), "+f"(c[2]), "+f"(c[3])
        : "r"(a[0]), "r"(a[1]), "r"(a[2]), "r"(a[3]), "r"(b[0]), "r"(b[1]));
}

#define LDA 36   // A smem row pitch (floats): bank stride 4 -> conflict-free frags
#define LDB 72   // B smem row pitch (floats): bank stride 8 -> conflict-free frags

// ---------------------------------------------------------------------------
// Kernel 0: transpose Wo [C,C] -> g_wot so the projection GEMM is coalesced.
// ---------------------------------------------------------------------------
__global__ void transpose_wo_kernel(const float* __restrict__ Wo) {
    __shared__ float tile[32][33];
    int x0 = blockIdx.x * 32;
    int y0 = blockIdx.y * 32;
    int tx = threadIdx.x, ty = threadIdx.y;
#pragma unroll
    for (int i = 0; i < 32; i += 8)
        tile[ty + i][tx] = Wo[(size_t)(y0 + ty + i) * C + x0 + tx];
    __syncthreads();
#pragma unroll
    for (int i = 0; i < 32; i += 8)
        g_wot[(size_t)(x0 + ty + i) * C + y0 + tx] = tile[tx][ty + i];
}

// ---------------------------------------------------------------------------
// Kernel 1: QKV projection, tf32 tensor cores.
// Block 128 thr = 4 warps; block tile 64(M)x64(N); warp tile 32x32
// (2 x m16 subtiles, 4 x n8 subtiles); K-chunks of 32.
// ---------------------------------------------------------------------------
__global__ void __launch_bounds__(128) qkv_tf32_kernel(
    const float* __restrict__ x,
    const float* __restrict__ Wq,
    const float* __restrict__ Wk,
    const float* __restrict__ Wv)
{
    __shared__ unsigned As[64][LDA];   // [m][k], tf32
    __shared__ unsigned Bs[32][LDB];   // [k][n], tf32

    int bh = blockIdx.z;
    int b  = bh >> 4;
    int h  = bh & 15;
    int t0 = blockIdx.x * 64;

    const float* W;
    float* out;
    if (blockIdx.y == 0)      { W = Wq; out = g_q; }
    else if (blockIdx.y == 1) { W = Wk; out = g_k; }
    else                      { W = Wv; out = g_v; }
    W += (size_t)h * C * HD;
    out += ((size_t)bh * T + t0) * HD;
    const float* A = x + ((size_t)b * T + t0) * C;

    int tid = threadIdx.x;
    int lane = tid & 31, w = tid >> 5;
    int g = lane >> 2, tq = lane & 3;
    int wm = (w >> 1) * 32, wn = (w & 1) * 32;

    float acc[2][4][4] = {};

    for (int k0 = 0; k0 < C; k0 += 32) {
        __syncthreads();
        // A tile: 64 x 32
#pragma unroll
        for (int it = 0; it < 4; it++) {
            int f = tid + it * 128;
            int r = f >> 3, c4 = f & 7;
            float4 v = *(const float4*)&A[(size_t)r * C + k0 + c4 * 4];
            As[r][c4 * 4 + 0] = f2tf32(v.x);
            As[r][c4 * 4 + 1] = f2tf32(v.y);
            As[r][c4 * 4 + 2] = f2tf32(v.z);
            As[r][c4 * 4 + 3] = f2tf32(v.w);
        }
        // B tile: 32 x 64 (W rows k0..k0+31)
#pragma unroll
        for (int it = 0; it < 4; it++) {
            int f = tid + it * 128;
            int r = f >> 4, c4 = f & 15;
            float4 v = *(const float4*)&W[(size_t)(k0 + r) * HD + c4 * 4];
            Bs[r][c4 * 4 + 0] = f2tf32(v.x);
            Bs[r][c4 * 4 + 1] = f2tf32(v.y);
            Bs[r][c4 * 4 + 2] = f2tf32(v.z);
            Bs[r][c4 * 4 + 3] = f2tf32(v.w);
        }
        __syncthreads();

#pragma unroll
        for (int kk = 0; kk < 32; kk += 8) {
            unsigned af[2][4], bf[4][2];
#pragma unroll
            for (int sm = 0; sm < 2; sm++) {
                int rb = wm + sm * 16;
                af[sm][0] = As[rb + g][kk + tq];
                af[sm][1] = As[rb + g + 8][kk + tq];
                af[sm][2] = As[rb + g][kk + tq + 4];
                af[sm][3] = As[rb + g + 8][kk + tq + 4];
            }
#pragma unroll
            for (int sn = 0; sn < 4; sn++) {
                int nb = wn + sn * 8;
                bf[sn][0] = Bs[kk + tq][nb + g];
                bf[sn][1] = Bs[kk + tq + 4][nb + g];
            }
#pragma unroll
            for (int sm = 0; sm < 2; sm++)
#pragma unroll
                for (int sn = 0; sn < 4; sn++)
                    mma_tf32(acc[sm][sn], af[sm], bf[sn]);
        }
    }

#pragma unroll
    for (int sm = 0; sm < 2; sm++) {
        int r0 = wm + sm * 16 + g;
#pragma unroll
        for (int sn = 0; sn < 4; sn++) {
            int cc = wn + sn * 8 + tq * 2;
            *(float2*)&out[(size_t)r0 * HD + cc] = make_float2(acc[sm][sn][0], acc[sm][sn][1]);
            *(float2*)&out[(size_t)(r0 + 8) * HD + cc] = make_float2(acc[sm][sn][2], acc[sm][sn][3]);
        }
    }
}

// ---------------------------------------------------------------------------
// Kernel 2: causal flash attention (fp32, unchanged from R2 - next target).
// ---------------------------------------------------------------------------
#define AQ 64
#define AK 64

__global__ void __launch_bounds__(256) attn_kernel() {
    __shared__ float QsT[HD][AQ + 4];
    __shared__ float KsT[HD][AK + 4];
    __shared__ float Vs[AK][HD + 4];
    __shared__ float Ps[AK][AQ + 4];

    int bh = blockIdx.y;
    int qt = gridDim.x - 1 - blockIdx.x;
    int t0 = qt * AQ;
    int tid = threadIdx.x;
    int tx = tid & 15, ty = tid >> 4;

    const float* qbase = g_q + ((size_t)bh * T + t0) * HD;
    const float* kbase = g_k + (size_t)bh * T * HD;
    const float* vbase = g_v + (size_t)bh * T * HD;

#pragma unroll
    for (int it = 0; it < 4; it++) {
        int f = tid + it * 256;
        int r = f >> 4, c4 = f & 15;
        float4 v = *(const float4*)&qbase[(size_t)r * HD + c4 * 4];
        QsT[c4 * 4 + 0][r] = v.x;
        QsT[c4 * 4 + 1][r] = v.y;
        QsT[c4 * 4 + 2][r] = v.z;
        QsT[c4 * 4 + 3][r] = v.w;
    }

    float m[4] = {-1e30f, -1e30f, -1e30f, -1e30f};
    float l[4] = {};
    float accO[4][4] = {};

    int ntiles = qt + 1;
    for (int itile = 0; itile < ntiles; itile++) {
        int s0 = itile * AK;
        __syncthreads();
#pragma unroll
        for (int it = 0; it < 4; it++) {
            int f = tid + it * 256;
            int r = f >> 4, c4 = f & 15;
            float4 kv = *(const float4*)&kbase[(size_t)(s0 + r) * HD + c4 * 4];
            KsT[c4 * 4 + 0][r] = kv.x;
            KsT[c4 * 4 + 1][r] = kv.y;
            KsT[c4 * 4 + 2][r] = kv.z;
            KsT[c4 * 4 + 3][r] = kv.w;
            *(float4*)&Vs[r][c4 * 4] = *(const float4*)&vbase[(size_t)(s0 + r) * HD + c4 * 4];
        }
        __syncthreads();

        float s[4][4] = {};
#pragma unroll
        for (int d = 0; d < HD; d++) {
            float4 a4 = *(const float4*)&QsT[d][ty * 4];
            float4 b4 = *(const float4*)&KsT[d][tx * 4];
            float a[4] = {a4.x, a4.y, a4.z, a4.w};
            float bb[4] = {b4.x, b4.y, b4.z, b4.w};
#pragma unroll
            for (int i = 0; i < 4; i++)
#pragma unroll
                for (int j = 0; j < 4; j++)
                    s[i][j] += a[i] * bb[j];
        }

        bool diag = (s0 == t0);
#pragma unroll
        for (int i = 0; i < 4; i++)
#pragma unroll
            for (int j = 0; j < 4; j++) {
                float sv = s[i][j] * 0.125f;
                if (diag && (tx * 4 + j > ty * 4 + i)) sv = -1e30f;
                s[i][j] = sv;
            }

#pragma unroll
        for (int i = 0; i < 4; i++) {
            float rmax = fmaxf(fmaxf(s[i][0], s[i][1]), fmaxf(s[i][2], s[i][3]));
#pragma unroll
            for (int ofs = 1; ofs < 16; ofs <<= 1)
                rmax = fmaxf(rmax, __shfl_xor_sync(0xffffffffu, rmax, ofs));
            float mn = fmaxf(m[i], rmax);
            float corr = __expf(m[i] - mn);
            m[i] = mn;
            float rs = 0.f;
#pragma unroll
            for (int j = 0; j < 4; j++) {
                float p = __expf(s[i][j] - mn);
                s[i][j] = p;
                rs += p;
            }
#pragma unroll
            for (int ofs = 1; ofs < 16; ofs <<= 1)
                rs += __shfl_xor_sync(0xffffffffu, rs, ofs);
            l[i] = l[i] * corr + rs;
#pragma unroll
            for (int d = 0; d < 4; d++) accO[i][d] *= corr;
        }

#pragma unroll
        for (int i = 0; i < 4; i++)
#pragma unroll
            for (int j = 0; j < 4; j++)
                Ps[tx * 4 + j][ty * 4 + i] = s[i][j];
        __syncthreads();

#pragma unroll
        for (int j = 0; j < AK; j++) {
            float4 p4 = *(const float4*)&Ps[j][ty * 4];
            float4 v4 = *(const float4*)&Vs[j][tx * 4];
            float p[4] = {p4.x, p4.y, p4.z, p4.w};
            float vv[4] = {v4.x, v4.y, v4.z, v4.w};
#pragma unroll
            for (int i = 0; i < 4; i++)
#pragma unroll
                for (int d = 0; d < 4; d++)
                    accO[i][d] += p[i] * vv[d];
        }
    }

    int b = bh >> 4, h = bh & 15;
#pragma unroll
    for (int i = 0; i < 4; i++) {
        float inv = 1.f / l[i];
        float4 o = make_float4(accO[i][0] * inv, accO[i][1] * inv,
                               accO[i][2] * inv, accO[i][3] * inv);
        *(float4*)&g_o[((size_t)b * T + t0 + ty * 4 + i) * C + h * HD + tx * 4] = o;
    }
}

// ---------------------------------------------------------------------------
// Kernel 3: output projection, tf32 tensor cores. Same structure as qkv.
// ---------------------------------------------------------------------------
__global__ void __launch_bounds__(128) proj_tf32_kernel(
    const float* __restrict__ bo, float* __restrict__ Y)
{
    __shared__ unsigned As[64][LDA];
    __shared__ unsigned Bs[32][LDB];

    int n0 = blockIdx.x * 64;
    int m0 = blockIdx.y * 64;

    const float* A = g_o + (size_t)m0 * C;

    int tid = threadIdx.x;
    int lane = tid & 31, w = tid >> 5;
    int g = lane >> 2, tq = lane & 3;
    int wm = (w >> 1) * 32, wn = (w & 1) * 32;

    float acc[2][4][4] = {};

    for (int k0 = 0; k0 < C; k0 += 32) {
        __syncthreads();
#pragma unroll
        for (int it = 0; it < 4; it++) {
            int f = tid + it * 128;
            int r = f >> 3, c4 = f & 7;
            float4 v = *(const float4*)&A[(size_t)r * C + k0 + c4 * 4];
            As[r][c4 * 4 + 0] = f2tf32(v.x);
            As[r][c4 * 4 + 1] = f2tf32(v.y);
            As[r][c4 * 4 + 2] = f2tf32(v.z);
            As[r][c4 * 4 + 3] = f2tf32(v.w);
        }
#pragma unroll
        for (int it = 0; it < 4; it++) {
            int f = tid + it * 128;
            int r = f >> 4, c4 = f & 15;
            float4 v = *(const float4*)&g_wot[(size_t)(k0 + r) * C + n0 + c4 * 4];
            Bs[r][c4 * 4 + 0] = f2tf32(v.x);
            Bs[r][c4 * 4 + 1] = f2tf32(v.y);
            Bs[r][c4 * 4 + 2] = f2tf32(v.z);
            Bs[r][c4 * 4 + 3] = f2tf32(v.w);
        }
        __syncthreads();

#pragma unroll
        for (int kk = 0; kk < 32; kk += 8) {
            unsigned af[2][4], bf[4][2];
#pragma unroll
            for (int sm = 0; sm < 2; sm++) {
                int rb = wm + sm * 16;
                af[sm][0] = As[rb + g][kk + tq];
                af[sm][1] = As[rb + g + 8][kk + tq];
                af[sm][2] = As[rb + g][kk + tq + 4];
                af[sm][3] = As[rb + g + 8][kk + tq + 4];
            }
#pragma unroll
            for (int sn = 0; sn < 4; sn++) {
                int nb = wn + sn * 8;
                bf[sn][0] = Bs[kk + tq][nb + g];
                bf[sn][1] = Bs[kk + tq + 4][nb + g];
            }
#pragma unroll
            for (int sm = 0; sm < 2; sm++)
#pragma unroll
                for (int sn = 0; sn < 4; sn++)
                    mma_tf32(acc[sm][sn], af[sm], bf[sn]);
        }
    }

#pragma unroll
    for (int sm = 0; sm < 2; sm++) {
        int r0 = m0 + wm + sm * 16 + g;
#pragma unroll
        for (int sn = 0; sn < 4; sn++) {
            int cc = n0 + wn + sn * 8 + tq * 2;
            float b0 = bo[cc], b1 = bo[cc + 1];
            *(float2*)&Y[(size_t)r0 * C + cc] =
                make_float2(acc[sm][sn][0] + b0, acc[sm][sn][1] + b1);
            *(float2*)&Y[(size_t)(r0 + 8) * C + cc] =
                make_float2(acc[sm][sn][2] + b0, acc[sm][sn][3] + b1);
        }
    }
}

// ---------------------------------------------------------------------------
extern "C" void kernel_launch(void* const* d_in, const int* in_sizes, int n_in,
                              void* d_out, int out_size)
{
    const float* x  = (const float*)d_in[0];
    const float* Wq = (const float*)d_in[1];
    const float* Wk = (const float*)d_in[2];
    const float* Wv = (const float*)d_in[3];
    const float* Wo = (const float*)d_in[4];
    const float* bo = (const float*)d_in[5];
    float* y = (float*)d_out;

    transpose_wo_kernel<<<dim3(C / 32, C / 32), dim3(32, 8)>>>(Wo);
    qkv_tf32_kernel<<<dim3(T / 64, 3, BH), 128>>>(x, Wq, Wk, Wv);
    attn_kernel<<<dim3(T / AQ, BH), 256>>>();
    proj_tf32_kernel<<<dim3(C / 64, (B * T) / 64), 128>>>(bo, y);
}

// round 4
// speedup vs baseline: 5.0305x; 1.8756x over previous
#include <cuda_runtime.h>
#include <cstdint>

#define B 2
#define T 2048
#define C 1024
#define H 16
#define HD 64
#define BH (B * H)

// ---- scratch (device globals; no runtime allocation allowed) ----
__device__ float g_q[(size_t)BH * T * HD];   // [B,H,T,HD]
__device__ float g_k[(size_t)BH * T * HD];
__device__ float g_v[(size_t)BH * T * HD];
__device__ float g_o[(size_t)B * T * C];     // attention out, [B,T,H*HD]
__device__ float g_wot[(size_t)C * C];       // Wo transposed

// ---------------------------------------------------------------------------
// helpers: tf32 convert + m16n8k8 tf32 mma
// ---------------------------------------------------------------------------
__device__ __forceinline__ unsigned f2tf32(float x) {
    unsigned r;
    asm("cvt.rna.tf32.f32 %0, %1;" : "=r"(r) : "f"(x));
    return r;
}

__device__ __forceinline__ void mma_tf32(float c[4], const unsigned a[4], const unsigned b[2]) {
    asm("mma.sync.aligned.m16n8k8.row.col.f32.tf32.tf32.f32 "
        "{%0,%1,%2,%3},{%4,%5,%6,%7},{%8,%9},{%0,%1,%2,%3};"
        : "+f"(c[0]), "+f"(c[1]), "+f"(c[2]), "+f"(c[3])
        : "r"(a[0]), "r"(a[1]), "r"(a[2]), "r"(a[3]), "r"(b[0]), "r"(b[1]));
}

#define LDA 36   // A smem row pitch (floats): bank stride 4 -> conflict-free frags
#define LDB 72   // B smem row pitch (floats): bank stride 8 -> conflict-free frags

// ---------------------------------------------------------------------------
// Kernel 0: transpose Wo [C,C] -> g_wot so the projection GEMM is coalesced.
// ---------------------------------------------------------------------------
__global__ void transpose_wo_kernel(const float* __restrict__ Wo) {
    __shared__ float tile[32][33];
    int x0 = blockIdx.x * 32;
    int y0 = blockIdx.y * 32;
    int tx = threadIdx.x, ty = threadIdx.y;
#pragma unroll
    for (int i = 0; i < 32; i += 8)
        tile[ty + i][tx] = Wo[(size_t)(y0 + ty + i) * C + x0 + tx];
    __syncthreads();
#pragma unroll
    for (int i = 0; i < 32; i += 8)
        g_wot[(size_t)(x0 + ty + i) * C + y0 + tx] = tile[tx][ty + i];
}

// ---------------------------------------------------------------------------
// Kernel 1: QKV projection, tf32 tensor cores.
// ---------------------------------------------------------------------------
__global__ void __launch_bounds__(128) qkv_tf32_kernel(
    const float* __restrict__ x,
    const float* __restrict__ Wq,
    const float* __restrict__ Wk,
    const float* __restrict__ Wv)
{
    __shared__ unsigned As[64][LDA];   // [m][k], tf32
    __shared__ unsigned Bs[32][LDB];   // [k][n], tf32

    int bh = blockIdx.z;
    int b  = bh >> 4;
    int h  = bh & 15;
    int t0 = blockIdx.x * 64;

    const float* W;
    float* out;
    if (blockIdx.y == 0)      { W = Wq; out = g_q; }
    else if (blockIdx.y == 1) { W = Wk; out = g_k; }
    else                      { W = Wv; out = g_v; }
    W += (size_t)h * C * HD;
    out += ((size_t)bh * T + t0) * HD;
    const float* A = x + ((size_t)b * T + t0) * C;

    int tid = threadIdx.x;
    int lane = tid & 31, w = tid >> 5;
    int g = lane >> 2, tq = lane & 3;
    int wm = (w >> 1) * 32, wn = (w & 1) * 32;

    float acc[2][4][4] = {};

    for (int k0 = 0; k0 < C; k0 += 32) {
        __syncthreads();
#pragma unroll
        for (int it = 0; it < 4; it++) {
            int f = tid + it * 128;
            int r = f >> 3, c4 = f & 7;
            float4 v = *(const float4*)&A[(size_t)r * C + k0 + c4 * 4];
            As[r][c4 * 4 + 0] = f2tf32(v.x);
            As[r][c4 * 4 + 1] = f2tf32(v.y);
            As[r][c4 * 4 + 2] = f2tf32(v.z);
            As[r][c4 * 4 + 3] = f2tf32(v.w);
        }
#pragma unroll
        for (int it = 0; it < 4; it++) {
            int f = tid + it * 128;
            int r = f >> 4, c4 = f & 15;
            float4 v = *(const float4*)&W[(size_t)(k0 + r) * HD + c4 * 4];
            Bs[r][c4 * 4 + 0] = f2tf32(v.x);
            Bs[r][c4 * 4 + 1] = f2tf32(v.y);
            Bs[r][c4 * 4 + 2] = f2tf32(v.z);
            Bs[r][c4 * 4 + 3] = f2tf32(v.w);
        }
        __syncthreads();

#pragma unroll
        for (int kk = 0; kk < 32; kk += 8) {
            unsigned af[2][4], bf[4][2];
#pragma unroll
            for (int sm = 0; sm < 2; sm++) {
                int rb = wm + sm * 16;
                af[sm][0] = As[rb + g][kk + tq];
                af[sm][1] = As[rb + g + 8][kk + tq];
                af[sm][2] = As[rb + g][kk + tq + 4];
                af[sm][3] = As[rb + g + 8][kk + tq + 4];
            }
#pragma unroll
            for (int sn = 0; sn < 4; sn++) {
                int nb = wn + sn * 8;
                bf[sn][0] = Bs[kk + tq][nb + g];
                bf[sn][1] = Bs[kk + tq + 4][nb + g];
            }
#pragma unroll
            for (int sm = 0; sm < 2; sm++)
#pragma unroll
                for (int sn = 0; sn < 4; sn++)
                    mma_tf32(acc[sm][sn], af[sm], bf[sn]);
        }
    }

#pragma unroll
    for (int sm = 0; sm < 2; sm++) {
        int r0 = wm + sm * 16 + g;
#pragma unroll
        for (int sn = 0; sn < 4; sn++) {
            int cc = wn + sn * 8 + tq * 2;
            *(float2*)&out[(size_t)r0 * HD + cc] = make_float2(acc[sm][sn][0], acc[sm][sn][1]);
            *(float2*)&out[(size_t)(r0 + 8) * HD + cc] = make_float2(acc[sm][sn][2], acc[sm][sn][3]);
        }
    }
}

// ---------------------------------------------------------------------------
// Kernel 2: causal flash attention on tf32 tensor cores.
// 128 threads = 4 warps; block = 64 q-rows; warp = 16 q-rows x all 64 keys.
// Per KV tile (64 keys): S = Q*K^T via mma (Q frags resident in registers),
// quad-shfl online softmax, K SMEM reused as P SMEM, O += P*V via mma.
// ---------------------------------------------------------------------------
#define AQ 64
#define AK 64

__global__ void __launch_bounds__(128) attn_tc_kernel() {
    __shared__ float KPs[AK][68];   // K tile (B of S-gemm), reused as P tile (A of PV-gemm)
    __shared__ float Vs[AK][72];    // V tile (B of PV-gemm)

    int bh = blockIdx.y;
    int qt = gridDim.x - 1 - blockIdx.x;   // heavy q-tiles first
    int t0 = qt * AQ;
    int tid = threadIdx.x;
    int lane = tid & 31, w = tid >> 5;
    int g = lane >> 2, tq = lane & 3;
    int wq = w * 16;

    const float* qbase = g_q + ((size_t)bh * T + t0) * HD;
    const float* kbase = g_k + (size_t)bh * T * HD;
    const float* vbase = g_v + (size_t)bh * T * HD;

    // Q fragments resident in registers (softmax scale folded in; exact *2^-3)
    unsigned qf[8][4];
#pragma unroll
    for (int ks = 0; ks < 8; ks++) {
        int k0 = ks * 8;
        qf[ks][0] = f2tf32(0.125f * qbase[(size_t)(wq + g) * HD + k0 + tq]);
        qf[ks][1] = f2tf32(0.125f * qbase[(size_t)(wq + g + 8) * HD + k0 + tq]);
        qf[ks][2] = f2tf32(0.125f * qbase[(size_t)(wq + g) * HD + k0 + tq + 4]);
        qf[ks][3] = f2tf32(0.125f * qbase[(size_t)(wq + g + 8) * HD + k0 + tq + 4]);
    }

    float m0 = -1e30f, m1 = -1e30f, l0 = 0.f, l1 = 0.f;
    float accO[8][4] = {};

    int ntiles = qt + 1;
    for (int itile = 0; itile < ntiles; itile++) {
        int s0 = itile * AK;
        __syncthreads();   // prior tile's reads of KPs/Vs complete
        // stage K (tf32) and V (tf32): 64x64 each, uint4 stores, conflict-free
#pragma unroll
        for (int it = 0; it < 8; it++) {
            int f = tid + it * 128;
            int r = f >> 4, c4 = f & 15;
            float4 kv = *(const float4*)&kbase[(size_t)(s0 + r) * HD + c4 * 4];
            uint4 kt = make_uint4(f2tf32(kv.x), f2tf32(kv.y), f2tf32(kv.z), f2tf32(kv.w));
            *(uint4*)&KPs[r][c4 * 4] = kt;
            float4 vv = *(const float4*)&vbase[(size_t)(s0 + r) * HD + c4 * 4];
            uint4 vt = make_uint4(f2tf32(vv.x), f2tf32(vv.y), f2tf32(vv.z), f2tf32(vv.w));
            *(uint4*)&Vs[r][c4 * 4] = vt;
        }
        __syncthreads();

        // S = Q * K^T : 8 k-steps x 8 n-subtiles
        float sc[8][4] = {};
#pragma unroll
        for (int ks = 0; ks < 8; ks++) {
            unsigned bf[8][2];
#pragma unroll
            for (int sn = 0; sn < 8; sn++) {
                bf[sn][0] = __float_as_uint(KPs[sn * 8 + g][ks * 8 + tq]);
                bf[sn][1] = __float_as_uint(KPs[sn * 8 + g][ks * 8 + tq + 4]);
            }
#pragma unroll
            for (int sn = 0; sn < 8; sn++)
                mma_tf32(sc[sn], qf[ks], bf[sn]);
        }

        // causal mask (diagonal tile only)
        if (itile == ntiles - 1) {
            int r0 = wq + g, r1 = wq + g + 8;
#pragma unroll
            for (int sn = 0; sn < 8; sn++) {
                int c0 = sn * 8 + tq * 2, c1 = c0 + 1;
                if (c0 > r0) sc[sn][0] = -1e30f;
                if (c1 > r0) sc[sn][1] = -1e30f;
                if (c0 > r1) sc[sn][2] = -1e30f;
                if (c1 > r1) sc[sn][3] = -1e30f;
            }
        }

        // online softmax: rows g (c0,c1) and g+8 (c2,c3); quad shfl reduce
        float rx0 = -1e30f, rx1 = -1e30f;
#pragma unroll
        for (int sn = 0; sn < 8; sn++) {
            rx0 = fmaxf(rx0, fmaxf(sc[sn][0], sc[sn][1]));
            rx1 = fmaxf(rx1, fmaxf(sc[sn][2], sc[sn][3]));
        }
        rx0 = fmaxf(rx0, __shfl_xor_sync(0xffffffffu, rx0, 1));
        rx0 = fmaxf(rx0, __shfl_xor_sync(0xffffffffu, rx0, 2));
        rx1 = fmaxf(rx1, __shfl_xor_sync(0xffffffffu, rx1, 1));
        rx1 = fmaxf(rx1, __shfl_xor_sync(0xffffffffu, rx1, 2));
        float mn0 = fmaxf(m0, rx0), mn1 = fmaxf(m1, rx1);
        float corr0 = __expf(m0 - mn0), corr1 = __expf(m1 - mn1);
        m0 = mn0; m1 = mn1;

        float rs0 = 0.f, rs1 = 0.f;
#pragma unroll
        for (int sn = 0; sn < 8; sn++) {
            float p0 = __uint_as_float(f2tf32(__expf(sc[sn][0] - mn0)));
            float p1 = __uint_as_float(f2tf32(__expf(sc[sn][1] - mn0)));
            float p2 = __uint_as_float(f2tf32(__expf(sc[sn][2] - mn1)));
            float p3 = __uint_as_float(f2tf32(__expf(sc[sn][3] - mn1)));
            sc[sn][0] = p0; sc[sn][1] = p1; sc[sn][2] = p2; sc[sn][3] = p3;
            rs0 += p0 + p1;
            rs1 += p2 + p3;
        }
        rs0 += __shfl_xor_sync(0xffffffffu, rs0, 1);
        rs0 += __shfl_xor_sync(0xffffffffu, rs0, 2);
        rs1 += __shfl_xor_sync(0xffffffffu, rs1, 1);
        rs1 += __shfl_xor_sync(0xffffffffu, rs1, 2);
        l0 = l0 * corr0 + rs0;
        l1 = l1 * corr1 + rs1;
#pragma unroll
        for (int sn = 0; sn < 8; sn++) {
            accO[sn][0] *= corr0; accO[sn][1] *= corr0;
            accO[sn][2] *= corr1; accO[sn][3] *= corr1;
        }

        // all warps done reading K from KPs -> safe to overwrite with P
        __syncthreads();
        // each warp stores its OWN 16 P-rows (only it reads them back)
#pragma unroll
        for (int sn = 0; sn < 8; sn++) {
            int cc = sn * 8 + tq * 2;
            KPs[wq + g][cc]     = sc[sn][0];
            KPs[wq + g][cc + 1] = sc[sn][1];
            KPs[wq + g + 8][cc]     = sc[sn][2];
            KPs[wq + g + 8][cc + 1] = sc[sn][3];
        }
        __syncwarp();

        // O += P * V : 8 key-chunks x 8 d-subtiles
#pragma unroll
        for (int kc = 0; kc < 8; kc++) {
            unsigned af[4];
            af[0] = __float_as_uint(KPs[wq + g][kc * 8 + tq]);
            af[1] = __float_as_uint(KPs[wq + g + 8][kc * 8 + tq]);
            af[2] = __float_as_uint(KPs[wq + g][kc * 8 + tq + 4]);
            af[3] = __float_as_uint(KPs[wq + g + 8][kc * 8 + tq + 4]);
#pragma unroll
            for (int sn = 0; sn < 8; sn++) {
                unsigned bf[2];
                bf[0] = __float_as_uint(Vs[kc * 8 + tq][sn * 8 + g]);
                bf[1] = __float_as_uint(Vs[kc * 8 + tq + 4][sn * 8 + g]);
                mma_tf32(accO[sn], af, bf);
            }
        }
    }

    // epilogue: normalize, write to [B,T,H*HD]
    float inv0 = 1.f / l0, inv1 = 1.f / l1;
    int b = bh >> 4, h = bh & 15;
    float* o0 = g_o + ((size_t)b * T + t0 + wq + g) * C + h * HD;
    float* o1 = o0 + (size_t)8 * C;
#pragma unroll
    for (int sn = 0; sn < 8; sn++) {
        int cc = sn * 8 + tq * 2;
        *(float2*)&o0[cc] = make_float2(accO[sn][0] * inv0, accO[sn][1] * inv0);
        *(float2*)&o1[cc] = make_float2(accO[sn][2] * inv1, accO[sn][3] * inv1);
    }
}

// ---------------------------------------------------------------------------
// Kernel 3: output projection, tf32 tensor cores.
// ---------------------------------------------------------------------------
__global__ void __launch_bounds__(128) proj_tf32_kernel(
    const float* __restrict__ bo, float* __restrict__ Y)
{
    __shared__ unsigned As[64][LDA];
    __shared__ unsigned Bs[32][LDB];

    int n0 = blockIdx.x * 64;
    int m0 = blockIdx.y * 64;

    const float* A = g_o + (size_t)m0 * C;

    int tid = threadIdx.x;
    int lane = tid & 31, w = tid >> 5;
    int g = lane >> 2, tq = lane & 3;
    int wm = (w >> 1) * 32, wn = (w & 1) * 32;

    float acc[2][4][4] = {};

    for (int k0 = 0; k0 < C; k0 += 32) {
        __syncthreads();
#pragma unroll
        for (int it = 0; it < 4; it++) {
            int f = tid + it * 128;
            int r = f >> 3, c4 = f & 7;
            float4 v = *(const float4*)&A[(size_t)r * C + k0 + c4 * 4];
            As[r][c4 * 4 + 0] = f2tf32(v.x);
            As[r][c4 * 4 + 1] = f2tf32(v.y);
            As[r][c4 * 4 + 2] = f2tf32(v.z);
            As[r][c4 * 4 + 3] = f2tf32(v.w);
        }
#pragma unroll
        for (int it = 0; it < 4; it++) {
            int f = tid + it * 128;
            int r = f >> 4, c4 = f & 15;
            float4 v = *(const float4*)&g_wot[(size_t)(k0 + r) * C + n0 + c4 * 4];
            Bs[r][c4 * 4 + 0] = f2tf32(v.x);
            Bs[r][c4 * 4 + 1] = f2tf32(v.y);
            Bs[r][c4 * 4 + 2] = f2tf32(v.z);
            Bs[r][c4 * 4 + 3] = f2tf32(v.w);
        }
        __syncthreads();

#pragma unroll
        for (int kk = 0; kk < 32; kk += 8) {
            unsigned af[2][4], bf[4][2];
#pragma unroll
            for (int sm = 0; sm < 2; sm++) {
                int rb = wm + sm * 16;
                af[sm][0] = As[rb + g][kk + tq];
                af[sm][1] = As[rb + g + 8][kk + tq];
                af[sm][2] = As[rb + g][kk + tq + 4];
                af[sm][3] = As[rb + g + 8][kk + tq + 4];
            }
#pragma unroll
            for (int sn = 0; sn < 4; sn++) {
                int nb = wn + sn * 8;
                bf[sn][0] = Bs[kk + tq][nb + g];
                bf[sn][1] = Bs[kk + tq + 4][nb + g];
            }
#pragma unroll
            for (int sm = 0; sm < 2; sm++)
#pragma unroll
                for (int sn = 0; sn < 4; sn++)
                    mma_tf32(acc[sm][sn], af[sm], bf[sn]);
        }
    }

#pragma unroll
    for (int sm = 0; sm < 2; sm++) {
        int r0 = m0 + wm + sm * 16 + g;
#pragma unroll
        for (int sn = 0; sn < 4; sn++) {
            int cc = n0 + wn + sn * 8 + tq * 2;
            float b0 = bo[cc], b1 = bo[cc + 1];
            *(float2*)&Y[(size_t)r0 * C + cc] =
                make_float2(acc[sm][sn][0] + b0, acc[sm][sn][1] + b1);
            *(float2*)&Y[(size_t)(r0 + 8) * C + cc] =
                make_float2(acc[sm][sn][2] + b0, acc[sm][sn][3] + b1);
        }
    }
}

// ---------------------------------------------------------------------------
extern "C" void kernel_launch(void* const* d_in, const int* in_sizes, int n_in,
                              void* d_out, int out_size)
{
    const float* x  = (const float*)d_in[0];
    const float* Wq = (const float*)d_in[1];
    const float* Wk = (const float*)d_in[2];
    const float* Wv = (const float*)d_in[3];
    const float* Wo = (const float*)d_in[4];
    const float* bo = (const float*)d_in[5];
    float* y = (float*)d_out;

    transpose_wo_kernel<<<dim3(C / 32, C / 32), dim3(32, 8)>>>(Wo);
    qkv_tf32_kernel<<<dim3(T / 64, 3, BH), 128>>>(x, Wq, Wk, Wv);
    attn_tc_kernel<<<dim3(T / AQ, BH), 128>>>();
    proj_tf32_kernel<<<dim3(C / 64, (B * T) / 64), 128>>>(bo, y);
}

// round 6
// speedup vs baseline: 5.5240x; 1.0981x over previous
#include <cuda_runtime.h>
#include <cstdint>

#define B 2
#define T 2048
#define C 1024
#define H 16
#define HD 64
#define BH (B * H)

// ---- scratch (device globals; no runtime allocation allowed) ----
__device__ float g_q[(size_t)BH * T * HD];   // [B,H,T,HD]
__device__ float g_k[(size_t)BH * T * HD];
__device__ float g_v[(size_t)BH * T * HD];
__device__ float g_o[(size_t)B * T * C];     // attention out, [B,T,H*HD]
__device__ float g_wot[(size_t)C * C];       // Wo transposed

// ---------------------------------------------------------------------------
// helpers
// ---------------------------------------------------------------------------
__device__ __forceinline__ unsigned f2tf32(float x) {
    unsigned r;
    asm("cvt.rna.tf32.f32 %0, %1;" : "=r"(r) : "f"(x));
    return r;
}

__device__ __forceinline__ void mma_tf32(float c[4], const unsigned a[4], const unsigned b[2]) {
    asm("mma.sync.aligned.m16n8k8.row.col.f32.tf32.tf32.f32 "
        "{%0,%1,%2,%3},{%4,%5,%6,%7},{%8,%9},{%0,%1,%2,%3};"
        : "+f"(c[0]), "+f"(c[1]), "+f"(c[2]), "+f"(c[3])
        : "r"(a[0]), "r"(a[1]), "r"(a[2]), "r"(a[3]), "r"(b[0]), "r"(b[1]));
}

__device__ __forceinline__ void cp16(void* smem_dst, const void* gmem_src) {
    unsigned saddr = (unsigned)__cvta_generic_to_shared(smem_dst);
    asm volatile("cp.async.cg.shared.global [%0], [%1], 16;" :: "r"(saddr), "l"(gmem_src));
}
#define CP_COMMIT asm volatile("cp.async.commit_group;")
#define CP_WAIT(n) asm volatile("cp.async.wait_group %0;" :: "n"(n))

// GEMM staging geometry (dynamic smem): A[2][128][36], B[2][32][72]
#define GA_PITCH 36
#define GB_PITCH 72
#define GB_OFF   (2 * 128 * GA_PITCH)
#define GEMM_SMEM ((GB_OFF + 2 * 32 * GB_PITCH) * 4)   // 55296 bytes

// ---------------------------------------------------------------------------
// Kernel 0: transpose Wo [C,C] -> g_wot.
// ---------------------------------------------------------------------------
__global__ void transpose_wo_kernel(const float* __restrict__ Wo) {
    __shared__ float tile[32][33];
    int x0 = blockIdx.x * 32;
    int y0 = blockIdx.y * 32;
    int tx = threadIdx.x, ty = threadIdx.y;
#pragma unroll
    for (int i = 0; i < 32; i += 8)
        tile[ty + i][tx] = Wo[(size_t)(y0 + ty + i) * C + x0 + tx];
    __syncthreads();
#pragma unroll
    for (int i = 0; i < 32; i += 8)
        g_wot[(size_t)(x0 + ty + i) * C + y0 + tx] = tile[tx][ty + i];
}

// ---------------------------------------------------------------------------
// Kernel 1: QKV projection, tf32 mma + 2-stage cp.async pipeline.
// Block 256 thr = 8 warps; tile 128(M) x 64(N); warp 32x32; K-chunk 32.
// ---------------------------------------------------------------------------
__global__ void __launch_bounds__(256) qkv_tf32_kernel(
    const float* __restrict__ x,
    const float* __restrict__ Wq,
    const float* __restrict__ Wk,
    const float* __restrict__ Wv)
{
    extern __shared__ float smg[];
    float (*Asf)[128][GA_PITCH] = (float(*)[128][GA_PITCH])smg;
    float (*Bsf)[32][GB_PITCH]  = (float(*)[32][GB_PITCH])(smg + GB_OFF);

    int bh = blockIdx.z;
    int b  = bh >> 4;
    int h  = bh & 15;
    int t0 = blockIdx.x * 128;

    const float* W;
    float* out;
    if (blockIdx.y == 0)      { W = Wq; out = g_q; }
    else if (blockIdx.y == 1) { W = Wk; out = g_k; }
    else                      { W = Wv; out = g_v; }
    W += (size_t)h * C * HD;
    out += ((size_t)bh * T + t0) * HD;
    const float* A = x + ((size_t)b * T + t0) * C;

    int tid = threadIdx.x;
    int lane = tid & 31, w = tid >> 5;
    int g = lane >> 2, tq = lane & 3;
    int wm = (w >> 1) * 32, wn = (w & 1) * 32;

    float acc[2][4][4] = {};

    // prefetch chunk 0 -> stage 0
#pragma unroll
    for (int it = 0; it < 4; it++) {
        int f = tid + it * 256;
        int r = f >> 3, c4 = f & 7;
        cp16(&Asf[0][r][c4 * 4], &A[(size_t)r * C + c4 * 4]);
    }
#pragma unroll
    for (int it = 0; it < 2; it++) {
        int f = tid + it * 256;
        int r = f >> 4, c4 = f & 15;
        cp16(&Bsf[0][r][c4 * 4], &W[(size_t)r * HD + c4 * 4]);
    }
    CP_COMMIT;

    const int NC = C / 32;
    for (int c = 0; c < NC; c++) {
        int st = c & 1;
        if (c + 1 < NC) {
            int k0 = (c + 1) * 32, s2 = st ^ 1;
#pragma unroll
            for (int it = 0; it < 4; it++) {
                int f = tid + it * 256;
                int r = f >> 3, c4 = f & 7;
                cp16(&Asf[s2][r][c4 * 4], &A[(size_t)r * C + k0 + c4 * 4]);
            }
#pragma unroll
            for (int it = 0; it < 2; it++) {
                int f = tid + it * 256;
                int r = f >> 4, c4 = f & 15;
                cp16(&Bsf[s2][r][c4 * 4], &W[(size_t)(k0 + r) * HD + c4 * 4]);
            }
            CP_COMMIT;
            CP_WAIT(1);
        } else {
            CP_WAIT(0);
        }
        __syncthreads();

#pragma unroll
        for (int kk = 0; kk < 32; kk += 8) {
            unsigned af[2][4], bf[4][2];
#pragma unroll
            for (int sm = 0; sm < 2; sm++) {
                int rb = wm + sm * 16;
                af[sm][0] = f2tf32(Asf[st][rb + g][kk + tq]);
                af[sm][1] = f2tf32(Asf[st][rb + g + 8][kk + tq]);
                af[sm][2] = f2tf32(Asf[st][rb + g][kk + tq + 4]);
                af[sm][3] = f2tf32(Asf[st][rb + g + 8][kk + tq + 4]);
            }
#pragma unroll
            for (int sn = 0; sn < 4; sn++) {
                int nb = wn + sn * 8;
                bf[sn][0] = f2tf32(Bsf[st][kk + tq][nb + g]);
                bf[sn][1] = f2tf32(Bsf[st][kk + tq + 4][nb + g]);
            }
#pragma unroll
            for (int sm = 0; sm < 2; sm++)
#pragma unroll
                for (int sn = 0; sn < 4; sn++)
                    mma_tf32(acc[sm][sn], af[sm], bf[sn]);
        }
        __syncthreads();   // all warps done with stage st before it is refilled
    }

#pragma unroll
    for (int sm = 0; sm < 2; sm++) {
        int r0 = wm + sm * 16 + g;
#pragma unroll
        for (int sn = 0; sn < 4; sn++) {
            int cc = wn + sn * 8 + tq * 2;
            *(float2*)&out[(size_t)r0 * HD + cc] = make_float2(acc[sm][sn][0], acc[sm][sn][1]);
            *(float2*)&out[(size_t)(r0 + 8) * HD + cc] = make_float2(acc[sm][sn][2], acc[sm][sn][3]);
        }
    }
}

// ---------------------------------------------------------------------------
// Kernel 2: causal flash attention, tf32 mma, 8 warps, 128 q-rows per block.
// ---------------------------------------------------------------------------
#define AQ 128
#define AK 64
#define KS_OFF 0
#define VS_OFF (64 * 68)
#define PS_OFF (VS_OFF + 64 * 72)
#define ATTN_SMEM ((PS_OFF + 128 * 68) * 4)

__global__ void __launch_bounds__(256) attn_tc_kernel() {
    extern __shared__ float sm_[];
    float (*Ks)[68] = (float(*)[68])(sm_ + KS_OFF);
    float (*Vs)[72] = (float(*)[72])(sm_ + VS_OFF);
    float (*Ps)[68] = (float(*)[68])(sm_ + PS_OFF);

    int bh = blockIdx.y;
    int qt = gridDim.x - 1 - blockIdx.x;   // heavy q-tiles first
    int t0 = qt * AQ;
    int tid = threadIdx.x;
    int lane = tid & 31, w = tid >> 5;
    int g = lane >> 2, tq = lane & 3;
    int wq = w * 16;

    const float* qbase = g_q + ((size_t)bh * T + t0) * HD;
    const float* kbase = g_k + (size_t)bh * T * HD;
    const float* vbase = g_v + (size_t)bh * T * HD;

    // Q fragments resident in registers (softmax scale folded in; exact *2^-3)
    unsigned qf[8][4];
#pragma unroll
    for (int ks = 0; ks < 8; ks++) {
        int k0 = ks * 8;
        qf[ks][0] = f2tf32(0.125f * qbase[(size_t)(wq + g) * HD + k0 + tq]);
        qf[ks][1] = f2tf32(0.125f * qbase[(size_t)(wq + g + 8) * HD + k0 + tq]);
        qf[ks][2] = f2tf32(0.125f * qbase[(size_t)(wq + g) * HD + k0 + tq + 4]);
        qf[ks][3] = f2tf32(0.125f * qbase[(size_t)(wq + g + 8) * HD + k0 + tq + 4]);
    }

    float m0 = -1e30f, m1 = -1e30f, l0 = 0.f, l1 = 0.f;
    float accO[8][4] = {};

    int ntiles = 2 * qt + 2;   // keys 0 .. t0+127
    for (int itile = 0; itile < ntiles; itile++) {
        int s0 = itile * AK;
        __syncthreads();   // prior tile reads complete
#pragma unroll
        for (int it = 0; it < 2; it++) {
            int f = tid + it * 256;
            int r = f >> 4, c4 = f & 15;
            float4 kv = *(const float4*)&kbase[(size_t)(s0 + r) * HD + c4 * 4];
            *(uint4*)&Ks[r][c4 * 4] =
                make_uint4(f2tf32(kv.x), f2tf32(kv.y), f2tf32(kv.z), f2tf32(kv.w));
            float4 vv = *(const float4*)&vbase[(size_t)(s0 + r) * HD + c4 * 4];
            *(uint4*)&Vs[r][c4 * 4] =
                make_uint4(f2tf32(vv.x), f2tf32(vv.y), f2tf32(vv.z), f2tf32(vv.w));
            float4 kv2 = *(const float4*)&kbase[(size_t)(s0 + r + 32) * HD + c4 * 4];
            *(uint4*)&Ks[r + 32][c4 * 4] =
                make_uint4(f2tf32(kv2.x), f2tf32(kv2.y), f2tf32(kv2.z), f2tf32(kv2.w));
            float4 vv2 = *(const float4*)&vbase[(size_t)(s0 + r + 32) * HD + c4 * 4];
            *(uint4*)&Vs[r + 32][c4 * 4] =
                make_uint4(f2tf32(vv2.x), f2tf32(vv2.y), f2tf32(vv2.z), f2tf32(vv2.w));
        }
        __syncthreads();

        if (s0 > t0 + wq + 15) continue;   // tile entirely in this warp's future

        // S = Q * K^T
        float sc[8][4] = {};
#pragma unroll
        for (int ks = 0; ks < 8; ks++) {
            unsigned bf[8][2];
#pragma unroll
            for (int sn = 0; sn < 8; sn++) {
                bf[sn][0] = __float_as_uint(Ks[sn * 8 + g][ks * 8 + tq]);
                bf[sn][1] = __float_as_uint(Ks[sn * 8 + g][ks * 8 + tq + 4]);
            }
#pragma unroll
            for (int sn = 0; sn < 8; sn++)
                mma_tf32(sc[sn], qf[ks], bf[sn]);
        }

        // causal mask (global indices), only when tile crosses this warp's rows
        if (s0 + 63 > t0 + wq) {
            int r0 = t0 + wq + g, r1 = r0 + 8;
#pragma unroll
            for (int sn = 0; sn < 8; sn++) {
                int c0 = s0 + sn * 8 + tq * 2, c1 = c0 + 1;
                if (c0 > r0) sc[sn][0] = -1e30f;
                if (c1 > r0) sc[sn][1] = -1e30f;
                if (c0 > r1) sc[sn][2] = -1e30f;
                if (c1 > r1) sc[sn][3] = -1e30f;
            }
        }

        // online softmax (rows g -> c0/c1, g+8 -> c2/c3), quad shfl reduce
        float rx0 = -1e30f, rx1 = -1e30f;
#pragma unroll
        for (int sn = 0; sn < 8; sn++) {
            rx0 = fmaxf(rx0, fmaxf(sc[sn][0], sc[sn][1]));
            rx1 = fmaxf(rx1, fmaxf(sc[sn][2], sc[sn][3]));
        }
        rx0 = fmaxf(rx0, __shfl_xor_sync(0xffffffffu, rx0, 1));
        rx0 = fmaxf(rx0, __shfl_xor_sync(0xffffffffu, rx0, 2));
        rx1 = fmaxf(rx1, __shfl_xor_sync(0xffffffffu, rx1, 1));
        rx1 = fmaxf(rx1, __shfl_xor_sync(0xffffffffu, rx1, 2));
        float mn0 = fmaxf(m0, rx0), mn1 = fmaxf(m1, rx1);
        float corr0 = __expf(m0 - mn0), corr1 = __expf(m1 - mn1);
        m0 = mn0; m1 = mn1;

        float rs0 = 0.f, rs1 = 0.f;
#pragma unroll
        for (int sn = 0; sn < 8; sn++) {
            float p0 = __uint_as_float(f2tf32(__expf(sc[sn][0] - mn0)));
            float p1 = __uint_as_float(f2tf32(__expf(sc[sn][1] - mn0)));
            float p2 = __uint_as_float(f2tf32(__expf(sc[sn][2] - mn1)));
            float p3 = __uint_as_float(f2tf32(__expf(sc[sn][3] - mn1)));
            sc[sn][0] = p0; sc[sn][1] = p1; sc[sn][2] = p2; sc[sn][3] = p3;
            rs0 += p0 + p1;
            rs1 += p2 + p3;
        }
        rs0 += __shfl_xor_sync(0xffffffffu, rs0, 1);
        rs0 += __shfl_xor_sync(0xffffffffu, rs0, 2);
        rs1 += __shfl_xor_sync(0xffffffffu, rs1, 1);
        rs1 += __shfl_xor_sync(0xffffffffu, rs1, 2);
        l0 = l0 * corr0 + rs0;
        l1 = l1 * corr1 + rs1;
#pragma unroll
        for (int sn = 0; sn < 8; sn++) {
            accO[sn][0] *= corr0; accO[sn][1] *= corr0;
            accO[sn][2] *= corr1; accO[sn][3] *= corr1;
        }

        // P to warp-private SMEM rows (only this warp reads them back)
#pragma unroll
        for (int sn = 0; sn < 8; sn++) {
            int cc = sn * 8 + tq * 2;
            *(float2*)&Ps[wq + g][cc]     = make_float2(sc[sn][0], sc[sn][1]);
            *(float2*)&Ps[wq + g + 8][cc] = make_float2(sc[sn][2], sc[sn][3]);
        }
        __syncwarp();

        // O += P * V
#pragma unroll
        for (int kc = 0; kc < 8; kc++) {
            unsigned af[4];
            af[0] = __float_as_uint(Ps[wq + g][kc * 8 + tq]);
            af[1] = __float_as_uint(Ps[wq + g + 8][kc * 8 + tq]);
            af[2] = __float_as_uint(Ps[wq + g][kc * 8 + tq + 4]);
            af[3] = __float_as_uint(Ps[wq + g + 8][kc * 8 + tq + 4]);
#pragma unroll
            for (int sn = 0; sn < 8; sn++) {
                unsigned bf[2];
                bf[0] = __float_as_uint(Vs[kc * 8 + tq][sn * 8 + g]);
                bf[1] = __float_as_uint(Vs[kc * 8 + tq + 4][sn * 8 + g]);
                mma_tf32(accO[sn], af, bf);
            }
        }
    }

    // epilogue: normalize, write to [B,T,H*HD]
    float inv0 = 1.f / l0, inv1 = 1.f / l1;
    int b = bh >> 4, h = bh & 15;
    float* o0 = g_o + ((size_t)b * T + t0 + wq + g) * C + h * HD;
    float* o1 = o0 + (size_t)8 * C;
#pragma unroll
    for (int sn = 0; sn < 8; sn++) {
        int cc = sn * 8 + tq * 2;
        *(float2*)&o0[cc] = make_float2(accO[sn][0] * inv0, accO[sn][1] * inv0);
        *(float2*)&o1[cc] = make_float2(accO[sn][2] * inv1, accO[sn][3] * inv1);
    }
}

// ---------------------------------------------------------------------------
// Kernel 3: output projection, tf32 mma + 2-stage cp.async pipeline.
// ---------------------------------------------------------------------------
__global__ void __launch_bounds__(256) proj_tf32_kernel(
    const float* __restrict__ bo, float* __restrict__ Y)
{
    extern __shared__ float smg[];
    float (*Asf)[128][GA_PITCH] = (float(*)[128][GA_PITCH])smg;
    float (*Bsf)[32][GB_PITCH]  = (float(*)[32][GB_PITCH])(smg + GB_OFF);

    int n0 = blockIdx.x * 64;
    int m0 = blockIdx.y * 128;

    const float* A = g_o + (size_t)m0 * C;
    const float* Bp = g_wot + n0;

    int tid = threadIdx.x;
    int lane = tid & 31, w = tid >> 5;
    int g = lane >> 2, tq = lane & 3;
    int wm = (w >> 1) * 32, wn = (w & 1) * 32;

    float acc[2][4][4] = {};

#pragma unroll
    for (int it = 0; it < 4; it++) {
        int f = tid + it * 256;
        int r = f >> 3, c4 = f & 7;
        cp16(&Asf[0][r][c4 * 4], &A[(size_t)r * C + c4 * 4]);
    }
#pragma unroll
    for (int it = 0; it < 2; it++) {
        int f = tid + it * 256;
        int r = f >> 4, c4 = f & 15;
        cp16(&Bsf[0][r][c4 * 4], &Bp[(size_t)r * C + c4 * 4]);
    }
    CP_COMMIT;

    const int NC = C / 32;
    for (int c = 0; c < NC; c++) {
        int st = c & 1;
        if (c + 1 < NC) {
            int k0 = (c + 1) * 32, s2 = st ^ 1;
#pragma unroll
            for (int it = 0; it < 4; it++) {
                int f = tid + it * 256;
                int r = f >> 3, c4 = f & 7;
                cp16(&Asf[s2][r][c4 * 4], &A[(size_t)r * C + k0 + c4 * 4]);
            }
#pragma unroll
            for (int it = 0; it < 2; it++) {
                int f = tid + it * 256;
                int r = f >> 4, c4 = f & 15;
                cp16(&Bsf[s2][r][c4 * 4], &Bp[(size_t)(k0 + r) * C + c4 * 4]);
            }
            CP_COMMIT;
            CP_WAIT(1);
        } else {
            CP_WAIT(0);
        }
        __syncthreads();

#pragma unroll
        for (int kk = 0; kk < 32; kk += 8) {
            unsigned af[2][4], bf[4][2];
#pragma unroll
            for (int sm = 0; sm < 2; sm++) {
                int rb = wm + sm * 16;
                af[sm][0] = f2tf32(Asf[st][rb + g][kk + tq]);
                af[sm][1] = f2tf32(Asf[st][rb + g + 8][kk + tq]);
                af[sm][2] = f2tf32(Asf[st][rb + g][kk + tq + 4]);
                af[sm][3] = f2tf32(Asf[st][rb + g + 8][kk + tq + 4]);
            }
#pragma unroll
            for (int sn = 0; sn < 4; sn++) {
                int nb = wn + sn * 8;
                bf[sn][0] = f2tf32(Bsf[st][kk + tq][nb + g]);
                bf[sn][1] = f2tf32(Bsf[st][kk + tq + 4][nb + g]);
            }
#pragma unroll
            for (int sm = 0; sm < 2; sm++)
#pragma unroll
                for (int sn = 0; sn < 4; sn++)
                    mma_tf32(acc[sm][sn], af[sm], bf[sn]);
        }
        __syncthreads();
    }

#pragma unroll
    for (int sm = 0; sm < 2; sm++) {
        int r0 = m0 + wm + sm * 16 + g;
#pragma unroll
        for (int sn = 0; sn < 4; sn++) {
            int cc = n0 + wn + sn * 8 + tq * 2;
            float b0 = bo[cc], b1 = bo[cc + 1];
            *(float2*)&Y[(size_t)r0 * C + cc] =
                make_float2(acc[sm][sn][0] + b0, acc[sm][sn][1] + b1);
            *(float2*)&Y[(size_t)(r0 + 8) * C + cc] =
                make_float2(acc[sm][sn][2] + b0, acc[sm][sn][3] + b1);
        }
    }
}

// ---------------------------------------------------------------------------
extern "C" void kernel_launch(void* const* d_in, const int* in_sizes, int n_in,
                              void* d_out, int out_size)
{
    const float* x  = (const float*)d_in[0];
    const float* Wq = (const float*)d_in[1];
    const float* Wk = (const float*)d_in[2];
    const float* Wv = (const float*)d_in[3];
    const float* Wo = (const float*)d_in[4];
    const float* bo = (const float*)d_in[5];
    float* y = (float*)d_out;

    static bool attr_done = false;
    if (!attr_done) {
        cudaFuncSetAttribute(attn_tc_kernel,
                             cudaFuncAttributeMaxDynamicSharedMemorySize, ATTN_SMEM);
        cudaFuncSetAttribute(qkv_tf32_kernel,
                             cudaFuncAttributeMaxDynamicSharedMemorySize, GEMM_SMEM);
        cudaFuncSetAttribute(proj_tf32_kernel,
                             cudaFuncAttributeMaxDynamicSharedMemorySize, GEMM_SMEM);
        attr_done = true;
    }

    transpose_wo_kernel<<<dim3(C / 32, C / 32), dim3(32, 8)>>>(Wo);
    qkv_tf32_kernel<<<dim3(T / 128, 3, BH), 256, GEMM_SMEM>>>(x, Wq, Wk, Wv);
    attn_tc_kernel<<<dim3(T / AQ, BH), 256, ATTN_SMEM>>>();
    proj_tf32_kernel<<<dim3(C / 64, (B * T) / 128), 256, GEMM_SMEM>>>(bo, y);
}

// round 7
// speedup vs baseline: 6.7478x; 1.2215x over previous
#include <cuda_runtime.h>
#include <cuda_fp16.h>
#include <cstdint>

#define B 2
#define T 2048
#define C 1024
#define H 16
#define HD 64
#define BH (B * H)

// ---- scratch (device globals; no runtime allocation allowed) ----
__device__ float g_q[(size_t)BH * T * HD];   // [B,H,T,HD]
__device__ float g_k[(size_t)BH * T * HD];
__device__ float g_v[(size_t)BH * T * HD];
__device__ float g_o[(size_t)B * T * C];     // attention out, [B,T,H*HD]
__device__ float g_wot[(size_t)C * C];       // Wo transposed

// ---------------------------------------------------------------------------
// helpers
// ---------------------------------------------------------------------------
__device__ __forceinline__ unsigned f2tf32(float x) {
    unsigned r;
    asm("cvt.rna.tf32.f32 %0, %1;" : "=r"(r) : "f"(x));
    return r;
}

__device__ __forceinline__ unsigned f2h2(float lo, float hi) {
    unsigned r;
    asm("cvt.rn.f16x2.f32 %0, %1, %2;" : "=r"(r) : "f"(hi), "f"(lo));
    return r;
}

__device__ __forceinline__ void mma_tf32(float c[4], const unsigned a[4], const unsigned b[2]) {
    asm("mma.sync.aligned.m16n8k8.row.col.f32.tf32.tf32.f32 "
        "{%0,%1,%2,%3},{%4,%5,%6,%7},{%8,%9},{%0,%1,%2,%3};"
        : "+f"(c[0]), "+f"(c[1]), "+f"(c[2]), "+f"(c[3])
        : "r"(a[0]), "r"(a[1]), "r"(a[2]), "r"(a[3]), "r"(b[0]), "r"(b[1]));
}

__device__ __forceinline__ void mma_f16(float c[4], const unsigned a[4], const unsigned b[2]) {
    asm("mma.sync.aligned.m16n8k16.row.col.f32.f16.f16.f32 "
        "{%0,%1,%2,%3},{%4,%5,%6,%7},{%8,%9},{%0,%1,%2,%3};"
        : "+f"(c[0]), "+f"(c[1]), "+f"(c[2]), "+f"(c[3])
        : "r"(a[0]), "r"(a[1]), "r"(a[2]), "r"(a[3]), "r"(b[0]), "r"(b[1]));
}

__device__ __forceinline__ void cp16(void* smem_dst, const void* gmem_src) {
    unsigned saddr = (unsigned)__cvta_generic_to_shared(smem_dst);
    asm volatile("cp.async.cg.shared.global [%0], [%1], 16;" :: "r"(saddr), "l"(gmem_src));
}
#define CP_COMMIT asm volatile("cp.async.commit_group;")
#define CP_WAIT(n) asm volatile("cp.async.wait_group %0;" :: "n"(n))

// GEMM staging geometry (dynamic smem, fp32): A[2][128][40], B[2][32][68]
#define GA_PITCH 40
#define GB_PITCH 68
#define GB_OFF   (2 * 128 * GA_PITCH)
#define GEMM_SMEM ((GB_OFF + 2 * 32 * GB_PITCH) * 4)   // 58368 bytes

// ---------------------------------------------------------------------------
// Kernel 0: transpose Wo [C,C] -> g_wot.
// ---------------------------------------------------------------------------
__global__ void transpose_wo_kernel(const float* __restrict__ Wo) {
    __shared__ float tile[32][33];
    int x0 = blockIdx.x * 32;
    int y0 = blockIdx.y * 32;
    int tx = threadIdx.x, ty = threadIdx.y;
#pragma unroll
    for (int i = 0; i < 32; i += 8)
        tile[ty + i][tx] = Wo[(size_t)(y0 + ty + i) * C + x0 + tx];
    __syncthreads();
#pragma unroll
    for (int i = 0; i < 32; i += 8)
        g_wot[(size_t)(x0 + ty + i) * C + y0 + tx] = tile[tx][ty + i];
}

// ---------------------------------------------------------------------------
// Kernel 1: QKV projection, fp16 mma + 2-stage cp.async pipeline.
// Block 256 thr = 8 warps; tile 128(M) x 64(N); warp 32x32; K-chunk 32.
// fp32 in SMEM; LDS.64 + cvt.rn.f16x2 at fragment load.
// ---------------------------------------------------------------------------
__global__ void __launch_bounds__(256) qkv_kernel(
    const float* __restrict__ x,
    const float* __restrict__ Wq,
    const float* __restrict__ Wk,
    const float* __restrict__ Wv)
{
    extern __shared__ float smg[];
    float (*Asf)[128][GA_PITCH] = (float(*)[128][GA_PITCH])smg;
    float (*Bsf)[32][GB_PITCH]  = (float(*)[32][GB_PITCH])(smg + GB_OFF);

    int bh = blockIdx.z;
    int b  = bh >> 4;
    int h  = bh & 15;
    int t0 = blockIdx.x * 128;

    const float* W;
    float* out;
    if (blockIdx.y == 0)      { W = Wq; out = g_q; }
    else if (blockIdx.y == 1) { W = Wk; out = g_k; }
    else                      { W = Wv; out = g_v; }
    W += (size_t)h * C * HD;
    out += ((size_t)bh * T + t0) * HD;
    const float* A = x + ((size_t)b * T + t0) * C;

    int tid = threadIdx.x;
    int lane = tid & 31, w = tid >> 5;
    int g = lane >> 2, tq = lane & 3;
    int wm = (w >> 1) * 32, wn = (w & 1) * 32;

    float acc[2][4][4] = {};

    // prefetch chunk 0 -> stage 0
#pragma unroll
    for (int it = 0; it < 4; it++) {
        int f = tid + it * 256;
        int r = f >> 3, c4 = f & 7;
        cp16(&Asf[0][r][c4 * 4], &A[(size_t)r * C + c4 * 4]);
    }
#pragma unroll
    for (int it = 0; it < 2; it++) {
        int f = tid + it * 256;
        int r = f >> 4, c4 = f & 15;
        cp16(&Bsf[0][r][c4 * 4], &W[(size_t)r * HD + c4 * 4]);
    }
    CP_COMMIT;

    const int NC = C / 32;
    for (int c = 0; c < NC; c++) {
        int st = c & 1;
        if (c + 1 < NC) {
            int k0 = (c + 1) * 32, s2 = st ^ 1;
#pragma unroll
            for (int it = 0; it < 4; it++) {
                int f = tid + it * 256;
                int r = f >> 3, c4 = f & 7;
                cp16(&Asf[s2][r][c4 * 4], &A[(size_t)r * C + k0 + c4 * 4]);
            }
#pragma unroll
            for (int it = 0; it < 2; it++) {
                int f = tid + it * 256;
                int r = f >> 4, c4 = f & 15;
                cp16(&Bsf[s2][r][c4 * 4], &W[(size_t)(k0 + r) * HD + c4 * 4]);
            }
            CP_COMMIT;
            CP_WAIT(1);
        } else {
            CP_WAIT(0);
        }
        __syncthreads();

#pragma unroll
        for (int kk = 0; kk < 32; kk += 16) {
            unsigned af[2][4], bf[4][2];
#pragma unroll
            for (int sm = 0; sm < 2; sm++) {
                int rb = wm + sm * 16;
                float2 x0 = *(const float2*)&Asf[st][rb + g][kk + 2 * tq];
                float2 x1 = *(const float2*)&Asf[st][rb + g + 8][kk + 2 * tq];
                float2 x2 = *(const float2*)&Asf[st][rb + g][kk + 2 * tq + 8];
                float2 x3 = *(const float2*)&Asf[st][rb + g + 8][kk + 2 * tq + 8];
                af[sm][0] = f2h2(x0.x, x0.y);
                af[sm][1] = f2h2(x1.x, x1.y);
                af[sm][2] = f2h2(x2.x, x2.y);
                af[sm][3] = f2h2(x3.x, x3.y);
            }
#pragma unroll
            for (int sn = 0; sn < 4; sn++) {
                int nb = wn + sn * 8 + g;
                bf[sn][0] = f2h2(Bsf[st][kk + 2 * tq][nb], Bsf[st][kk + 2 * tq + 1][nb]);
                bf[sn][1] = f2h2(Bsf[st][kk + 2 * tq + 8][nb], Bsf[st][kk + 2 * tq + 9][nb]);
            }
#pragma unroll
            for (int sm = 0; sm < 2; sm++)
#pragma unroll
                for (int sn = 0; sn < 4; sn++)
                    mma_f16(acc[sm][sn], af[sm], bf[sn]);
        }
        __syncthreads();   // all warps done with stage st before it is refilled
    }

#pragma unroll
    for (int sm = 0; sm < 2; sm++) {
        int r0 = wm + sm * 16 + g;
#pragma unroll
        for (int sn = 0; sn < 4; sn++) {
            int cc = wn + sn * 8 + tq * 2;
            *(float2*)&out[(size_t)r0 * HD + cc] = make_float2(acc[sm][sn][0], acc[sm][sn][1]);
            *(float2*)&out[(size_t)(r0 + 8) * HD + cc] = make_float2(acc[sm][sn][2], acc[sm][sn][3]);
        }
    }
}

// ---------------------------------------------------------------------------
// Kernel 2: causal flash attention. S-gemm fp16 (K staged as half, Q frags
// pre-packed in regs), softmax fp32, PV-gemm tf32. 8 warps, 128 q-rows/block.
// ---------------------------------------------------------------------------
#define AQ 128
#define AK 64
#define ATTN_VS_OFF (64 * 72 * 2)                      // after Ks (half)
#define ATTN_PS_OFF (ATTN_VS_OFF + 64 * 72 * 4)        // after Vs (float)
#define ATTN_SMEM   (ATTN_PS_OFF + 128 * 68 * 4)       // 62464 bytes

__global__ void __launch_bounds__(256) attn_tc_kernel() {
    extern __shared__ char smc[];
    __half (*Ks)[72] = (__half(*)[72])smc;             // K tile, fp16 [key][d]
    float  (*Vs)[72] = (float(*)[72])(smc + ATTN_VS_OFF);
    float  (*Ps)[68] = (float(*)[68])(smc + ATTN_PS_OFF);

    int bh = blockIdx.y;
    int qt = gridDim.x - 1 - blockIdx.x;   // heavy q-tiles first
    int t0 = qt * AQ;
    int tid = threadIdx.x;
    int lane = tid & 31, w = tid >> 5;
    int g = lane >> 2, tq = lane & 3;
    int wq = w * 16;

    const float* qbase = g_q + ((size_t)bh * T + t0) * HD;
    const float* kbase = g_k + (size_t)bh * T * HD;
    const float* vbase = g_v + (size_t)bh * T * HD;

    // Q fragments resident in registers, fp16-packed (scale 0.125 exact)
    unsigned qf[4][4];
#pragma unroll
    for (int ks = 0; ks < 4; ks++) {
        float2 q00 = *(const float2*)&qbase[(size_t)(wq + g) * HD + ks * 16 + 2 * tq];
        float2 q10 = *(const float2*)&qbase[(size_t)(wq + g + 8) * HD + ks * 16 + 2 * tq];
        float2 q01 = *(const float2*)&qbase[(size_t)(wq + g) * HD + ks * 16 + 2 * tq + 8];
        float2 q11 = *(const float2*)&qbase[(size_t)(wq + g + 8) * HD + ks * 16 + 2 * tq + 8];
        qf[ks][0] = f2h2(0.125f * q00.x, 0.125f * q00.y);
        qf[ks][1] = f2h2(0.125f * q10.x, 0.125f * q10.y);
        qf[ks][2] = f2h2(0.125f * q01.x, 0.125f * q01.y);
        qf[ks][3] = f2h2(0.125f * q11.x, 0.125f * q11.y);
    }

    float m0 = -1e30f, m1 = -1e30f, l0 = 0.f, l1 = 0.f;
    float accO[8][4] = {};

    int ntiles = 2 * qt + 2;   // keys 0 .. t0+127
    for (int itile = 0; itile < ntiles; itile++) {
        int s0 = itile * AK;
        __syncthreads();   // prior tile reads complete
        // stage K as fp16 pairs, V as tf32
#pragma unroll
        for (int it = 0; it < 2; it++) {
            int f = tid + it * 256;
            int r = f >> 4, c4 = f & 15;
            float4 kv = *(const float4*)&kbase[(size_t)(s0 + r) * HD + c4 * 4];
            *(uint2*)&Ks[r][c4 * 4] = make_uint2(f2h2(kv.x, kv.y), f2h2(kv.z, kv.w));
            float4 vv = *(const float4*)&vbase[(size_t)(s0 + r) * HD + c4 * 4];
            *(uint4*)&Vs[r][c4 * 4] =
                make_uint4(f2tf32(vv.x), f2tf32(vv.y), f2tf32(vv.z), f2tf32(vv.w));
            float4 kv2 = *(const float4*)&kbase[(size_t)(s0 + r + 32) * HD + c4 * 4];
            *(uint2*)&Ks[r + 32][c4 * 4] = make_uint2(f2h2(kv2.x, kv2.y), f2h2(kv2.z, kv2.w));
            float4 vv2 = *(const float4*)&vbase[(size_t)(s0 + r + 32) * HD + c4 * 4];
            *(uint4*)&Vs[r + 32][c4 * 4] =
                make_uint4(f2tf32(vv2.x), f2tf32(vv2.y), f2tf32(vv2.z), f2tf32(vv2.w));
        }
        __syncthreads();

        if (s0 > t0 + wq + 15) continue;   // tile entirely in this warp's future

        // S = Q * K^T  (fp16, 4 k-steps of 16)
        float sc[8][4] = {};
#pragma unroll
        for (int ks = 0; ks < 4; ks++) {
            unsigned bfr[8][2];
#pragma unroll
            for (int sn = 0; sn < 8; sn++) {
                bfr[sn][0] = *(const unsigned*)&Ks[sn * 8 + g][ks * 16 + 2 * tq];
                bfr[sn][1] = *(const unsigned*)&Ks[sn * 8 + g][ks * 16 + 2 * tq + 8];
            }
#pragma unroll
            for (int sn = 0; sn < 8; sn++)
                mma_f16(sc[sn], qf[ks], bfr[sn]);
        }

        // causal mask (global indices), only when tile crosses this warp's rows
        if (s0 + 63 > t0 + wq) {
            int r0 = t0 + wq + g, r1 = r0 + 8;
#pragma unroll
            for (int sn = 0; sn < 8; sn++) {
                int c0 = s0 + sn * 8 + tq * 2, c1 = c0 + 1;
                if (c0 > r0) sc[sn][0] = -1e30f;
                if (c1 > r0) sc[sn][1] = -1e30f;
                if (c0 > r1) sc[sn][2] = -1e30f;
                if (c1 > r1) sc[sn][3] = -1e30f;
            }
        }

        // online softmax (rows g -> c0/c1, g+8 -> c2/c3), quad shfl reduce
        float rx0 = -1e30f, rx1 = -1e30f;
#pragma unroll
        for (int sn = 0; sn < 8; sn++) {
            rx0 = fmaxf(rx0, fmaxf(sc[sn][0], sc[sn][1]));
            rx1 = fmaxf(rx1, fmaxf(sc[sn][2], sc[sn][3]));
        }
        rx0 = fmaxf(rx0, __shfl_xor_sync(0xffffffffu, rx0, 1));
        rx0 = fmaxf(rx0, __shfl_xor_sync(0xffffffffu, rx0, 2));
        rx1 = fmaxf(rx1, __shfl_xor_sync(0xffffffffu, rx1, 1));
        rx1 = fmaxf(rx1, __shfl_xor_sync(0xffffffffu, rx1, 2));
        float mn0 = fmaxf(m0, rx0), mn1 = fmaxf(m1, rx1);
        float corr0 = __expf(m0 - mn0), corr1 = __expf(m1 - mn1);
        m0 = mn0; m1 = mn1;

        float rs0 = 0.f, rs1 = 0.f;
#pragma unroll
        for (int sn = 0; sn < 8; sn++) {
            float p0 = __uint_as_float(f2tf32(__expf(sc[sn][0] - mn0)));
            float p1 = __uint_as_float(f2tf32(__expf(sc[sn][1] - mn0)));
            float p2 = __uint_as_float(f2tf32(__expf(sc[sn][2] - mn1)));
            float p3 = __uint_as_float(f2tf32(__expf(sc[sn][3] - mn1)));
            sc[sn][0] = p0; sc[sn][1] = p1; sc[sn][2] = p2; sc[sn][3] = p3;
            rs0 += p0 + p1;
            rs1 += p2 + p3;
        }
        rs0 += __shfl_xor_sync(0xffffffffu, rs0, 1);
        rs0 += __shfl_xor_sync(0xffffffffu, rs0, 2);
        rs1 += __shfl_xor_sync(0xffffffffu, rs1, 1);
        rs1 += __shfl_xor_sync(0xffffffffu, rs1, 2);
        l0 = l0 * corr0 + rs0;
        l1 = l1 * corr1 + rs1;
#pragma unroll
        for (int sn = 0; sn < 8; sn++) {
            accO[sn][0] *= corr0; accO[sn][1] *= corr0;
            accO[sn][2] *= corr1; accO[sn][3] *= corr1;
        }

        // P to warp-private SMEM rows (only this warp reads them back)
#pragma unroll
        for (int sn = 0; sn < 8; sn++) {
            int cc = sn * 8 + tq * 2;
            *(float2*)&Ps[wq + g][cc]     = make_float2(sc[sn][0], sc[sn][1]);
            *(float2*)&Ps[wq + g + 8][cc] = make_float2(sc[sn][2], sc[sn][3]);
        }
        __syncwarp();

        // O += P * V  (tf32)
#pragma unroll
        for (int kc = 0; kc < 8; kc++) {
            unsigned af[4];
            af[0] = __float_as_uint(Ps[wq + g][kc * 8 + tq]);
            af[1] = __float_as_uint(Ps[wq + g + 8][kc * 8 + tq]);
            af[2] = __float_as_uint(Ps[wq + g][kc * 8 + tq + 4]);
            af[3] = __float_as_uint(Ps[wq + g + 8][kc * 8 + tq + 4]);
#pragma unroll
            for (int sn = 0; sn < 8; sn++) {
                unsigned bf[2];
                bf[0] = __float_as_uint(Vs[kc * 8 + tq][sn * 8 + g]);
                bf[1] = __float_as_uint(Vs[kc * 8 + tq + 4][sn * 8 + g]);
                mma_tf32(accO[sn], af, bf);
            }
        }
    }

    // epilogue: normalize, write to [B,T,H*HD]
    float inv0 = 1.f / l0, inv1 = 1.f / l1;
    int b = bh >> 4, h = bh & 15;
    float* o0 = g_o + ((size_t)b * T + t0 + wq + g) * C + h * HD;
    float* o1 = o0 + (size_t)8 * C;
#pragma unroll
    for (int sn = 0; sn < 8; sn++) {
        int cc = sn * 8 + tq * 2;
        *(float2*)&o0[cc] = make_float2(accO[sn][0] * inv0, accO[sn][1] * inv0);
        *(float2*)&o1[cc] = make_float2(accO[sn][2] * inv1, accO[sn][3] * inv1);
    }
}

// ---------------------------------------------------------------------------
// Kernel 3: output projection, fp16 mma + 2-stage cp.async pipeline.
// ---------------------------------------------------------------------------
__global__ void __launch_bounds__(256) proj_kernel(
    const float* __restrict__ bo, float* __restrict__ Y)
{
    extern __shared__ float smg[];
    float (*Asf)[128][GA_PITCH] = (float(*)[128][GA_PITCH])smg;
    float (*Bsf)[32][GB_PITCH]  = (float(*)[32][GB_PITCH])(smg + GB_OFF);

    int n0 = blockIdx.x * 64;
    int m0 = blockIdx.y * 128;

    const float* A = g_o + (size_t)m0 * C;
    const float* Bp = g_wot + n0;

    int tid = threadIdx.x;
    int lane = tid & 31, w = tid >> 5;
    int g = lane >> 2, tq = lane & 3;
    int wm = (w >> 1) * 32, wn = (w & 1) * 32;

    float acc[2][4][4] = {};

#pragma unroll
    for (int it = 0; it < 4; it++) {
        int f = tid + it * 256;
        int r = f >> 3, c4 = f & 7;
        cp16(&Asf[0][r][c4 * 4], &A[(size_t)r * C + c4 * 4]);
    }
#pragma unroll
    for (int it = 0; it < 2; it++) {
        int f = tid + it * 256;
        int r = f >> 4, c4 = f & 15;
        cp16(&Bsf[0][r][c4 * 4], &Bp[(size_t)r * C + c4 * 4]);
    }
    CP_COMMIT;

    const int NC = C / 32;
    for (int c = 0; c < NC; c++) {
        int st = c & 1;
        if (c + 1 < NC) {
            int k0 = (c + 1) * 32, s2 = st ^ 1;
#pragma unroll
            for (int it = 0; it < 4; it++) {
                int f = tid + it * 256;
                int r = f >> 3, c4 = f & 7;
                cp16(&Asf[s2][r][c4 * 4], &A[(size_t)r * C + k0 + c4 * 4]);
            }
#pragma unroll
            for (int it = 0; it < 2; it++) {
                int f = tid + it * 256;
                int r = f >> 4, c4 = f & 15;
                cp16(&Bsf[s2][r][c4 * 4], &Bp[(size_t)(k0 + r) * C + c4 * 4]);
            }
            CP_COMMIT;
            CP_WAIT(1);
        } else {
            CP_WAIT(0);
        }
        __syncthreads();

#pragma unroll
        for (int kk = 0; kk < 32; kk += 16) {
            unsigned af[2][4], bf[4][2];
#pragma unroll
            for (int sm = 0; sm < 2; sm++) {
                int rb = wm + sm * 16;
                float2 x0 = *(const float2*)&Asf[st][rb + g][kk + 2 * tq];
                float2 x1 = *(const float2*)&Asf[st][rb + g + 8][kk + 2 * tq];
                float2 x2 = *(const float2*)&Asf[st][rb + g][kk + 2 * tq + 8];
                float2 x3 = *(const float2*)&Asf[st][rb + g + 8][kk + 2 * tq + 8];
                af[sm][0] = f2h2(x0.x, x0.y);
                af[sm][1] = f2h2(x1.x, x1.y);
                af[sm][2] = f2h2(x2.x, x2.y);
                af[sm][3] = f2h2(x3.x, x3.y);
            }
#pragma unroll
            for (int sn = 0; sn < 4; sn++) {
                int nb = wn + sn * 8 + g;
                bf[sn][0] = f2h2(Bsf[st][kk + 2 * tq][nb], Bsf[st][kk + 2 * tq + 1][nb]);
                bf[sn][1] = f2h2(Bsf[st][kk + 2 * tq + 8][nb], Bsf[st][kk + 2 * tq + 9][nb]);
            }
#pragma unroll
            for (int sm = 0; sm < 2; sm++)
#pragma unroll
                for (int sn = 0; sn < 4; sn++)
                    mma_f16(acc[sm][sn], af[sm], bf[sn]);
        }
        __syncthreads();
    }

#pragma unroll
    for (int sm = 0; sm < 2; sm++) {
        int r0 = m0 + wm + sm * 16 + g;
#pragma unroll
        for (int sn = 0; sn < 4; sn++) {
            int cc = n0 + wn + sn * 8 + tq * 2;
            float b0 = bo[cc], b1 = bo[cc + 1];
            *(float2*)&Y[(size_t)r0 * C + cc] =
                make_float2(acc[sm][sn][0] + b0, acc[sm][sn][1] + b1);
            *(float2*)&Y[(size_t)(r0 + 8) * C + cc] =
                make_float2(acc[sm][sn][2] + b0, acc[sm][sn][3] + b1);
        }
    }
}

// ---------------------------------------------------------------------------
extern "C" void kernel_launch(void* const* d_in, const int* in_sizes, int n_in,
                              void* d_out, int out_size)
{
    const float* x  = (const float*)d_in[0];
    const float* Wq = (const float*)d_in[1];
    const float* Wk = (const float*)d_in[2];
    const float* Wv = (const float*)d_in[3];
    const float* Wo = (const float*)d_in[4];
    const float* bo = (const float*)d_in[5];
    float* y = (float*)d_out;

    static bool attr_done = false;
    if (!attr_done) {
        cudaFuncSetAttribute(attn_tc_kernel,
                             cudaFuncAttributeMaxDynamicSharedMemorySize, ATTN_SMEM);
        cudaFuncSetAttribute(qkv_kernel,
                             cudaFuncAttributeMaxDynamicSharedMemorySize, GEMM_SMEM);
        cudaFuncSetAttribute(proj_kernel,
                             cudaFuncAttributeMaxDynamicSharedMemorySize, GEMM_SMEM);
        attr_done = true;
    }

    transpose_wo_kernel<<<dim3(C / 32, C / 32), dim3(32, 8)>>>(Wo);
    qkv_kernel<<<dim3(T / 128, 3, BH), 256, GEMM_SMEM>>>(x, Wq, Wk, Wv);
    attn_tc_kernel<<<dim3(T / AQ, BH), 256, ATTN_SMEM>>>();
    proj_kernel<<<dim3(C / 64, (B * T) / 128), 256, GEMM_SMEM>>>(bo, y);
}

// round 8
// speedup vs baseline: 10.7443x; 1.5923x over previous
#include <cuda_runtime.h>
#include <cuda_fp16.h>
#include <cstdint>

#define B 2
#define T 2048
#define C 1024
#define H 16
#define HD 64
#define BH (B * H)

// ---- scratch (device globals; no runtime allocation allowed) ----
__device__ __half g_xh[(size_t)B * T * C];        // x in fp16
__device__ __half g_wh[(size_t)3 * H * C * HD];   // Wq|Wk|Wv in fp16
__device__ __half g_woth[(size_t)C * C];          // Wo^T in fp16
__device__ __half g_qh[(size_t)BH * T * HD];
__device__ __half g_kh[(size_t)BH * T * HD];
__device__ __half g_vh[(size_t)BH * T * HD];
__device__ __half g_oh[(size_t)B * T * C];        // attention out [B,T,H*HD]

// ---------------------------------------------------------------------------
// helpers
// ---------------------------------------------------------------------------
__device__ __forceinline__ unsigned f2h2(float lo, float hi) {
    unsigned r;
    asm("cvt.rn.f16x2.f32 %0, %1, %2;" : "=r"(r) : "f"(hi), "f"(lo));
    return r;
}

__device__ __forceinline__ void mma_f16(float c[4], const unsigned a[4], const unsigned b[2]) {
    asm("mma.sync.aligned.m16n8k16.row.col.f32.f16.f16.f32 "
        "{%0,%1,%2,%3},{%4,%5,%6,%7},{%8,%9},{%0,%1,%2,%3};"
        : "+f"(c[0]), "+f"(c[1]), "+f"(c[2]), "+f"(c[3])
        : "r"(a[0]), "r"(a[1]), "r"(a[2]), "r"(a[3]), "r"(b[0]), "r"(b[1]));
}

__device__ __forceinline__ void ldsm4(unsigned& d0, unsigned& d1, unsigned& d2, unsigned& d3,
                                      const void* p) {
    unsigned a = (unsigned)__cvta_generic_to_shared(p);
    asm volatile("ldmatrix.sync.aligned.m8n8.x4.shared.b16 {%0,%1,%2,%3}, [%4];"
                 : "=r"(d0), "=r"(d1), "=r"(d2), "=r"(d3) : "r"(a));
}

__device__ __forceinline__ void ldsm4t(unsigned& d0, unsigned& d1, unsigned& d2, unsigned& d3,
                                       const void* p) {
    unsigned a = (unsigned)__cvta_generic_to_shared(p);
    asm volatile("ldmatrix.sync.aligned.m8n8.x4.trans.shared.b16 {%0,%1,%2,%3}, [%4];"
                 : "=r"(d0), "=r"(d1), "=r"(d2), "=r"(d3) : "r"(a));
}

__device__ __forceinline__ void cp16(void* smem_dst, const void* gmem_src) {
    unsigned saddr = (unsigned)__cvta_generic_to_shared(smem_dst);
    asm volatile("cp.async.cg.shared.global [%0], [%1], 16;" :: "r"(saddr), "l"(gmem_src));
}
#define CP_COMMIT asm volatile("cp.async.commit_group;")
#define CP_WAIT(n) asm volatile("cp.async.wait_group %0;" :: "n"(n))

// ---------------------------------------------------------------------------
// Kernel P0: convert x, Wq, Wk, Wv to fp16 (elementwise).
// ---------------------------------------------------------------------------
__global__ void prep_convert_kernel(const float* __restrict__ x,
                                    const float* __restrict__ Wq,
                                    const float* __restrict__ Wk,
                                    const float* __restrict__ Wv) {
    int seg = blockIdx.y;
    const float* src;
    __half* dst;
    int n;
    const int WSZ = H * C * HD;
    if (seg == 0)      { src = x;  dst = g_xh;            n = B * T * C; }
    else if (seg == 1) { src = Wq; dst = g_wh;            n = WSZ; }
    else if (seg == 2) { src = Wk; dst = g_wh + WSZ;      n = WSZ; }
    else               { src = Wv; dst = g_wh + 2 * WSZ;  n = WSZ; }
    int i = (blockIdx.x * 256 + threadIdx.x) * 4;
    if (i < n) {
        float4 v = *(const float4*)&src[i];
        *(__half2*)&dst[i]     = __floats2half2_rn(v.x, v.y);
        *(__half2*)&dst[i + 2] = __floats2half2_rn(v.z, v.w);
    }
}

// ---------------------------------------------------------------------------
// Kernel P1: transpose Wo [C,C] -> g_woth (fp16).
// ---------------------------------------------------------------------------
__global__ void transpose_wo_kernel(const float* __restrict__ Wo) {
    __shared__ float tile[32][33];
    int x0 = blockIdx.x * 32;
    int y0 = blockIdx.y * 32;
    int tx = threadIdx.x, ty = threadIdx.y;
#pragma unroll
    for (int i = 0; i < 32; i += 8)
        tile[ty + i][tx] = Wo[(size_t)(y0 + ty + i) * C + x0 + tx];
    __syncthreads();
#pragma unroll
    for (int i = 0; i < 32; i += 8)
        g_woth[(size_t)(x0 + ty + i) * C + y0 + tx] = __float2half(tile[tx][ty + i]);
}

// ---------------------------------------------------------------------------
// Kernel 1: QKV projection. fp16 mma + ldmatrix + 2-stage cp.async pipeline.
// Block 256 thr = 8 warps; tile 128(M) x 64(N); warp 32x32; K-chunk 32.
// ---------------------------------------------------------------------------
__global__ void __launch_bounds__(256) qkv_kernel() {
    __shared__ __half As[2][128][40];   // A rows 64B data, pitch 80B (conflict-free ldsm)
    __shared__ __half Bs[2][32][72];    // B rows 128B data, pitch 144B

    int bh = blockIdx.z;
    int b  = bh >> 4;
    int h  = bh & 15;
    int t0 = blockIdx.x * 128;
    int sel = blockIdx.y;

    const __half* W = g_wh + ((size_t)sel * H + h) * C * HD;
    __half* out = (sel == 0 ? g_qh : sel == 1 ? g_kh : g_vh) + ((size_t)bh * T + t0) * HD;
    const __half* A = g_xh + ((size_t)b * T + t0) * C;

    int tid = threadIdx.x;
    int lane = tid & 31, w = tid >> 5;
    int g = lane >> 2, tq = lane & 3;
    int wm = (w >> 1) * 32, wn = (w & 1) * 32;
    int mi = lane >> 3, mrow = lane & 7;         // ldmatrix lane roles
    int mb = mi & 1, kb = mi >> 1;

    float acc[2][4][4] = {};

    // prefetch chunk 0 -> stage 0
#pragma unroll
    for (int it = 0; it < 2; it++) {
        int f = tid + it * 256;
        int r = f >> 2, c8 = f & 3;
        cp16(&As[0][r][c8 * 8], &A[(size_t)r * C + c8 * 8]);
    }
    { int r = tid >> 3, c8 = tid & 7;
      cp16(&Bs[0][r][c8 * 8], &W[(size_t)r * HD + c8 * 8]); }
    CP_COMMIT;

    const int NC = C / 32;
    for (int c = 0; c < NC; c++) {
        int st = c & 1;
        if (c + 1 < NC) {
            int k0 = (c + 1) * 32, s2 = st ^ 1;
#pragma unroll
            for (int it = 0; it < 2; it++) {
                int f = tid + it * 256;
                int r = f >> 2, c8 = f & 3;
                cp16(&As[s2][r][c8 * 8], &A[(size_t)r * C + k0 + c8 * 8]);
            }
            { int r = tid >> 3, c8 = tid & 7;
              cp16(&Bs[s2][r][c8 * 8], &W[(size_t)(k0 + r) * HD + c8 * 8]); }
            CP_COMMIT;
            CP_WAIT(1);
        } else {
            CP_WAIT(0);
        }
        __syncthreads();

#pragma unroll
        for (int ks = 0; ks < 2; ks++) {
            unsigned af[2][4], bf[4][2];
#pragma unroll
            for (int sm = 0; sm < 2; sm++)
                ldsm4(af[sm][0], af[sm][1], af[sm][2], af[sm][3],
                      &As[st][wm + sm * 16 + mb * 8 + mrow][ks * 16 + kb * 8]);
#pragma unroll
            for (int snp = 0; snp < 2; snp++)
                ldsm4t(bf[snp * 2][0], bf[snp * 2][1], bf[snp * 2 + 1][0], bf[snp * 2 + 1][1],
                       &Bs[st][ks * 16 + mb * 8 + mrow][wn + snp * 16 + kb * 8]);
#pragma unroll
            for (int sm = 0; sm < 2; sm++)
#pragma unroll
                for (int sn = 0; sn < 4; sn++)
                    mma_f16(acc[sm][sn], af[sm], bf[sn]);
        }
        __syncthreads();
    }

#pragma unroll
    for (int sm = 0; sm < 2; sm++) {
        int r0 = wm + sm * 16 + g;
#pragma unroll
        for (int sn = 0; sn < 4; sn++) {
            int cc = wn + sn * 8 + tq * 2;
            *(unsigned*)&out[(size_t)r0 * HD + cc]       = f2h2(acc[sm][sn][0], acc[sm][sn][1]);
            *(unsigned*)&out[(size_t)(r0 + 8) * HD + cc] = f2h2(acc[sm][sn][2], acc[sm][sn][3]);
        }
    }
}

// ---------------------------------------------------------------------------
// Kernel 2: causal flash attention, all-fp16 mma, double-buffered K/V tiles.
// 8 warps, 128 q-rows/block; warp owns 16 rows. P stays in registers
// (S-accum fragment layout == PV A-fragment layout after f2h2 packing).
// ---------------------------------------------------------------------------
#define AQ 128
#define AK 64

__global__ void __launch_bounds__(256) attn_kernel() {
    __shared__ __half Ks[2][AK][72];
    __shared__ __half Vs[2][AK][72];

    int bh = blockIdx.y;
    int qt = gridDim.x - 1 - blockIdx.x;   // heavy q-tiles first
    int t0 = qt * AQ;
    int tid = threadIdx.x;
    int lane = tid & 31, w = tid >> 5;
    int g = lane >> 2, tq = lane & 3;
    int wq = w * 16;
    int mi = lane >> 3, mrow = lane & 7;
    int mb = mi & 1, sb = mi >> 1;

    const __half* qb = g_qh + ((size_t)bh * T + t0) * HD;
    const __half* kb = g_kh + (size_t)bh * T * HD;
    const __half* vb = g_vh + (size_t)bh * T * HD;

    // Q fragments resident in registers (raw; 0.125 scale applied to S)
    unsigned qf[4][4];
#pragma unroll
    for (int ks = 0; ks < 4; ks++) {
        qf[ks][0] = *(const unsigned*)&qb[(size_t)(wq + g) * HD + ks * 16 + 2 * tq];
        qf[ks][1] = *(const unsigned*)&qb[(size_t)(wq + g + 8) * HD + ks * 16 + 2 * tq];
        qf[ks][2] = *(const unsigned*)&qb[(size_t)(wq + g) * HD + ks * 16 + 2 * tq + 8];
        qf[ks][3] = *(const unsigned*)&qb[(size_t)(wq + g + 8) * HD + ks * 16 + 2 * tq + 8];
    }

    float m0 = -1e30f, m1 = -1e30f, l0 = 0.f, l1 = 0.f;
    float accO[8][4] = {};

    int ntiles = 2 * qt + 2;   // keys 0 .. t0+127

    // prefetch tile 0 -> buf 0
#pragma unroll
    for (int it = 0; it < 2; it++) {
        int f = tid + it * 256;
        int r = f >> 3, c8 = f & 7;
        cp16(&Ks[0][r][c8 * 8], &kb[(size_t)r * HD + c8 * 8]);
        cp16(&Vs[0][r][c8 * 8], &vb[(size_t)r * HD + c8 * 8]);
    }
    CP_COMMIT;

    for (int itile = 0; itile < ntiles; itile++) {
        int buf = itile & 1;
        int s0 = itile * AK;
        __syncthreads();   // all warps done reading buf^1 (tile itile-1)
        if (itile + 1 < ntiles) {
            int sn0 = (itile + 1) * AK;
#pragma unroll
            for (int it = 0; it < 2; it++) {
                int f = tid + it * 256;
                int r = f >> 3, c8 = f & 7;
                cp16(&Ks[buf ^ 1][r][c8 * 8], &kb[(size_t)(sn0 + r) * HD + c8 * 8]);
                cp16(&Vs[buf ^ 1][r][c8 * 8], &vb[(size_t)(sn0 + r) * HD + c8 * 8]);
            }
            CP_COMMIT;
            CP_WAIT(1);
        } else {
            CP_WAIT(0);
        }
        __syncthreads();   // tile itile visible to all warps

        if (s0 > t0 + wq + 15) continue;   // tile entirely in this warp's future

        // S = Q * K^T   (B fragments via ldmatrix on K rows)
        float sc[8][4] = {};
#pragma unroll
        for (int ks = 0; ks < 4; ks++) {
#pragma unroll
            for (int snp = 0; snp < 4; snp++) {
                unsigned b0, b1, b2, b3;
                ldsm4(b0, b1, b2, b3,
                      &Ks[buf][snp * 16 + sb * 8 + mrow][ks * 16 + mb * 8]);
                unsigned bb0[2] = {b0, b1}, bb1[2] = {b2, b3};
                mma_f16(sc[snp * 2], qf[ks], bb0);
                mma_f16(sc[snp * 2 + 1], qf[ks], bb1);
            }
        }

        // scale; causal mask on crossing tiles
#pragma unroll
        for (int sn = 0; sn < 8; sn++)
#pragma unroll
            for (int j = 0; j < 4; j++) sc[sn][j] *= 0.125f;
        if (s0 + 63 > t0 + wq) {
            int r0 = t0 + wq + g, r1 = r0 + 8;
#pragma unroll
            for (int sn = 0; sn < 8; sn++) {
                int c0 = s0 + sn * 8 + tq * 2, c1 = c0 + 1;
                if (c0 > r0) sc[sn][0] = -1e30f;
                if (c1 > r0) sc[sn][1] = -1e30f;
                if (c0 > r1) sc[sn][2] = -1e30f;
                if (c1 > r1) sc[sn][3] = -1e30f;
            }
        }

        // online softmax (rows g -> c0/c1, g+8 -> c2/c3), quad shfl reduce
        float rx0 = -1e30f, rx1 = -1e30f;
#pragma unroll
        for (int sn = 0; sn < 8; sn++) {
            rx0 = fmaxf(rx0, fmaxf(sc[sn][0], sc[sn][1]));
            rx1 = fmaxf(rx1, fmaxf(sc[sn][2], sc[sn][3]));
        }
        rx0 = fmaxf(rx0, __shfl_xor_sync(0xffffffffu, rx0, 1));
        rx0 = fmaxf(rx0, __shfl_xor_sync(0xffffffffu, rx0, 2));
        rx1 = fmaxf(rx1, __shfl_xor_sync(0xffffffffu, rx1, 1));
        rx1 = fmaxf(rx1, __shfl_xor_sync(0xffffffffu, rx1, 2));
        float mn0 = fmaxf(m0, rx0), mn1 = fmaxf(m1, rx1);
        float corr0 = __expf(m0 - mn0), corr1 = __expf(m1 - mn1);
        m0 = mn0; m1 = mn1;

        float rs0 = 0.f, rs1 = 0.f;
#pragma unroll
        for (int sn = 0; sn < 8; sn++) {
            float p0 = __expf(sc[sn][0] - mn0);
            float p1 = __expf(sc[sn][1] - mn0);
            float p2 = __expf(sc[sn][2] - mn1);
            float p3 = __expf(sc[sn][3] - mn1);
            sc[sn][0] = p0; sc[sn][1] = p1; sc[sn][2] = p2; sc[sn][3] = p3;
            rs0 += p0 + p1;
            rs1 += p2 + p3;
        }
        rs0 += __shfl_xor_sync(0xffffffffu, rs0, 1);
        rs0 += __shfl_xor_sync(0xffffffffu, rs0, 2);
        rs1 += __shfl_xor_sync(0xffffffffu, rs1, 1);
        rs1 += __shfl_xor_sync(0xffffffffu, rs1, 2);
        l0 = l0 * corr0 + rs0;
        l1 = l1 * corr1 + rs1;
#pragma unroll
        for (int sn = 0; sn < 8; sn++) {
            accO[sn][0] *= corr0; accO[sn][1] *= corr0;
            accO[sn][2] *= corr1; accO[sn][3] *= corr1;
        }

        // O += P * V : P packed from sc registers, V via trans-ldmatrix
#pragma unroll
        for (int kc = 0; kc < 4; kc++) {
            unsigned af[4];
            af[0] = f2h2(sc[2 * kc][0], sc[2 * kc][1]);
            af[1] = f2h2(sc[2 * kc][2], sc[2 * kc][3]);
            af[2] = f2h2(sc[2 * kc + 1][0], sc[2 * kc + 1][1]);
            af[3] = f2h2(sc[2 * kc + 1][2], sc[2 * kc + 1][3]);
#pragma unroll
            for (int snp = 0; snp < 4; snp++) {
                unsigned b0, b1, b2, b3;
                ldsm4t(b0, b1, b2, b3,
                       &Vs[buf][kc * 16 + mb * 8 + mrow][(snp * 2 + sb) * 8]);
                unsigned bb0[2] = {b0, b1}, bb1[2] = {b2, b3};
                mma_f16(accO[snp * 2], af, bb0);
                mma_f16(accO[snp * 2 + 1], af, bb1);
            }
        }
    }

    // epilogue: normalize, write fp16 to [B,T,H*HD]
    float inv0 = 1.f / l0, inv1 = 1.f / l1;
    int b = bh >> 4, h = bh & 15;
    __half* o0 = g_oh + ((size_t)b * T + t0 + wq + g) * C + h * HD;
    __half* o1 = o0 + (size_t)8 * C;
#pragma unroll
    for (int sn = 0; sn < 8; sn++) {
        int cc = sn * 8 + tq * 2;
        *(unsigned*)&o0[cc] = f2h2(accO[sn][0] * inv0, accO[sn][1] * inv0);
        *(unsigned*)&o1[cc] = f2h2(accO[sn][2] * inv1, accO[sn][3] * inv1);
    }
}

// ---------------------------------------------------------------------------
// Kernel 3: output projection. fp16 mma + ldmatrix + cp.async pipeline.
// ---------------------------------------------------------------------------
__global__ void __launch_bounds__(256) proj_kernel(
    const float* __restrict__ bo, float* __restrict__ Y)
{
    __shared__ __half As[2][128][40];
    __shared__ __half Bs[2][32][72];

    int n0 = blockIdx.x * 64;
    int m0 = blockIdx.y * 128;

    const __half* A = g_oh + (size_t)m0 * C;
    const __half* Bp = g_woth + n0;

    int tid = threadIdx.x;
    int lane = tid & 31, w = tid >> 5;
    int g = lane >> 2, tq = lane & 3;
    int wm = (w >> 1) * 32, wn = (w & 1) * 32;
    int mi = lane >> 3, mrow = lane & 7;
    int mb = mi & 1, kbl = mi >> 1;

    float acc[2][4][4] = {};

#pragma unroll
    for (int it = 0; it < 2; it++) {
        int f = tid + it * 256;
        int r = f >> 2, c8 = f & 3;
        cp16(&As[0][r][c8 * 8], &A[(size_t)r * C + c8 * 8]);
    }
    { int r = tid >> 3, c8 = tid & 7;
      cp16(&Bs[0][r][c8 * 8], &Bp[(size_t)r * C + c8 * 8]); }
    CP_COMMIT;

    const int NC = C / 32;
    for (int c = 0; c < NC; c++) {
        int st = c & 1;
        if (c + 1 < NC) {
            int k0 = (c + 1) * 32, s2 = st ^ 1;
#pragma unroll
            for (int it = 0; it < 2; it++) {
                int f = tid + it * 256;
                int r = f >> 2, c8 = f & 3;
                cp16(&As[s2][r][c8 * 8], &A[(size_t)r * C + k0 + c8 * 8]);
            }
            { int r = tid >> 3, c8 = tid & 7;
              cp16(&Bs[s2][r][c8 * 8], &Bp[(size_t)(k0 + r) * C + c8 * 8]); }
            CP_COMMIT;
            CP_WAIT(1);
        } else {
            CP_WAIT(0);
        }
        __syncthreads();

#pragma unroll
        for (int ks = 0; ks < 2; ks++) {
            unsigned af[2][4], bf[4][2];
#pragma unroll
            for (int sm = 0; sm < 2; sm++)
                ldsm4(af[sm][0], af[sm][1], af[sm][2], af[sm][3],
                      &As[st][wm + sm * 16 + mb * 8 + mrow][ks * 16 + kbl * 8]);
#pragma unroll
            for (int snp = 0; snp < 2; snp++)
                ldsm4t(bf[snp * 2][0], bf[snp * 2][1], bf[snp * 2 + 1][0], bf[snp * 2 + 1][1],
                       &Bs[st][ks * 16 + mb * 8 + mrow][wn + snp * 16 + kbl * 8]);
#pragma unroll
            for (int sm = 0; sm < 2; sm++)
#pragma unroll
                for (int sn = 0; sn < 4; sn++)
                    mma_f16(acc[sm][sn], af[sm], bf[sn]);
        }
        __syncthreads();
    }

#pragma unroll
    for (int sm = 0; sm < 2; sm++) {
        int r0 = m0 + wm + sm * 16 + g;
#pragma unroll
        for (int sn = 0; sn < 4; sn++) {
            int cc = n0 + wn + sn * 8 + tq * 2;
            float b0 = bo[cc], b1 = bo[cc + 1];
            *(float2*)&Y[(size_t)r0 * C + cc] =
                make_float2(acc[sm][sn][0] + b0, acc[sm][sn][1] + b1);
            *(float2*)&Y[(size_t)(r0 + 8) * C + cc] =
                make_float2(acc[sm][sn][2] + b0, acc[sm][sn][3] + b1);
        }
    }
}

// ---------------------------------------------------------------------------
extern "C" void kernel_launch(void* const* d_in, const int* in_sizes, int n_in,
                              void* d_out, int out_size)
{
    const float* x  = (const float*)d_in[0];
    const float* Wq = (const float*)d_in[1];
    const float* Wk = (const float*)d_in[2];
    const float* Wv = (const float*)d_in[3];
    const float* Wo = (const float*)d_in[4];
    const float* bo = (const float*)d_in[5];
    float* y = (float*)d_out;

    prep_convert_kernel<<<dim3((B * T * C / 4 + 255) / 256, 4), 256>>>(x, Wq, Wk, Wv);
    transpose_wo_kernel<<<dim3(C / 32, C / 32), dim3(32, 8)>>>(Wo);
    qkv_kernel<<<dim3(T / 128, 3, BH), 256>>>();
    attn_kernel<<<dim3(T / AQ, BH), 256>>>();
    proj_kernel<<<dim3(C / 64, (B * T) / 128), 256>>>(bo, y);
}

// round 9
// speedup vs baseline: 11.9559x; 1.1128x over previous
#include <cuda_runtime.h>
#include <cuda_fp16.h>
#include <cstdint>

#define B 2
#define T 2048
#define C 1024
#define H 16
#define HD 64
#define BH (B * H)
#define N3 (3 * C)   // fused QKV output width = 3072

// ---- scratch (device globals; no runtime allocation allowed) ----
__device__ __half g_xh[(size_t)B * T * C];        // x in fp16
__device__ __half g_wi[(size_t)C * N3];           // interleaved W: [c][sel*1024+h*64+d]
__device__ __half g_woth[(size_t)C * C];          // Wo^T in fp16
__device__ __half g_qh[(size_t)BH * T * HD];      // Q pre-scaled by 0.125*log2e
__device__ __half g_kh[(size_t)BH * T * HD];
__device__ __half g_vh[(size_t)BH * T * HD];
__device__ __half g_oh[(size_t)B * T * C];        // attention out [B,T,H*HD]

// ---------------------------------------------------------------------------
// helpers
// ---------------------------------------------------------------------------
__device__ __forceinline__ unsigned f2h2(float lo, float hi) {
    unsigned r;
    asm("cvt.rn.f16x2.f32 %0, %1, %2;" : "=r"(r) : "f"(hi), "f"(lo));
    return r;
}

__device__ __forceinline__ float ex2f(float x) {
    float r;
    asm("ex2.approx.f32 %0, %1;" : "=f"(r) : "f"(x));
    return r;
}

__device__ __forceinline__ void mma_f16(float c[4], const unsigned a[4], const unsigned b[2]) {
    asm("mma.sync.aligned.m16n8k16.row.col.f32.f16.f16.f32 "
        "{%0,%1,%2,%3},{%4,%5,%6,%7},{%8,%9},{%0,%1,%2,%3};"
        : "+f"(c[0]), "+f"(c[1]), "+f"(c[2]), "+f"(c[3])
        : "r"(a[0]), "r"(a[1]), "r"(a[2]), "r"(a[3]), "r"(b[0]), "r"(b[1]));
}

__device__ __forceinline__ void ldsm4(unsigned& d0, unsigned& d1, unsigned& d2, unsigned& d3,
                                      const void* p) {
    unsigned a = (unsigned)__cvta_generic_to_shared(p);
    asm volatile("ldmatrix.sync.aligned.m8n8.x4.shared.b16 {%0,%1,%2,%3}, [%4];"
                 : "=r"(d0), "=r"(d1), "=r"(d2), "=r"(d3) : "r"(a));
}

__device__ __forceinline__ void ldsm4t(unsigned& d0, unsigned& d1, unsigned& d2, unsigned& d3,
                                       const void* p) {
    unsigned a = (unsigned)__cvta_generic_to_shared(p);
    asm volatile("ldmatrix.sync.aligned.m8n8.x4.trans.shared.b16 {%0,%1,%2,%3}, [%4];"
                 : "=r"(d0), "=r"(d1), "=r"(d2), "=r"(d3) : "r"(a));
}

__device__ __forceinline__ void cp16(void* smem_dst, const void* gmem_src) {
    unsigned saddr = (unsigned)__cvta_generic_to_shared(smem_dst);
    asm volatile("cp.async.cg.shared.global [%0], [%1], 16;" :: "r"(saddr), "l"(gmem_src));
}
#define CP_COMMIT asm volatile("cp.async.commit_group;")
#define CP_WAIT(n) asm volatile("cp.async.wait_group %0;" :: "n"(n))

// ---------------------------------------------------------------------------
// Kernel P0: convert x to fp16; interleave Wq/Wk/Wv into g_wi (fp16).
// g_wi[c][sel*1024 + h*64 + d] = W_sel[h][c][d]
// ---------------------------------------------------------------------------
__global__ void prep_kernel(const float* __restrict__ x,
                            const float* __restrict__ Wq,
                            const float* __restrict__ Wk,
                            const float* __restrict__ Wv) {
    int seg = blockIdx.y;
    int i = (blockIdx.x * 256 + threadIdx.x) * 4;
    if (seg == 0) {
        if (i < B * T * C) {
            float4 v = *(const float4*)&x[i];
            *(__half2*)&g_xh[i]     = __floats2half2_rn(v.x, v.y);
            *(__half2*)&g_xh[i + 2] = __floats2half2_rn(v.z, v.w);
        }
    } else {
        const float* src = seg == 1 ? Wq : seg == 2 ? Wk : Wv;
        if (i < H * C * HD) {
            float4 v = *(const float4*)&src[i];
            int d = i & 63, c = (i >> 6) & 1023, h = i >> 16;
            __half* dst = g_wi + ((size_t)c * N3 + (seg - 1) * 1024 + h * 64 + d);
            *(__half2*)&dst[0] = __floats2half2_rn(v.x, v.y);
            *(__half2*)&dst[2] = __floats2half2_rn(v.z, v.w);
        }
    }
}

// ---------------------------------------------------------------------------
// Kernel P1: transpose Wo [C,C] -> g_woth (fp16).
// ---------------------------------------------------------------------------
__global__ void transpose_wo_kernel(const float* __restrict__ Wo) {
    __shared__ float tile[32][33];
    int x0 = blockIdx.x * 32;
    int y0 = blockIdx.y * 32;
    int tx = threadIdx.x, ty = threadIdx.y;
#pragma unroll
    for (int i = 0; i < 32; i += 8)
        tile[ty + i][tx] = Wo[(size_t)(y0 + ty + i) * C + x0 + tx];
    __syncthreads();
#pragma unroll
    for (int i = 0; i < 32; i += 8)
        g_woth[(size_t)(x0 + ty + i) * C + y0 + tx] = __float2half(tile[tx][ty + i]);
}

// ---------------------------------------------------------------------------
// Kernel 1: fused QKV GEMM [4096 x 3072 x 1024], fp16 mma + ldmatrix +
// 2-stage cp.async. Block 256 thr = 8 warps (4x2); tile 128x128; warp 32x64.
// Q columns (sel==0) scaled by 0.125*log2e for exp2-domain softmax.
// ---------------------------------------------------------------------------
__global__ void __launch_bounds__(256) qkv_kernel() {
    __shared__ __half As[2][128][40];    // rows 64B data, pitch 80B
    __shared__ __half Bs[2][32][136];    // rows 256B data, pitch 272B

    int n0 = blockIdx.x * 128;
    int m0 = blockIdx.y * 128;

    const __half* A = g_xh + (size_t)m0 * C;
    const __half* Bp = g_wi + n0;

    int tid = threadIdx.x;
    int lane = tid & 31, w = tid >> 5;
    int g = lane >> 2, tq = lane & 3;
    int wm = (w & 3) * 32, wn = (w >> 2) * 64;
    int mi = lane >> 3, mrow = lane & 7;
    int mb = mi & 1, kb = mi >> 1;

    float acc[2][8][4] = {};

    // prefetch chunk 0 -> stage 0
#pragma unroll
    for (int it = 0; it < 2; it++) {
        int f = tid + it * 256;
        int r = f >> 2, c8 = f & 3;
        cp16(&As[0][r][c8 * 8], &A[(size_t)r * C + c8 * 8]);
    }
#pragma unroll
    for (int it = 0; it < 2; it++) {
        int f = tid + it * 256;
        int r = f >> 4, c8 = f & 15;
        cp16(&Bs[0][r][c8 * 8], &Bp[(size_t)r * N3 + c8 * 8]);
    }
    CP_COMMIT;

    const int NC = C / 32;
    for (int c = 0; c < NC; c++) {
        int st = c & 1;
        if (c + 1 < NC) {
            int k0 = (c + 1) * 32, s2 = st ^ 1;
#pragma unroll
            for (int it = 0; it < 2; it++) {
                int f = tid + it * 256;
                int r = f >> 2, c8 = f & 3;
                cp16(&As[s2][r][c8 * 8], &A[(size_t)r * C + k0 + c8 * 8]);
            }
#pragma unroll
            for (int it = 0; it < 2; it++) {
                int f = tid + it * 256;
                int r = f >> 4, c8 = f & 15;
                cp16(&Bs[s2][r][c8 * 8], &Bp[(size_t)(k0 + r) * N3 + c8 * 8]);
            }
            CP_COMMIT;
            CP_WAIT(1);
        } else {
            CP_WAIT(0);
        }
        __syncthreads();

#pragma unroll
        for (int ks = 0; ks < 2; ks++) {
            unsigned af[2][4], bf[8][2];
#pragma unroll
            for (int sm = 0; sm < 2; sm++)
                ldsm4(af[sm][0], af[sm][1], af[sm][2], af[sm][3],
                      &As[st][wm + sm * 16 + mb * 8 + mrow][ks * 16 + kb * 8]);
#pragma unroll
            for (int snp = 0; snp < 4; snp++)
                ldsm4t(bf[snp * 2][0], bf[snp * 2][1], bf[snp * 2 + 1][0], bf[snp * 2 + 1][1],
                       &Bs[st][ks * 16 + mb * 8 + mrow][wn + snp * 16 + kb * 8]);
#pragma unroll
            for (int sm = 0; sm < 2; sm++)
#pragma unroll
                for (int sn = 0; sn < 8; sn++)
                    mma_f16(acc[sm][sn], af[sm], bf[sn]);
        }
        __syncthreads();
    }

    // epilogue: route columns to q/k/v tensors ([bh][t][d] layout)
    int sel = n0 >> 10;                       // constant per block (128 | 1024)
    __half* outb = sel == 0 ? g_qh : sel == 1 ? g_kh : g_vh;
    float scl = (sel == 0) ? 0.18033688f : 1.f;   // 0.125 * log2(e)
#pragma unroll
    for (int sm = 0; sm < 2; sm++) {
        int m = m0 + wm + sm * 16 + g;
        int b = m >> 11, t = m & 2047;
#pragma unroll
        for (int sn = 0; sn < 8; sn++) {
            int nn = (n0 & 1023) + wn + sn * 8 + tq * 2;
            int h = nn >> 6, d = nn & 63;
            __half* p0 = outb + (((size_t)(b * 16 + h) * T + t) * HD + d);
            *(unsigned*)p0 = f2h2(acc[sm][sn][0] * scl, acc[sm][sn][1] * scl);
            *(unsigned*)(p0 + 8 * HD) = f2h2(acc[sm][sn][2] * scl, acc[sm][sn][3] * scl);
        }
    }
}

// ---------------------------------------------------------------------------
// Kernel 2: causal flash attention, all-fp16 mma, exp2-domain softmax,
// double-buffered K/V. 8 warps, 128 q-rows/block; warp owns 16 rows.
// Q comes in pre-scaled by 0.125*log2e, so S is directly in log2 units.
// ---------------------------------------------------------------------------
#define AQ 128
#define AK 64

__global__ void __launch_bounds__(256) attn_kernel() {
    __shared__ __half Ks[2][AK][72];
    __shared__ __half Vs[2][AK][72];

    int bh = blockIdx.y;
    int qt = gridDim.x - 1 - blockIdx.x;   // heavy q-tiles first
    int t0 = qt * AQ;
    int tid = threadIdx.x;
    int lane = tid & 31, w = tid >> 5;
    int g = lane >> 2, tq = lane & 3;
    int wq = w * 16;
    int mi = lane >> 3, mrow = lane & 7;
    int mb = mi & 1, sb = mi >> 1;

    const __half* qb = g_qh + ((size_t)bh * T + t0) * HD;
    const __half* kb = g_kh + (size_t)bh * T * HD;
    const __half* vb = g_vh + (size_t)bh * T * HD;

    unsigned qf[4][4];
#pragma unroll
    for (int ks = 0; ks < 4; ks++) {
        qf[ks][0] = *(const unsigned*)&qb[(size_t)(wq + g) * HD + ks * 16 + 2 * tq];
        qf[ks][1] = *(const unsigned*)&qb[(size_t)(wq + g + 8) * HD + ks * 16 + 2 * tq];
        qf[ks][2] = *(const unsigned*)&qb[(size_t)(wq + g) * HD + ks * 16 + 2 * tq + 8];
        qf[ks][3] = *(const unsigned*)&qb[(size_t)(wq + g + 8) * HD + ks * 16 + 2 * tq + 8];
    }

    float m0 = -1e30f, m1 = -1e30f, l0 = 0.f, l1 = 0.f;
    float accO[8][4] = {};

    int ntiles = 2 * qt + 2;   // keys 0 .. t0+127

    // prefetch tile 0 -> buf 0
#pragma unroll
    for (int it = 0; it < 2; it++) {
        int f = tid + it * 256;
        int r = f >> 3, c8 = f & 7;
        cp16(&Ks[0][r][c8 * 8], &kb[(size_t)r * HD + c8 * 8]);
        cp16(&Vs[0][r][c8 * 8], &vb[(size_t)r * HD + c8 * 8]);
    }
    CP_COMMIT;

    for (int itile = 0; itile < ntiles; itile++) {
        int buf = itile & 1;
        int s0 = itile * AK;
        __syncthreads();   // all warps done reading buf^1
        if (itile + 1 < ntiles) {
            int sn0 = (itile + 1) * AK;
#pragma unroll
            for (int it = 0; it < 2; it++) {
                int f = tid + it * 256;
                int r = f >> 3, c8 = f & 7;
                cp16(&Ks[buf ^ 1][r][c8 * 8], &kb[(size_t)(sn0 + r) * HD + c8 * 8]);
                cp16(&Vs[buf ^ 1][r][c8 * 8], &vb[(size_t)(sn0 + r) * HD + c8 * 8]);
            }
            CP_COMMIT;
            CP_WAIT(1);
        } else {
            CP_WAIT(0);
        }
        __syncthreads();

        if (s0 > t0 + wq + 15) continue;   // tile entirely in this warp's future

        // S = Q * K^T  (log2-domain scores)
        float sc[8][4] = {};
#pragma unroll
        for (int ks = 0; ks < 4; ks++) {
#pragma unroll
            for (int snp = 0; snp < 4; snp++) {
                unsigned b0, b1, b2, b3;
                ldsm4(b0, b1, b2, b3,
                      &Ks[buf][snp * 16 + sb * 8 + mrow][ks * 16 + mb * 8]);
                unsigned bb0[2] = {b0, b1}, bb1[2] = {b2, b3};
                mma_f16(sc[snp * 2], qf[ks], bb0);
                mma_f16(sc[snp * 2 + 1], qf[ks], bb1);
            }
        }

        // causal mask on crossing tiles
        if (s0 + 63 > t0 + wq) {
            int r0 = t0 + wq + g, r1 = r0 + 8;
#pragma unroll
            for (int sn = 0; sn < 8; sn++) {
                int c0 = s0 + sn * 8 + tq * 2, c1 = c0 + 1;
                if (c0 > r0) sc[sn][0] = -1e30f;
                if (c1 > r0) sc[sn][1] = -1e30f;
                if (c0 > r1) sc[sn][2] = -1e30f;
                if (c1 > r1) sc[sn][3] = -1e30f;
            }
        }

        // online softmax in exp2 domain, quad shfl reduce
        float rx0 = -1e30f, rx1 = -1e30f;
#pragma unroll
        for (int sn = 0; sn < 8; sn++) {
            rx0 = fmaxf(rx0, fmaxf(sc[sn][0], sc[sn][1]));
            rx1 = fmaxf(rx1, fmaxf(sc[sn][2], sc[sn][3]));
        }
        rx0 = fmaxf(rx0, __shfl_xor_sync(0xffffffffu, rx0, 1));
        rx0 = fmaxf(rx0, __shfl_xor_sync(0xffffffffu, rx0, 2));
        rx1 = fmaxf(rx1, __shfl_xor_sync(0xffffffffu, rx1, 1));
        rx1 = fmaxf(rx1, __shfl_xor_sync(0xffffffffu, rx1, 2));
        float mn0 = fmaxf(m0, rx0), mn1 = fmaxf(m1, rx1);
        float corr0 = ex2f(m0 - mn0), corr1 = ex2f(m1 - mn1);
        m0 = mn0; m1 = mn1;

        float rs0 = 0.f, rs1 = 0.f;
#pragma unroll
        for (int sn = 0; sn < 8; sn++) {
            float p0 = ex2f(sc[sn][0] - mn0);
            float p1 = ex2f(sc[sn][1] - mn0);
            float p2 = ex2f(sc[sn][2] - mn1);
            float p3 = ex2f(sc[sn][3] - mn1);
            sc[sn][0] = p0; sc[sn][1] = p1; sc[sn][2] = p2; sc[sn][3] = p3;
            rs0 += p0 + p1;
            rs1 += p2 + p3;
        }
        rs0 += __shfl_xor_sync(0xffffffffu, rs0, 1);
        rs0 += __shfl_xor_sync(0xffffffffu, rs0, 2);
        rs1 += __shfl_xor_sync(0xffffffffu, rs1, 1);
        rs1 += __shfl_xor_sync(0xffffffffu, rs1, 2);
        l0 = l0 * corr0 + rs0;
        l1 = l1 * corr1 + rs1;
#pragma unroll
        for (int sn = 0; sn < 8; sn++) {
            accO[sn][0] *= corr0; accO[sn][1] *= corr0;
            accO[sn][2] *= corr1; accO[sn][3] *= corr1;
        }

        // O += P * V : P packed straight from sc registers
#pragma unroll
        for (int kc = 0; kc < 4; kc++) {
            unsigned af[4];
            af[0] = f2h2(sc[2 * kc][0], sc[2 * kc][1]);
            af[1] = f2h2(sc[2 * kc][2], sc[2 * kc][3]);
            af[2] = f2h2(sc[2 * kc + 1][0], sc[2 * kc + 1][1]);
            af[3] = f2h2(sc[2 * kc + 1][2], sc[2 * kc + 1][3]);
#pragma unroll
            for (int snp = 0; snp < 4; snp++) {
                unsigned b0, b1, b2, b3;
                ldsm4t(b0, b1, b2, b3,
                       &Vs[buf][kc * 16 + mb * 8 + mrow][(snp * 2 + sb) * 8]);
                unsigned bb0[2] = {b0, b1}, bb1[2] = {b2, b3};
                mma_f16(accO[snp * 2], af, bb0);
                mma_f16(accO[snp * 2 + 1], af, bb1);
            }
        }
    }

    // epilogue: normalize, write fp16 to [B,T,H*HD]
    float inv0 = 1.f / l0, inv1 = 1.f / l1;
    int b = bh >> 4, h = bh & 15;
    __half* o0 = g_oh + ((size_t)b * T + t0 + wq + g) * C + h * HD;
    __half* o1 = o0 + (size_t)8 * C;
#pragma unroll
    for (int sn = 0; sn < 8; sn++) {
        int cc = sn * 8 + tq * 2;
        *(unsigned*)&o0[cc] = f2h2(accO[sn][0] * inv0, accO[sn][1] * inv0);
        *(unsigned*)&o1[cc] = f2h2(accO[sn][2] * inv1, accO[sn][3] * inv1);
    }
}

// ---------------------------------------------------------------------------
// Kernel 3: output projection [4096 x 1024 x 1024], 128x128 tiles.
// ---------------------------------------------------------------------------
__global__ void __launch_bounds__(256) proj_kernel(
    const float* __restrict__ bo, float* __restrict__ Y)
{
    __shared__ __half As[2][128][40];
    __shared__ __half Bs[2][32][136];

    int n0 = blockIdx.x * 128;
    int m0 = blockIdx.y * 128;

    const __half* A = g_oh + (size_t)m0 * C;
    const __half* Bp = g_woth + n0;

    int tid = threadIdx.x;
    int lane = tid & 31, w = tid >> 5;
    int g = lane >> 2, tq = lane & 3;
    int wm = (w & 3) * 32, wn = (w >> 2) * 64;
    int mi = lane >> 3, mrow = lane & 7;
    int mb = mi & 1, kb = mi >> 1;

    float acc[2][8][4] = {};

#pragma unroll
    for (int it = 0; it < 2; it++) {
        int f = tid + it * 256;
        int r = f >> 2, c8 = f & 3;
        cp16(&As[0][r][c8 * 8], &A[(size_t)r * C + c8 * 8]);
    }
#pragma unroll
    for (int it = 0; it < 2; it++) {
        int f = tid + it * 256;
        int r = f >> 4, c8 = f & 15;
        cp16(&Bs[0][r][c8 * 8], &Bp[(size_t)r * C + c8 * 8]);
    }
    CP_COMMIT;

    const int NC = C / 32;
    for (int c = 0; c < NC; c++) {
        int st = c & 1;
        if (c + 1 < NC) {
            int k0 = (c + 1) * 32, s2 = st ^ 1;
#pragma unroll
            for (int it = 0; it < 2; it++) {
                int f = tid + it * 256;
                int r = f >> 2, c8 = f & 3;
                cp16(&As[s2][r][c8 * 8], &A[(size_t)r * C + k0 + c8 * 8]);
            }
#pragma unroll
            for (int it = 0; it < 2; it++) {
                int f = tid + it * 256;
                int r = f >> 4, c8 = f & 15;
                cp16(&Bs[s2][r][c8 * 8], &Bp[(size_t)(k0 + r) * C + c8 * 8]);
            }
            CP_COMMIT;
            CP_WAIT(1);
        } else {
            CP_WAIT(0);
        }
        __syncthreads();

#pragma unroll
        for (int ks = 0; ks < 2; ks++) {
            unsigned af[2][4], bf[8][2];
#pragma unroll
            for (int sm = 0; sm < 2; sm++)
                ldsm4(af[sm][0], af[sm][1], af[sm][2], af[sm][3],
                      &As[st][wm + sm * 16 + mb * 8 + mrow][ks * 16 + kb * 8]);
#pragma unroll
            for (int snp = 0; snp < 4; snp++)
                ldsm4t(bf[snp * 2][0], bf[snp * 2][1], bf[snp * 2 + 1][0], bf[snp * 2 + 1][1],
                       &Bs[st][ks * 16 + mb * 8 + mrow][wn + snp * 16 + kb * 8]);
#pragma unroll
            for (int sm = 0; sm < 2; sm++)
#pragma unroll
                for (int sn = 0; sn < 8; sn++)
                    mma_f16(acc[sm][sn], af[sm], bf[sn]);
        }
        __syncthreads();
    }

#pragma unroll
    for (int sm = 0; sm < 2; sm++) {
        int r0 = m0 + wm + sm * 16 + g;
#pragma unroll
        for (int sn = 0; sn < 8; sn++) {
            int cc = n0 + wn + sn * 8 + tq * 2;
            float b0 = bo[cc], b1 = bo[cc + 1];
            *(float2*)&Y[(size_t)r0 * C + cc] =
                make_float2(acc[sm][sn][0] + b0, acc[sm][sn][1] + b1);
            *(float2*)&Y[(size_t)(r0 + 8) * C + cc] =
                make_float2(acc[sm][sn][2] + b0, acc[sm][sn][3] + b1);
        }
    }
}

// ---------------------------------------------------------------------------
extern "C" void kernel_launch(void* const* d_in, const int* in_sizes, int n_in,
                              void* d_out, int out_size)
{
    const float* x  = (const float*)d_in[0];
    const float* Wq = (const float*)d_in[1];
    const float* Wk = (const float*)d_in[2];
    const float* Wv = (const float*)d_in[3];
    const float* Wo = (const float*)d_in[4];
    const float* bo = (const float*)d_in[5];
    float* y = (float*)d_out;

    prep_kernel<<<dim3((B * T * C / 4 + 255) / 256, 4), 256>>>(x, Wq, Wk, Wv);
    transpose_wo_kernel<<<dim3(C / 32, C / 32), dim3(32, 8)>>>(Wo);
    qkv_kernel<<<dim3(N3 / 128, (B * T) / 128), 256>>>();
    attn_kernel<<<dim3(T / AQ, BH), 256>>>();
    proj_kernel<<<dim3(C / 128, (B * T) / 128), 256>>>(bo, y);
}

// round 11
// speedup vs baseline: 12.4008x; 1.0372x over previous
#include <cuda_runtime.h>
#include <cuda_fp16.h>
#include <cstdint>

#define B 2
#define T 2048
#define C 1024
#define H 16
#define HD 64
#define BH (B * H)
#define N3 (3 * C)   // fused QKV output width = 3072

// ---- scratch (device globals; no runtime allocation allowed) ----
__device__ __half g_xh[(size_t)B * T * C];        // x in fp16
__device__ __half g_wi[(size_t)C * N3];           // interleaved W: [c][sel*1024+h*64+d]
__device__ __half g_woth[(size_t)C * C];          // Wo^T in fp16
__device__ __half g_qh[(size_t)BH * T * HD];      // Q pre-scaled by 0.125*log2e
__device__ __half g_kh[(size_t)BH * T * HD];
__device__ __half g_vh[(size_t)BH * T * HD];
__device__ __half g_oh[(size_t)B * T * C];        // attention out [B,T,H*HD]

// ---------------------------------------------------------------------------
// helpers
// ---------------------------------------------------------------------------
__device__ __forceinline__ unsigned f2h2(float lo, float hi) {
    unsigned r;
    asm("cvt.rn.f16x2.f32 %0, %1, %2;" : "=r"(r) : "f"(hi), "f"(lo));
    return r;
}
__device__ __forceinline__ float ex2f(float x) {
    float r;
    asm("ex2.approx.f32 %0, %1;" : "=f"(r) : "f"(x));
    return r;
}
__device__ __forceinline__ unsigned h2ex2(unsigned x) {
    unsigned r;
    asm("ex2.approx.f16x2 %0, %1;" : "=r"(r) : "r"(x));
    return r;
}
__device__ __forceinline__ void mma_f16(float c[4], const unsigned a[4], const unsigned b[2]) {
    asm("mma.sync.aligned.m16n8k16.row.col.f32.f16.f16.f32 "
        "{%0,%1,%2,%3},{%4,%5,%6,%7},{%8,%9},{%0,%1,%2,%3};"
        : "+f"(c[0]), "+f"(c[1]), "+f"(c[2]), "+f"(c[3])
        : "r"(a[0]), "r"(a[1]), "r"(a[2]), "r"(a[3]), "r"(b[0]), "r"(b[1]));
}
__device__ __forceinline__ void ldsm4(unsigned& d0, unsigned& d1, unsigned& d2, unsigned& d3,
                                      const void* p) {
    unsigned a = (unsigned)__cvta_generic_to_shared(p);
    asm volatile("ldmatrix.sync.aligned.m8n8.x4.shared.b16 {%0,%1,%2,%3}, [%4];"
                 : "=r"(d0), "=r"(d1), "=r"(d2), "=r"(d3) : "r"(a));
}
__device__ __forceinline__ void ldsm4t(unsigned& d0, unsigned& d1, unsigned& d2, unsigned& d3,
                                       const void* p) {
    unsigned a = (unsigned)__cvta_generic_to_shared(p);
    asm volatile("ldmatrix.sync.aligned.m8n8.x4.trans.shared.b16 {%0,%1,%2,%3}, [%4];"
                 : "=r"(d0), "=r"(d1), "=r"(d2), "=r"(d3) : "r"(a));
}
__device__ __forceinline__ void cp16(void* smem_dst, const void* gmem_src) {
    unsigned saddr = (unsigned)__cvta_generic_to_shared(smem_dst);
    asm volatile("cp.async.cg.shared.global [%0], [%1], 16;" :: "r"(saddr), "l"(gmem_src));
}
#define CP_COMMIT asm volatile("cp.async.commit_group;")
#define CP_WAIT(n) asm volatile("cp.async.wait_group %0;" :: "n"(n))

// ---------------------------------------------------------------------------
// Kernel P0: convert x to fp16; interleave Wq/Wk/Wv into g_wi (fp16).
// ---------------------------------------------------------------------------
__global__ void prep_kernel(const float* __restrict__ x,
                            const float* __restrict__ Wq,
                            const float* __restrict__ Wk,
                            const float* __restrict__ Wv) {
    int seg = blockIdx.y;
    int i = (blockIdx.x * 256 + threadIdx.x) * 4;
    if (seg == 0) {
        if (i < B * T * C) {
            float4 v = *(const float4*)&x[i];
            *(__half2*)&g_xh[i]     = __floats2half2_rn(v.x, v.y);
            *(__half2*)&g_xh[i + 2] = __floats2half2_rn(v.z, v.w);
        }
    } else {
        const float* src = seg == 1 ? Wq : seg == 2 ? Wk : Wv;
        if (i < H * C * HD) {
            float4 v = *(const float4*)&src[i];
            int d = i & 63, c = (i >> 6) & 1023, h = i >> 16;
            __half* dst = g_wi + ((size_t)c * N3 + (seg - 1) * 1024 + h * 64 + d);
            *(__half2*)&dst[0] = __floats2half2_rn(v.x, v.y);
            *(__half2*)&dst[2] = __floats2half2_rn(v.z, v.w);
        }
    }
}

// ---------------------------------------------------------------------------
// Kernel P1: transpose Wo [C,C] -> g_woth (fp16).
// ---------------------------------------------------------------------------
__global__ void transpose_wo_kernel(const float* __restrict__ Wo) {
    __shared__ float tile[32][33];
    int x0 = blockIdx.x * 32;
    int y0 = blockIdx.y * 32;
    int tx = threadIdx.x, ty = threadIdx.y;
#pragma unroll
    for (int i = 0; i < 32; i += 8)
        tile[ty + i][tx] = Wo[(size_t)(y0 + ty + i) * C + x0 + tx];
    __syncthreads();
#pragma unroll
    for (int i = 0; i < 32; i += 8)
        g_woth[(size_t)(x0 + ty + i) * C + y0 + tx] = __float2half(tile[tx][ty + i]);
}

// ---------------------------------------------------------------------------
// Kernel 1: fused QKV GEMM [4096 x 3072 x 1024], fp16 mma + ldmatrix +
// 2-stage cp.async, K-chunk 64. Block 256 thr = 8 warps; tile 128x128.
// Q columns (sel==0) scaled by 0.125*log2e for exp2-domain softmax.
// ---------------------------------------------------------------------------
__global__ void __launch_bounds__(256) qkv_kernel() {
    __shared__ __half As[2][128][72];    // rows 128B data, pitch 144B
    __shared__ __half Bs[2][64][136];    // rows 256B data, pitch 272B

    int n0 = blockIdx.x * 128;
    int m0 = blockIdx.y * 128;

    const __half* A = g_xh + (size_t)m0 * C;
    const __half* Bp = g_wi + n0;

    int tid = threadIdx.x;
    int lane = tid & 31, w = tid >> 5;
    int g = lane >> 2, tq = lane & 3;
    int wm = (w & 3) * 32, wn = (w >> 2) * 64;
    int mi = lane >> 3, mrow = lane & 7;
    int mb = mi & 1, kb = mi >> 1;

    float acc[2][8][4] = {};

    // prefetch chunk 0 -> stage 0
#pragma unroll
    for (int it = 0; it < 4; it++) {
        int f = tid + it * 256;
        int r = f >> 3, c8 = f & 7;
        cp16(&As[0][r][c8 * 8], &A[(size_t)r * C + c8 * 8]);
    }
#pragma unroll
    for (int it = 0; it < 4; it++) {
        int f = tid + it * 256;
        int r = f >> 4, c8 = f & 15;
        cp16(&Bs[0][r][c8 * 8], &Bp[(size_t)r * N3 + c8 * 8]);
    }
    CP_COMMIT;

    const int NC = C / 64;
    for (int c = 0; c < NC; c++) {
        int st = c & 1;
        if (c + 1 < NC) {
            int k0 = (c + 1) * 64, s2 = st ^ 1;
#pragma unroll
            for (int it = 0; it < 4; it++) {
                int f = tid + it * 256;
                int r = f >> 3, c8 = f & 7;
                cp16(&As[s2][r][c8 * 8], &A[(size_t)r * C + k0 + c8 * 8]);
            }
#pragma unroll
            for (int it = 0; it < 4; it++) {
                int f = tid + it * 256;
                int r = f >> 4, c8 = f & 15;
                cp16(&Bs[s2][r][c8 * 8], &Bp[(size_t)(k0 + r) * N3 + c8 * 8]);
            }
            CP_COMMIT;
            CP_WAIT(1);
        } else {
            CP_WAIT(0);
        }
        __syncthreads();

#pragma unroll
        for (int ks = 0; ks < 4; ks++) {
            unsigned af[2][4], bf[8][2];
#pragma unroll
            for (int sm = 0; sm < 2; sm++)
                ldsm4(af[sm][0], af[sm][1], af[sm][2], af[sm][3],
                      &As[st][wm + sm * 16 + mb * 8 + mrow][ks * 16 + kb * 8]);
#pragma unroll
            for (int snp = 0; snp < 4; snp++)
                ldsm4t(bf[snp * 2][0], bf[snp * 2][1], bf[snp * 2 + 1][0], bf[snp * 2 + 1][1],
                       &Bs[st][ks * 16 + mb * 8 + mrow][wn + snp * 16 + kb * 8]);
#pragma unroll
            for (int sm = 0; sm < 2; sm++)
#pragma unroll
                for (int sn = 0; sn < 8; sn++)
                    mma_f16(acc[sm][sn], af[sm], bf[sn]);
        }
        __syncthreads();
    }

    // epilogue: route columns to q/k/v tensors ([bh][t][d] layout)
    int sel = n0 >> 10;
    __half* outb = sel == 0 ? g_qh : sel == 1 ? g_kh : g_vh;
    float scl = (sel == 0) ? 0.18033688f : 1.f;   // 0.125 * log2(e)
#pragma unroll
    for (int sm = 0; sm < 2; sm++) {
        int m = m0 + wm + sm * 16 + g;
        int b = m >> 11, t = m & 2047;
#pragma unroll
        for (int sn = 0; sn < 8; sn++) {
            int nn = (n0 & 1023) + wn + sn * 8 + tq * 2;
            int h = nn >> 6, d = nn & 63;
            __half* p0 = outb + (((size_t)(b * 16 + h) * T + t) * HD + d);
            *(unsigned*)p0 = f2h2(acc[sm][sn][0] * scl, acc[sm][sn][1] * scl);
            *(unsigned*)(p0 + 8 * HD) = f2h2(acc[sm][sn][2] * scl, acc[sm][sn][3] * scl);
        }
    }
}

// ---------------------------------------------------------------------------
// Kernel 2: causal flash attention, fp16 mma, exp2 softmax with:
//   - p computed via ex2.approx.f16x2 directly into PV A-fragment registers
//   - row sums (l) via MMA against an all-ones B fragment (no shfl adds)
// 8 warps, 128 q-rows/block; warp owns 16 rows; double-buffered K/V.
// ---------------------------------------------------------------------------
#define AQ 128
#define AK 64

__global__ void __launch_bounds__(256) attn_kernel() {
    __shared__ __half Ks[2][AK][72];
    __shared__ __half Vs[2][AK][72];

    int bh = blockIdx.y;
    int qt = gridDim.x - 1 - blockIdx.x;   // heavy q-tiles first
    int t0 = qt * AQ;
    int tid = threadIdx.x;
    int lane = tid & 31, w = tid >> 5;
    int g = lane >> 2, tq = lane & 3;
    int wq = w * 16;
    int mi = lane >> 3, mrow = lane & 7;
    int mb = mi & 1, sb = mi >> 1;

    const __half* qb = g_qh + ((size_t)bh * T + t0) * HD;
    const __half* kb = g_kh + (size_t)bh * T * HD;
    const __half* vb = g_vh + (size_t)bh * T * HD;

    unsigned qf[4][4];
#pragma unroll
    for (int ks = 0; ks < 4; ks++) {
        qf[ks][0] = *(const unsigned*)&qb[(size_t)(wq + g) * HD + ks * 16 + 2 * tq];
        qf[ks][1] = *(const unsigned*)&qb[(size_t)(wq + g + 8) * HD + ks * 16 + 2 * tq];
        qf[ks][2] = *(const unsigned*)&qb[(size_t)(wq + g) * HD + ks * 16 + 2 * tq + 8];
        qf[ks][3] = *(const unsigned*)&qb[(size_t)(wq + g + 8) * HD + ks * 16 + 2 * tq + 8];
    }

    float m0 = -1e30f, m1 = -1e30f, l0 = 0.f, l1 = 0.f;
    float accO[8][4] = {};

    int ntiles = 2 * qt + 2;   // keys 0 .. t0+127

#pragma unroll
    for (int it = 0; it < 2; it++) {
        int f = tid + it * 256;
        int r = f >> 3, c8 = f & 7;
        cp16(&Ks[0][r][c8 * 8], &kb[(size_t)r * HD + c8 * 8]);
        cp16(&Vs[0][r][c8 * 8], &vb[(size_t)r * HD + c8 * 8]);
    }
    CP_COMMIT;

    for (int itile = 0; itile < ntiles; itile++) {
        int buf = itile & 1;
        int s0 = itile * AK;
        __syncthreads();
        if (itile + 1 < ntiles) {
            int sn0 = (itile + 1) * AK;
#pragma unroll
            for (int it = 0; it < 2; it++) {
                int f = tid + it * 256;
                int r = f >> 3, c8 = f & 7;
                cp16(&Ks[buf ^ 1][r][c8 * 8], &kb[(size_t)(sn0 + r) * HD + c8 * 8]);
                cp16(&Vs[buf ^ 1][r][c8 * 8], &vb[(size_t)(sn0 + r) * HD + c8 * 8]);
            }
            CP_COMMIT;
            CP_WAIT(1);
        } else {
            CP_WAIT(0);
        }
        __syncthreads();

        if (s0 > t0 + wq + 15) continue;

        // S = Q * K^T  (log2-domain scores)
        float sc[8][4] = {};
#pragma unroll
        for (int ks = 0; ks < 4; ks++) {
#pragma unroll
            for (int snp = 0; snp < 4; snp++) {
                unsigned b0, b1, b2, b3;
                ldsm4(b0, b1, b2, b3,
                      &Ks[buf][snp * 16 + sb * 8 + mrow][ks * 16 + mb * 8]);
                unsigned bb0[2] = {b0, b1}, bb1[2] = {b2, b3};
                mma_f16(sc[snp * 2], qf[ks], bb0);
                mma_f16(sc[snp * 2 + 1], qf[ks], bb1);
            }
        }

        // causal mask on crossing tiles
        if (s0 + 63 > t0 + wq) {
            int r0 = t0 + wq + g, r1 = r0 + 8;
#pragma unroll
            for (int sn = 0; sn < 8; sn++) {
                int c0 = s0 + sn * 8 + tq * 2, c1 = c0 + 1;
                if (c0 > r0) sc[sn][0] = -1e30f;
                if (c1 > r0) sc[sn][1] = -1e30f;
                if (c0 > r1) sc[sn][2] = -1e30f;
                if (c1 > r1) sc[sn][3] = -1e30f;
            }
        }

        // running max (fp32) with quad shfl reduce
        float rx0 = -1e30f, rx1 = -1e30f;
#pragma unroll
        for (int sn = 0; sn < 8; sn++) {
            rx0 = fmaxf(rx0, fmaxf(sc[sn][0], sc[sn][1]));
            rx1 = fmaxf(rx1, fmaxf(sc[sn][2], sc[sn][3]));
        }
        rx0 = fmaxf(rx0, __shfl_xor_sync(0xffffffffu, rx0, 1));
        rx0 = fmaxf(rx0, __shfl_xor_sync(0xffffffffu, rx0, 2));
        rx1 = fmaxf(rx1, __shfl_xor_sync(0xffffffffu, rx1, 1));
        rx1 = fmaxf(rx1, __shfl_xor_sync(0xffffffffu, rx1, 2));
        float mn0 = fmaxf(m0, rx0), mn1 = fmaxf(m1, rx1);
        float corr0 = ex2f(m0 - mn0), corr1 = ex2f(m1 - mn1);
        m0 = mn0; m1 = mn1;

        // p = 2^(s-m), computed in fp16x2 directly into PV A-fragment regs
        unsigned p0h[8], p1h[8];
#pragma unroll
        for (int sn = 0; sn < 8; sn++) {
            p0h[sn] = h2ex2(f2h2(sc[sn][0] - mn0, sc[sn][1] - mn0));
            p1h[sn] = h2ex2(f2h2(sc[sn][2] - mn1, sc[sn][3] - mn1));
        }

        // row sums via MMA against all-ones B: rs replicated across j columns
        const unsigned ONE2 = 0x3C003C00u;
        unsigned onesb[2] = {ONE2, ONE2};
        float rsacc[4] = {0.f, 0.f, 0.f, 0.f};
#pragma unroll
        for (int kc = 0; kc < 4; kc++) {
            unsigned af[4] = {p0h[2 * kc], p1h[2 * kc], p0h[2 * kc + 1], p1h[2 * kc + 1]};
            mma_f16(rsacc, af, onesb);
        }
        l0 = l0 * corr0 + rsacc[0];
        l1 = l1 * corr1 + rsacc[2];
#pragma unroll
        for (int sn = 0; sn < 8; sn++) {
            accO[sn][0] *= corr0; accO[sn][1] *= corr0;
            accO[sn][2] *= corr1; accO[sn][3] *= corr1;
        }

        // O += P * V
#pragma unroll
        for (int kc = 0; kc < 4; kc++) {
            unsigned af[4] = {p0h[2 * kc], p1h[2 * kc], p0h[2 * kc + 1], p1h[2 * kc + 1]};
#pragma unroll
            for (int snp = 0; snp < 4; snp++) {
                unsigned b0, b1, b2, b3;
                ldsm4t(b0, b1, b2, b3,
                       &Vs[buf][kc * 16 + mb * 8 + mrow][(snp * 2 + sb) * 8]);
                unsigned bb0[2] = {b0, b1}, bb1[2] = {b2, b3};
                mma_f16(accO[snp * 2], af, bb0);
                mma_f16(accO[snp * 2 + 1], af, bb1);
            }
        }
    }

    // epilogue: normalize, write fp16 to [B,T,H*HD]
    float inv0 = 1.f / l0, inv1 = 1.f / l1;
    int b = bh >> 4, h = bh & 15;
    __half* o0 = g_oh + ((size_t)b * T + t0 + wq + g) * C + h * HD;
    __half* o1 = o0 + (size_t)8 * C;
#pragma unroll
    for (int sn = 0; sn < 8; sn++) {
        int cc = sn * 8 + tq * 2;
        *(unsigned*)&o0[cc] = f2h2(accO[sn][0] * inv0, accO[sn][1] * inv0);
        *(unsigned*)&o1[cc] = f2h2(accO[sn][2] * inv1, accO[sn][3] * inv1);
    }
}

// ---------------------------------------------------------------------------
// Kernel 3: output projection [4096 x 1024 x 1024], K-chunk 64, 128x128 tiles.
// ---------------------------------------------------------------------------
__global__ void __launch_bounds__(256) proj_kernel(
    const float* __restrict__ bo, float* __restrict__ Y)
{
    __shared__ __half As[2][128][72];
    __shared__ __half Bs[2][64][136];

    int n0 = blockIdx.x * 128;
    int m0 = blockIdx.y * 128;

    const __half* A = g_oh + (size_t)m0 * C;
    const __half* Bp = g_woth + n0;

    int tid = threadIdx.x;
    int lane = tid & 31, w = tid >> 5;
    int g = lane >> 2, tq = lane & 3;
    int wm = (w & 3) * 32, wn = (w >> 2) * 64;
    int mi = lane >> 3, mrow = lane & 7;
    int mb = mi & 1, kb = mi >> 1;

    float acc[2][8][4] = {};

#pragma unroll
    for (int it = 0; it < 4; it++) {
        int f = tid + it * 256;
        int r = f >> 3, c8 = f & 7;
        cp16(&As[0][r][c8 * 8], &A[(size_t)r * C + c8 * 8]);
    }
#pragma unroll
    for (int it = 0; it < 4; it++) {
        int f = tid + it * 256;
        int r = f >> 4, c8 = f & 15;
        cp16(&Bs[0][r][c8 * 8], &Bp[(size_t)r * C + c8 * 8]);
    }
    CP_COMMIT;

    const int NC = C / 64;
    for (int c = 0; c < NC; c++) {
        int st = c & 1;
        if (c + 1 < NC) {
            int k0 = (c + 1) * 64, s2 = st ^ 1;
#pragma unroll
            for (int it = 0; it < 4; it++) {
                int f = tid + it * 256;
                int r = f >> 3, c8 = f & 7;
                cp16(&As[s2][r][c8 * 8], &A[(size_t)r * C + k0 + c8 * 8]);
            }
#pragma unroll
            for (int it = 0; it < 4; it++) {
                int f = tid + it * 256;
                int r = f >> 4, c8 = f & 15;
                cp16(&Bs[s2][r][c8 * 8], &Bp[(size_t)(k0 + r) * C + c8 * 8]);
            }
            CP_COMMIT;
            CP_WAIT(1);
        } else {
            CP_WAIT(0);
        }
        __syncthreads();

#pragma unroll
        for (int ks = 0; ks < 4; ks++) {
            unsigned af[2][4], bf[8][2];
#pragma unroll
            for (int sm = 0; sm < 2; sm++)
                ldsm4(af[sm][0], af[sm][1], af[sm][2], af[sm][3],
                      &As[st][wm + sm * 16 + mb * 8 + mrow][ks * 16 + kb * 8]);
#pragma unroll
            for (int snp = 0; snp < 4; snp++)
                ldsm4t(bf[snp * 2][0], bf[snp * 2][1], bf[snp * 2 + 1][0], bf[snp * 2 + 1][1],
                       &Bs[st][ks * 16 + mb * 8 + mrow][wn + snp * 16 + kb * 8]);
#pragma unroll
            for (int sm = 0; sm < 2; sm++)
#pragma unroll
                for (int sn = 0; sn < 8; sn++)
                    mma_f16(acc[sm][sn], af[sm], bf[sn]);
        }
        __syncthreads();
    }

#pragma unroll
    for (int sm = 0; sm < 2; sm++) {
        int r0 = m0 + wm + sm * 16 + g;
#pragma unroll
        for (int sn = 0; sn < 8; sn++) {
            int cc = n0 + wn + sn * 8 + tq * 2;
            float b0 = bo[cc], b1 = bo[cc + 1];
            *(float2*)&Y[(size_t)r0 * C + cc] =
                make_float2(acc[sm][sn][0] + b0, acc[sm][sn][1] + b1);
            *(float2*)&Y[(size_t)(r0 + 8) * C + cc] =
                make_float2(acc[sm][sn][2] + b0, acc[sm][sn][3] + b1);
        }
    }
}

// ---------------------------------------------------------------------------
extern "C" void kernel_launch(void* const* d_in, const int* in_sizes, int n_in,
                              void* d_out, int out_size)
{
    const float* x  = (const float*)d_in[0];
    const float* Wq = (const float*)d_in[1];
    const float* Wk = (const float*)d_in[2];
    const float* Wv = (const float*)d_in[3];
    const float* Wo = (const float*)d_in[4];
    const float* bo = (const float*)d_in[5];
    float* y = (float*)d_out;

    prep_kernel<<<dim3((B * T * C / 4 + 255) / 256, 4), 256>>>(x, Wq, Wk, Wv);
    transpose_wo_kernel<<<dim3(C / 32, C / 32), dim3(32, 8)>>>(Wo);
    qkv_kernel<<<dim3(N3 / 128, (B * T) / 128), 256>>>();
    attn_kernel<<<dim3(T / AQ, BH), 256>>>();
    proj_kernel<<<dim3(C / 128, (B * T) / 128), 256>>>(bo, y);
}

// round 12
// speedup vs baseline: 13.2024x; 1.0646x over previous
#include <cuda_runtime.h>
#include <cuda_fp16.h>
#include <cstdint>

#define B 2
#define T 2048
#define C 1024
#define H 16
#define HD 64
#define BH (B * H)
#define N3 (3 * C)   // fused QKV output width = 3072

// ---- scratch (device globals; no runtime allocation allowed) ----
__device__ __half g_xh[(size_t)B * T * C];        // x in fp16
__device__ __half g_wi[(size_t)C * N3];           // interleaved W: [c][sel*1024+h*64+d]
__device__ __half g_woth[(size_t)C * C];          // Wo^T in fp16
__device__ __half g_qh[(size_t)BH * T * HD];      // Q pre-scaled by 0.125*log2e
__device__ __half g_kh[(size_t)BH * T * HD];
__device__ __half g_vh[(size_t)BH * T * HD];
__device__ __half g_oh[(size_t)B * T * C];        // attention out [B,T,H*HD]

// ---------------------------------------------------------------------------
// helpers
// ---------------------------------------------------------------------------
__device__ __forceinline__ unsigned f2h2(float lo, float hi) {
    unsigned r;
    asm("cvt.rn.f16x2.f32 %0, %1, %2;" : "=r"(r) : "f"(hi), "f"(lo));
    return r;
}
__device__ __forceinline__ float ex2f(float x) {
    float r;
    asm("ex2.approx.f32 %0, %1;" : "=f"(r) : "f"(x));
    return r;
}
__device__ __forceinline__ unsigned h2ex2(unsigned x) {
    unsigned r;
    asm("ex2.approx.f16x2 %0, %1;" : "=r"(r) : "r"(x));
    return r;
}
__device__ __forceinline__ void mma_f16(float c[4], const unsigned a[4], const unsigned b[2]) {
    asm("mma.sync.aligned.m16n8k16.row.col.f32.f16.f16.f32 "
        "{%0,%1,%2,%3},{%4,%5,%6,%7},{%8,%9},{%0,%1,%2,%3};"
        : "+f"(c[0]), "+f"(c[1]), "+f"(c[2]), "+f"(c[3])
        : "r"(a[0]), "r"(a[1]), "r"(a[2]), "r"(a[3]), "r"(b[0]), "r"(b[1]));
}
__device__ __forceinline__ void ldsm4(unsigned& d0, unsigned& d1, unsigned& d2, unsigned& d3,
                                      const void* p) {
    unsigned a = (unsigned)__cvta_generic_to_shared(p);
    asm volatile("ldmatrix.sync.aligned.m8n8.x4.shared.b16 {%0,%1,%2,%3}, [%4];"
                 : "=r"(d0), "=r"(d1), "=r"(d2), "=r"(d3) : "r"(a));
}
__device__ __forceinline__ void ldsm4t(unsigned& d0, unsigned& d1, unsigned& d2, unsigned& d3,
                                       const void* p) {
    unsigned a = (unsigned)__cvta_generic_to_shared(p);
    asm volatile("ldmatrix.sync.aligned.m8n8.x4.trans.shared.b16 {%0,%1,%2,%3}, [%4];"
                 : "=r"(d0), "=r"(d1), "=r"(d2), "=r"(d3) : "r"(a));
}
__device__ __forceinline__ void cp16(void* smem_dst, const void* gmem_src) {
    unsigned saddr = (unsigned)__cvta_generic_to_shared(smem_dst);
    asm volatile("cp.async.cg.shared.global [%0], [%1], 16;" :: "r"(saddr), "l"(gmem_src));
}
#define CP_COMMIT asm volatile("cp.async.commit_group;")
#define CP_WAIT(n) asm volatile("cp.async.wait_group %0;" :: "n"(n))

// ---------------------------------------------------------------------------
// Kernel P0: convert x to fp16; interleave Wq/Wk/Wv into g_wi (fp16).
// ---------------------------------------------------------------------------
__global__ void prep_kernel(const float* __restrict__ x,
                            const float* __restrict__ Wq,
                            const float* __restrict__ Wk,
                            const float* __restrict__ Wv) {
    int seg = blockIdx.y;
    int i = (blockIdx.x * 256 + threadIdx.x) * 4;
    if (seg == 0) {
        if (i < B * T * C) {
            float4 v = *(const float4*)&x[i];
            *(__half2*)&g_xh[i]     = __floats2half2_rn(v.x, v.y);
            *(__half2*)&g_xh[i + 2] = __floats2half2_rn(v.z, v.w);
        }
    } else {
        const float* src = seg == 1 ? Wq : seg == 2 ? Wk : Wv;
        if (i < H * C * HD) {
            float4 v = *(const float4*)&src[i];
            int d = i & 63, c = (i >> 6) & 1023, h = i >> 16;
            __half* dst = g_wi + ((size_t)c * N3 + (seg - 1) * 1024 + h * 64 + d);
            *(__half2*)&dst[0] = __floats2half2_rn(v.x, v.y);
            *(__half2*)&dst[2] = __floats2half2_rn(v.z, v.w);
        }
    }
}

// ---------------------------------------------------------------------------
// Kernel P1: transpose Wo [C,C] -> g_woth (fp16).
// ---------------------------------------------------------------------------
__global__ void transpose_wo_kernel(const float* __restrict__ Wo) {
    __shared__ float tile[32][33];
    int x0 = blockIdx.x * 32;
    int y0 = blockIdx.y * 32;
    int tx = threadIdx.x, ty = threadIdx.y;
#pragma unroll
    for (int i = 0; i < 32; i += 8)
        tile[ty + i][tx] = Wo[(size_t)(y0 + ty + i) * C + x0 + tx];
    __syncthreads();
#pragma unroll
    for (int i = 0; i < 32; i += 8)
        g_woth[(size_t)(x0 + ty + i) * C + y0 + tx] = __float2half(tile[tx][ty + i]);
}

// ---------------------------------------------------------------------------
// Kernel 1: fused QKV GEMM [4096 x 3072 x 1024], fp16 mma + ldmatrix +
// single-barrier double-buffered cp.async, K-chunk 64. 8 warps; tile 128x128.
// ---------------------------------------------------------------------------
__global__ void __launch_bounds__(256) qkv_kernel() {
    __shared__ __half As[2][128][72];    // rows 128B data, pitch 144B
    __shared__ __half Bs[2][64][136];    // rows 256B data, pitch 272B

    int n0 = blockIdx.x * 128;
    int m0 = blockIdx.y * 128;

    const __half* A = g_xh + (size_t)m0 * C;
    const __half* Bp = g_wi + n0;

    int tid = threadIdx.x;
    int lane = tid & 31, w = tid >> 5;
    int g = lane >> 2, tq = lane & 3;
    int wm = (w & 3) * 32, wn = (w >> 2) * 64;
    int mi = lane >> 3, mrow = lane & 7;
    int mb = mi & 1, kb = mi >> 1;

    float acc[2][8][4] = {};

    // prefetch chunk 0 -> stage 0
#pragma unroll
    for (int it = 0; it < 4; it++) {
        int f = tid + it * 256;
        int r = f >> 3, c8 = f & 7;
        cp16(&As[0][r][c8 * 8], &A[(size_t)r * C + c8 * 8]);
    }
#pragma unroll
    for (int it = 0; it < 4; it++) {
        int f = tid + it * 256;
        int r = f >> 4, c8 = f & 15;
        cp16(&Bs[0][r][c8 * 8], &Bp[(size_t)r * N3 + c8 * 8]);
    }
    CP_COMMIT;

    const int NC = C / 64;
    for (int c = 0; c < NC; c++) {
        int st = c & 1;
        CP_WAIT(0);          // chunk c resident
        __syncthreads();     // visible to all; all warps done with buf st^1
        if (c + 1 < NC) {    // prefetch chunk c+1 into the other buffer
            int k0 = (c + 1) * 64, s2 = st ^ 1;
#pragma unroll
            for (int it = 0; it < 4; it++) {
                int f = tid + it * 256;
                int r = f >> 3, c8 = f & 7;
                cp16(&As[s2][r][c8 * 8], &A[(size_t)r * C + k0 + c8 * 8]);
            }
#pragma unroll
            for (int it = 0; it < 4; it++) {
                int f = tid + it * 256;
                int r = f >> 4, c8 = f & 15;
                cp16(&Bs[s2][r][c8 * 8], &Bp[(size_t)(k0 + r) * N3 + c8 * 8]);
            }
            CP_COMMIT;
        }

#pragma unroll
        for (int ks = 0; ks < 4; ks++) {
            unsigned af[2][4], bf[8][2];
#pragma unroll
            for (int sm = 0; sm < 2; sm++)
                ldsm4(af[sm][0], af[sm][1], af[sm][2], af[sm][3],
                      &As[st][wm + sm * 16 + mb * 8 + mrow][ks * 16 + kb * 8]);
#pragma unroll
            for (int snp = 0; snp < 4; snp++)
                ldsm4t(bf[snp * 2][0], bf[snp * 2][1], bf[snp * 2 + 1][0], bf[snp * 2 + 1][1],
                       &Bs[st][ks * 16 + mb * 8 + mrow][wn + snp * 16 + kb * 8]);
#pragma unroll
            for (int sm = 0; sm < 2; sm++)
#pragma unroll
                for (int sn = 0; sn < 8; sn++)
                    mma_f16(acc[sm][sn], af[sm], bf[sn]);
        }
    }

    // epilogue: route columns to q/k/v tensors ([bh][t][d] layout)
    int sel = n0 >> 10;
    __half* outb = sel == 0 ? g_qh : sel == 1 ? g_kh : g_vh;
    float scl = (sel == 0) ? 0.18033688f : 1.f;   // 0.125 * log2(e)
#pragma unroll
    for (int sm = 0; sm < 2; sm++) {
        int m = m0 + wm + sm * 16 + g;
        int b = m >> 11, t = m & 2047;
#pragma unroll
        for (int sn = 0; sn < 8; sn++) {
            int nn = (n0 & 1023) + wn + sn * 8 + tq * 2;
            int h = nn >> 6, d = nn & 63;
            __half* p0 = outb + (((size_t)(b * 16 + h) * T + t) * HD + d);
            *(unsigned*)p0 = f2h2(acc[sm][sn][0] * scl, acc[sm][sn][1] * scl);
            *(unsigned*)(p0 + 8 * HD) = f2h2(acc[sm][sn][2] * scl, acc[sm][sn][3] * scl);
        }
    }
}

// ---------------------------------------------------------------------------
// Kernel 2: causal flash attention, fp16 mma, exp2 softmax.
// 128 threads = 4 warps; block = 64 q-rows (warp owns 16). 4 CTAs/SM ->
// 4 independent scheduling domains; single barrier per KV tile.
// ---------------------------------------------------------------------------
#define AQ 64
#define AK 64

__global__ void __launch_bounds__(128, 4) attn_kernel() {
    __shared__ __half Ks[2][AK][72];
    __shared__ __half Vs[2][AK][72];

    int bh = blockIdx.y;
    int qt = gridDim.x - 1 - blockIdx.x;   // heavy q-tiles first
    int t0 = qt * AQ;
    int tid = threadIdx.x;
    int lane = tid & 31, w = tid >> 5;
    int g = lane >> 2, tq = lane & 3;
    int wq = w * 16;
    int mi = lane >> 3, mrow = lane & 7;
    int mb = mi & 1, sb = mi >> 1;

    const __half* qb = g_qh + ((size_t)bh * T + t0) * HD;
    const __half* kb = g_kh + (size_t)bh * T * HD;
    const __half* vb = g_vh + (size_t)bh * T * HD;

    unsigned qf[4][4];
#pragma unroll
    for (int ks = 0; ks < 4; ks++) {
        qf[ks][0] = *(const unsigned*)&qb[(size_t)(wq + g) * HD + ks * 16 + 2 * tq];
        qf[ks][1] = *(const unsigned*)&qb[(size_t)(wq + g + 8) * HD + ks * 16 + 2 * tq];
        qf[ks][2] = *(const unsigned*)&qb[(size_t)(wq + g) * HD + ks * 16 + 2 * tq + 8];
        qf[ks][3] = *(const unsigned*)&qb[(size_t)(wq + g + 8) * HD + ks * 16 + 2 * tq + 8];
    }

    float m0 = -1e30f, m1 = -1e30f, l0 = 0.f, l1 = 0.f;
    float accO[8][4] = {};

    int ntiles = qt + 1;   // keys 0 .. t0+63

    // prefetch tile 0 -> buf 0 (4 float4 per thread per tensor)
#pragma unroll
    for (int it = 0; it < 4; it++) {
        int f = tid + it * 128;
        int r = f >> 3, c8 = f & 7;
        cp16(&Ks[0][r][c8 * 8], &kb[(size_t)r * HD + c8 * 8]);
        cp16(&Vs[0][r][c8 * 8], &vb[(size_t)r * HD + c8 * 8]);
    }
    CP_COMMIT;

    for (int itile = 0; itile < ntiles; itile++) {
        int buf = itile & 1;
        int s0 = itile * AK;
        CP_WAIT(0);          // tile itile resident
        __syncthreads();     // visible; all warps done reading buf^1
        if (itile + 1 < ntiles) {
            int sn0 = (itile + 1) * AK;
#pragma unroll
            for (int it = 0; it < 4; it++) {
                int f = tid + it * 128;
                int r = f >> 3, c8 = f & 7;
                cp16(&Ks[buf ^ 1][r][c8 * 8], &kb[(size_t)(sn0 + r) * HD + c8 * 8]);
                cp16(&Vs[buf ^ 1][r][c8 * 8], &vb[(size_t)(sn0 + r) * HD + c8 * 8]);
            }
            CP_COMMIT;
        }

        // S = Q * K^T  (log2-domain scores)
        float sc[8][4] = {};
#pragma unroll
        for (int ks = 0; ks < 4; ks++) {
#pragma unroll
            for (int snp = 0; snp < 4; snp++) {
                unsigned b0, b1, b2, b3;
                ldsm4(b0, b1, b2, b3,
                      &Ks[buf][snp * 16 + sb * 8 + mrow][ks * 16 + mb * 8]);
                unsigned bb0[2] = {b0, b1}, bb1[2] = {b2, b3};
                mma_f16(sc[snp * 2], qf[ks], bb0);
                mma_f16(sc[snp * 2 + 1], qf[ks], bb1);
            }
        }

        // causal mask on the diagonal tile
        if (itile == ntiles - 1) {
            int r0 = t0 + wq + g, r1 = r0 + 8;
#pragma unroll
            for (int sn = 0; sn < 8; sn++) {
                int c0 = s0 + sn * 8 + tq * 2, c1 = c0 + 1;
                if (c0 > r0) sc[sn][0] = -1e30f;
                if (c1 > r0) sc[sn][1] = -1e30f;
                if (c0 > r1) sc[sn][2] = -1e30f;
                if (c1 > r1) sc[sn][3] = -1e30f;
            }
        }

        // running max (fp32) with quad shfl reduce
        float rx0 = -1e30f, rx1 = -1e30f;
#pragma unroll
        for (int sn = 0; sn < 8; sn++) {
            rx0 = fmaxf(rx0, fmaxf(sc[sn][0], sc[sn][1]));
            rx1 = fmaxf(rx1, fmaxf(sc[sn][2], sc[sn][3]));
        }
        rx0 = fmaxf(rx0, __shfl_xor_sync(0xffffffffu, rx0, 1));
        rx0 = fmaxf(rx0, __shfl_xor_sync(0xffffffffu, rx0, 2));
        rx1 = fmaxf(rx1, __shfl_xor_sync(0xffffffffu, rx1, 1));
        rx1 = fmaxf(rx1, __shfl_xor_sync(0xffffffffu, rx1, 2));
        float mn0 = fmaxf(m0, rx0), mn1 = fmaxf(m1, rx1);
        float corr0 = ex2f(m0 - mn0), corr1 = ex2f(m1 - mn1);
        m0 = mn0; m1 = mn1;

        // p = 2^(s-m) in fp16x2, directly in PV A-fragment registers
        unsigned p0h[8], p1h[8];
#pragma unroll
        for (int sn = 0; sn < 8; sn++) {
            p0h[sn] = h2ex2(f2h2(sc[sn][0] - mn0, sc[sn][1] - mn0));
            p1h[sn] = h2ex2(f2h2(sc[sn][2] - mn1, sc[sn][3] - mn1));
        }

        // row sums via MMA against all-ones B fragment
        const unsigned ONE2 = 0x3C003C00u;
        unsigned onesb[2] = {ONE2, ONE2};
        float rsacc[4] = {0.f, 0.f, 0.f, 0.f};
#pragma unroll
        for (int kc = 0; kc < 4; kc++) {
            unsigned af[4] = {p0h[2 * kc], p1h[2 * kc], p0h[2 * kc + 1], p1h[2 * kc + 1]};
            mma_f16(rsacc, af, onesb);
        }
        l0 = l0 * corr0 + rsacc[0];
        l1 = l1 * corr1 + rsacc[2];
#pragma unroll
        for (int sn = 0; sn < 8; sn++) {
            accO[sn][0] *= corr0; accO[sn][1] *= corr0;
            accO[sn][2] *= corr1; accO[sn][3] *= corr1;
        }

        // O += P * V
#pragma unroll
        for (int kc = 0; kc < 4; kc++) {
            unsigned af[4] = {p0h[2 * kc], p1h[2 * kc], p0h[2 * kc + 1], p1h[2 * kc + 1]};
#pragma unroll
            for (int snp = 0; snp < 4; snp++) {
                unsigned b0, b1, b2, b3;
                ldsm4t(b0, b1, b2, b3,
                       &Vs[buf][kc * 16 + mb * 8 + mrow][(snp * 2 + sb) * 8]);
                unsigned bb0[2] = {b0, b1}, bb1[2] = {b2, b3};
                mma_f16(accO[snp * 2], af, bb0);
                mma_f16(accO[snp * 2 + 1], af, bb1);
            }
        }
    }

    // epilogue: normalize, write fp16 to [B,T,H*HD]
    float inv0 = 1.f / l0, inv1 = 1.f / l1;
    int b = bh >> 4, h = bh & 15;
    __half* o0 = g_oh + ((size_t)b * T + t0 + wq + g) * C + h * HD;
    __half* o1 = o0 + (size_t)8 * C;
#pragma unroll
    for (int sn = 0; sn < 8; sn++) {
        int cc = sn * 8 + tq * 2;
        *(unsigned*)&o0[cc] = f2h2(accO[sn][0] * inv0, accO[sn][1] * inv0);
        *(unsigned*)&o1[cc] = f2h2(accO[sn][2] * inv1, accO[sn][3] * inv1);
    }
}

// ---------------------------------------------------------------------------
// Kernel 3: output projection [4096 x 1024 x 1024], K-chunk 64, 128x128 tiles,
// single-barrier double-buffer.
// ---------------------------------------------------------------------------
__global__ void __launch_bounds__(256) proj_kernel(
    const float* __restrict__ bo, float* __restrict__ Y)
{
    __shared__ __half As[2][128][72];
    __shared__ __half Bs[2][64][136];

    int n0 = blockIdx.x * 128;
    int m0 = blockIdx.y * 128;

    const __half* A = g_oh + (size_t)m0 * C;
    const __half* Bp = g_woth + n0;

    int tid = threadIdx.x;
    int lane = tid & 31, w = tid >> 5;
    int g = lane >> 2, tq = lane & 3;
    int wm = (w & 3) * 32, wn = (w >> 2) * 64;
    int mi = lane >> 3, mrow = lane & 7;
    int mb = mi & 1, kb = mi >> 1;

    float acc[2][8][4] = {};

#pragma unroll
    for (int it = 0; it < 4; it++) {
        int f = tid + it * 256;
        int r = f >> 3, c8 = f & 7;
        cp16(&As[0][r][c8 * 8], &A[(size_t)r * C + c8 * 8]);
    }
#pragma unroll
    for (int it = 0; it < 4; it++) {
        int f = tid + it * 256;
        int r = f >> 4, c8 = f & 15;
        cp16(&Bs[0][r][c8 * 8], &Bp[(size_t)r * C + c8 * 8]);
    }
    CP_COMMIT;

    const int NC = C / 64;
    for (int c = 0; c < NC; c++) {
        int st = c & 1;
        CP_WAIT(0);
        __syncthreads();
        if (c + 1 < NC) {
            int k0 = (c + 1) * 64, s2 = st ^ 1;
#pragma unroll
            for (int it = 0; it < 4; it++) {
                int f = tid + it * 256;
                int r = f >> 3, c8 = f & 7;
                cp16(&As[s2][r][c8 * 8], &A[(size_t)r * C + k0 + c8 * 8]);
            }
#pragma unroll
            for (int it = 0; it < 4; it++) {
                int f = tid + it * 256;
                int r = f >> 4, c8 = f & 15;
                cp16(&Bs[s2][r][c8 * 8], &Bp[(size_t)(k0 + r) * C + c8 * 8]);
            }
            CP_COMMIT;
        }

#pragma unroll
        for (int ks = 0; ks < 4; ks++) {
            unsigned af[2][4], bf[8][2];
#pragma unroll
            for (int sm = 0; sm < 2; sm++)
                ldsm4(af[sm][0], af[sm][1], af[sm][2], af[sm][3],
                      &As[st][wm + sm * 16 + mb * 8 + mrow][ks * 16 + kb * 8]);
#pragma unroll
            for (int snp = 0; snp < 4; snp++)
                ldsm4t(bf[snp * 2][0], bf[snp * 2][1], bf[snp * 2 + 1][0], bf[snp * 2 + 1][1],
                       &Bs[st][ks * 16 + mb * 8 + mrow][wn + snp * 16 + kb * 8]);
#pragma unroll
            for (int sm = 0; sm < 2; sm++)
#pragma unroll
                for (int sn = 0; sn < 8; sn++)
                    mma_f16(acc[sm][sn], af[sm], bf[sn]);
        }
    }

#pragma unroll
    for (int sm = 0; sm < 2; sm++) {
        int r0 = m0 + wm + sm * 16 + g;
#pragma unroll
        for (int sn = 0; sn < 8; sn++) {
            int cc = n0 + wn + sn * 8 + tq * 2;
            float b0 = bo[cc], b1 = bo[cc + 1];
            *(float2*)&Y[(size_t)r0 * C + cc] =
                make_float2(acc[sm][sn][0] + b0, acc[sm][sn][1] + b1);
            *(float2*)&Y[(size_t)(r0 + 8) * C + cc] =
                make_float2(acc[sm][sn][2] + b0, acc[sm][sn][3] + b1);
        }
    }
}

// ---------------------------------------------------------------------------
extern "C" void kernel_launch(void* const* d_in, const int* in_sizes, int n_in,
                              void* d_out, int out_size)
{
    const float* x  = (const float*)d_in[0];
    const float* Wq = (const float*)d_in[1];
    const float* Wk = (const float*)d_in[2];
    const float* Wv = (const float*)d_in[3];
    const float* Wo = (const float*)d_in[4];
    const float* bo = (const float*)d_in[5];
    float* y = (float*)d_out;

    prep_kernel<<<dim3((B * T * C / 4 + 255) / 256, 4), 256>>>(x, Wq, Wk, Wv);
    transpose_wo_kernel<<<dim3(C / 32, C / 32), dim3(32, 8)>>>(Wo);
    qkv_kernel<<<dim3(N3 / 128, (B * T) / 128), 256>>>();
    attn_kernel<<<dim3(T / AQ, BH), 128>>>();
    proj_kernel<<<dim3(C / 128, (B * T) / 128), 256>>>(bo, y);
}

// round 13
// speedup vs baseline: 13.3004x; 1.0074x over previous
#include <cuda_runtime.h>
#include <cuda_fp16.h>
#include <cstdint>

#define B 2
#define T 2048
#define C 1024
#define H 16
#define HD 64
#define BH (B * H)
#define N3 (3 * C)   // fused QKV output width = 3072

// ---- scratch (device globals; no runtime allocation allowed) ----
__device__ __half g_xh[(size_t)B * T * C];        // x in fp16
__device__ __half g_wi[(size_t)C * N3];           // interleaved W: [c][sel*1024+h*64+d]
__device__ __half g_woth[(size_t)C * C];          // Wo^T in fp16
__device__ __half g_qh[(size_t)BH * T * HD];      // Q pre-scaled by 0.125*log2e
__device__ __half g_kh[(size_t)BH * T * HD];
__device__ __half g_vh[(size_t)BH * T * HD];
__device__ __half g_oh[(size_t)B * T * C];        // attention out [B,T,H*HD]

// ---------------------------------------------------------------------------
// helpers
// ---------------------------------------------------------------------------
__device__ __forceinline__ unsigned f2h2(float lo, float hi) {
    unsigned r;
    asm("cvt.rn.f16x2.f32 %0, %1, %2;" : "=r"(r) : "f"(hi), "f"(lo));
    return r;
}
__device__ __forceinline__ float ex2f(float x) {
    float r;
    asm("ex2.approx.f32 %0, %1;" : "=f"(r) : "f"(x));
    return r;
}
__device__ __forceinline__ unsigned h2ex2(unsigned x) {
    unsigned r;
    asm("ex2.approx.f16x2 %0, %1;" : "=r"(r) : "r"(x));
    return r;
}
__device__ __forceinline__ void mma_f16(float c[4], const unsigned a[4], const unsigned b[2]) {
    asm("mma.sync.aligned.m16n8k16.row.col.f32.f16.f16.f32 "
        "{%0,%1,%2,%3},{%4,%5,%6,%7},{%8,%9},{%0,%1,%2,%3};"
        : "+f"(c[0]), "+f"(c[1]), "+f"(c[2]), "+f"(c[3])
        : "r"(a[0]), "r"(a[1]), "r"(a[2]), "r"(a[3]), "r"(b[0]), "r"(b[1]));
}
__device__ __forceinline__ void ldsm4(unsigned& d0, unsigned& d1, unsigned& d2, unsigned& d3,
                                      const void* p) {
    unsigned a = (unsigned)__cvta_generic_to_shared(p);
    asm volatile("ldmatrix.sync.aligned.m8n8.x4.shared.b16 {%0,%1,%2,%3}, [%4];"
                 : "=r"(d0), "=r"(d1), "=r"(d2), "=r"(d3) : "r"(a));
}
__device__ __forceinline__ void ldsm4t(unsigned& d0, unsigned& d1, unsigned& d2, unsigned& d3,
                                       const void* p) {
    unsigned a = (unsigned)__cvta_generic_to_shared(p);
    asm volatile("ldmatrix.sync.aligned.m8n8.x4.trans.shared.b16 {%0,%1,%2,%3}, [%4];"
                 : "=r"(d0), "=r"(d1), "=r"(d2), "=r"(d3) : "r"(a));
}
__device__ __forceinline__ void cp16(void* smem_dst, const void* gmem_src) {
    unsigned saddr = (unsigned)__cvta_generic_to_shared(smem_dst);
    asm volatile("cp.async.cg.shared.global [%0], [%1], 16;" :: "r"(saddr), "l"(gmem_src));
}
#define CP_COMMIT asm volatile("cp.async.commit_group;")
#define CP_WAIT(n) asm volatile("cp.async.wait_group %0;" :: "n"(n))

// ---------------------------------------------------------------------------
// Kernel P0: convert x to fp16; interleave Wq/Wk/Wv; transpose Wo. One launch.
// ---------------------------------------------------------------------------
__global__ void prep_kernel(const float* __restrict__ x,
                            const float* __restrict__ Wq,
                            const float* __restrict__ Wk,
                            const float* __restrict__ Wv,
                            const float* __restrict__ Wo) {
    int seg = blockIdx.y;
    if (seg == 4) {
        // Wo transpose: 32x32 tiles, 256 threads as 32x8
        if (blockIdx.x >= 1024) return;
        __shared__ float tile[32][33];
        int xt = (blockIdx.x & 31) * 32, yt = (blockIdx.x >> 5) * 32;
        int tx = threadIdx.x & 31, ty = threadIdx.x >> 5;
#pragma unroll
        for (int i = 0; i < 32; i += 8)
            tile[ty + i][tx] = Wo[(size_t)(yt + ty + i) * C + xt + tx];
        __syncthreads();
#pragma unroll
        for (int i = 0; i < 32; i += 8)
            g_woth[(size_t)(xt + ty + i) * C + yt + tx] = __float2half(tile[tx][ty + i]);
        return;
    }
    int i = (blockIdx.x * 256 + threadIdx.x) * 4;
    if (seg == 0) {
        if (i < B * T * C) {
            float4 v = *(const float4*)&x[i];
            *(__half2*)&g_xh[i]     = __floats2half2_rn(v.x, v.y);
            *(__half2*)&g_xh[i + 2] = __floats2half2_rn(v.z, v.w);
        }
    } else {
        const float* src = seg == 1 ? Wq : seg == 2 ? Wk : Wv;
        if (i < H * C * HD) {
            float4 v = *(const float4*)&src[i];
            int d = i & 63, c = (i >> 6) & 1023, h = i >> 16;
            __half* dst = g_wi + ((size_t)c * N3 + (seg - 1) * 1024 + h * 64 + d);
            *(__half2*)&dst[0] = __floats2half2_rn(v.x, v.y);
            *(__half2*)&dst[2] = __floats2half2_rn(v.z, v.w);
        }
    }
}

// ---------------------------------------------------------------------------
// GEMM smem geometry (3-stage, dynamic): A[3][128][72], B[3][64][136]
// ---------------------------------------------------------------------------
#define GB_OFF (3 * 128 * 72)
#define GEMM_SMEM ((GB_OFF + 3 * 64 * 136) * 2)   // 107520 bytes

// ---------------------------------------------------------------------------
// Kernel 1: fused QKV GEMM [4096 x 3072 x 1024], fp16 mma + ldmatrix +
// 3-stage cp.async, K-chunk 64. 8 warps; tile 128x128.
// ---------------------------------------------------------------------------
__global__ void __launch_bounds__(256) qkv_kernel() {
    extern __shared__ __half smg[];
    __half (*As)[72]  = (__half(*)[72])smg;            // [3*128][72]
    __half (*Bs)[136] = (__half(*)[136])(smg + GB_OFF); // [3*64][136]

    int n0 = blockIdx.x * 128;
    int m0 = blockIdx.y * 128;

    const __half* A = g_xh + (size_t)m0 * C;
    const __half* Bp = g_wi + n0;

    int tid = threadIdx.x;
    int lane = tid & 31, w = tid >> 5;
    int g = lane >> 2, tq = lane & 3;
    int wm = (w & 3) * 32, wn = (w >> 2) * 64;
    int mi = lane >> 3, mrow = lane & 7;
    int mb = mi & 1, kb = mi >> 1;

    float acc[2][8][4] = {};

    const int NC = C / 64;
    // prologue: prefetch chunks 0 and 1
#pragma unroll
    for (int pc = 0; pc < 2; pc++) {
        int k0 = pc * 64;
#pragma unroll
        for (int it = 0; it < 4; it++) {
            int f = tid + it * 256;
            int r = f >> 3, c8 = f & 7;
            cp16(&As[pc * 128 + r][c8 * 8], &A[(size_t)r * C + k0 + c8 * 8]);
        }
#pragma unroll
        for (int it = 0; it < 4; it++) {
            int f = tid + it * 256;
            int r = f >> 4, c8 = f & 15;
            cp16(&Bs[pc * 64 + r][c8 * 8], &Bp[(size_t)(k0 + r) * N3 + c8 * 8]);
        }
        CP_COMMIT;
    }

    for (int c = 0; c < NC; c++) {
        int st = c % 3;
        if (c + 1 < NC) CP_WAIT(1); else CP_WAIT(0);   // chunk c resident
        __syncthreads();                                // visible; slot (c+2)%3 free
        if (c + 2 < NC) {
            int k0 = (c + 2) * 64, s2 = (c + 2) % 3;
#pragma unroll
            for (int it = 0; it < 4; it++) {
                int f = tid + it * 256;
                int r = f >> 3, c8 = f & 7;
                cp16(&As[s2 * 128 + r][c8 * 8], &A[(size_t)r * C + k0 + c8 * 8]);
            }
#pragma unroll
            for (int it = 0; it < 4; it++) {
                int f = tid + it * 256;
                int r = f >> 4, c8 = f & 15;
                cp16(&Bs[s2 * 64 + r][c8 * 8], &Bp[(size_t)(k0 + r) * N3 + c8 * 8]);
            }
            CP_COMMIT;
        }

#pragma unroll
        for (int ks = 0; ks < 4; ks++) {
            unsigned af[2][4], bf[8][2];
#pragma unroll
            for (int sm = 0; sm < 2; sm++)
                ldsm4(af[sm][0], af[sm][1], af[sm][2], af[sm][3],
                      &As[st * 128 + wm + sm * 16 + mb * 8 + mrow][ks * 16 + kb * 8]);
#pragma unroll
            for (int snp = 0; snp < 4; snp++)
                ldsm4t(bf[snp * 2][0], bf[snp * 2][1], bf[snp * 2 + 1][0], bf[snp * 2 + 1][1],
                       &Bs[st * 64 + ks * 16 + mb * 8 + mrow][wn + snp * 16 + kb * 8]);
#pragma unroll
            for (int sm = 0; sm < 2; sm++)
#pragma unroll
                for (int sn = 0; sn < 8; sn++)
                    mma_f16(acc[sm][sn], af[sm], bf[sn]);
        }
    }

    // epilogue: route columns to q/k/v tensors ([bh][t][d] layout)
    int sel = n0 >> 10;
    __half* outb = sel == 0 ? g_qh : sel == 1 ? g_kh : g_vh;
    float scl = (sel == 0) ? 0.18033688f : 1.f;   // 0.125 * log2(e)
#pragma unroll
    for (int sm = 0; sm < 2; sm++) {
        int m = m0 + wm + sm * 16 + g;
        int b = m >> 11, t = m & 2047;
#pragma unroll
        for (int sn = 0; sn < 8; sn++) {
            int nn = (n0 & 1023) + wn + sn * 8 + tq * 2;
            int h = nn >> 6, d = nn & 63;
            __half* p0 = outb + (((size_t)(b * 16 + h) * T + t) * HD + d);
            *(unsigned*)p0 = f2h2(acc[sm][sn][0] * scl, acc[sm][sn][1] * scl);
            *(unsigned*)(p0 + 8 * HD) = f2h2(acc[sm][sn][2] * scl, acc[sm][sn][3] * scl);
        }
    }
}

// ---------------------------------------------------------------------------
// Kernel 2: causal flash attention, fp16 mma, exp2 softmax.
// 128 threads = 4 warps; block = 64 q-rows; 3-buffer K/V ring (prefetch
// 2 tiles ahead); 4 CTAs/SM.
// ---------------------------------------------------------------------------
#define AQ 64
#define AK 64
#define AVS_OFF (3 * AK * 72)
#define ATTN_SMEM ((AVS_OFF * 2) * 2)   // 55296 bytes

__global__ void __launch_bounds__(128, 4) attn_kernel() {
    extern __shared__ __half sma[];
    __half (*Ks)[72] = (__half(*)[72])sma;             // [3*64][72]
    __half (*Vs)[72] = (__half(*)[72])(sma + AVS_OFF); // [3*64][72]

    int bh = blockIdx.y;
    int qt = gridDim.x - 1 - blockIdx.x;   // heavy q-tiles first
    int t0 = qt * AQ;
    int tid = threadIdx.x;
    int lane = tid & 31, w = tid >> 5;
    int g = lane >> 2, tq = lane & 3;
    int wq = w * 16;
    int mi = lane >> 3, mrow = lane & 7;
    int mb = mi & 1, sb = mi >> 1;

    const __half* qb = g_qh + ((size_t)bh * T + t0) * HD;
    const __half* kb = g_kh + (size_t)bh * T * HD;
    const __half* vb = g_vh + (size_t)bh * T * HD;

    unsigned qf[4][4];
#pragma unroll
    for (int ks = 0; ks < 4; ks++) {
        qf[ks][0] = *(const unsigned*)&qb[(size_t)(wq + g) * HD + ks * 16 + 2 * tq];
        qf[ks][1] = *(const unsigned*)&qb[(size_t)(wq + g + 8) * HD + ks * 16 + 2 * tq];
        qf[ks][2] = *(const unsigned*)&qb[(size_t)(wq + g) * HD + ks * 16 + 2 * tq + 8];
        qf[ks][3] = *(const unsigned*)&qb[(size_t)(wq + g + 8) * HD + ks * 16 + 2 * tq + 8];
    }

    float m0 = -1e30f, m1 = -1e30f, l0 = 0.f, l1 = 0.f;
    float accO[8][4] = {};

    int ntiles = qt + 1;   // keys 0 .. t0+63

    // prologue: prefetch tiles 0 and (if present) 1
#pragma unroll
    for (int it = 0; it < 4; it++) {
        int f = tid + it * 128;
        int r = f >> 3, c8 = f & 7;
        cp16(&Ks[r][c8 * 8], &kb[(size_t)r * HD + c8 * 8]);
        cp16(&Vs[r][c8 * 8], &vb[(size_t)r * HD + c8 * 8]);
    }
    CP_COMMIT;
    if (ntiles > 1) {
#pragma unroll
        for (int it = 0; it < 4; it++) {
            int f = tid + it * 128;
            int r = f >> 3, c8 = f & 7;
            cp16(&Ks[64 + r][c8 * 8], &kb[(size_t)(AK + r) * HD + c8 * 8]);
            cp16(&Vs[64 + r][c8 * 8], &vb[(size_t)(AK + r) * HD + c8 * 8]);
        }
        CP_COMMIT;
    }

    for (int itile = 0; itile < ntiles; itile++) {
        int buf = itile % 3;
        int s0 = itile * AK;
        if (itile + 1 < ntiles) CP_WAIT(1); else CP_WAIT(0);  // tile itile resident
        __syncthreads();                                      // slot (itile+2)%3 free
        if (itile + 2 < ntiles) {
            int sn0 = (itile + 2) * AK, b2 = (itile + 2) % 3;
#pragma unroll
            for (int it = 0; it < 4; it++) {
                int f = tid + it * 128;
                int r = f >> 3, c8 = f & 7;
                cp16(&Ks[b2 * 64 + r][c8 * 8], &kb[(size_t)(sn0 + r) * HD + c8 * 8]);
                cp16(&Vs[b2 * 64 + r][c8 * 8], &vb[(size_t)(sn0 + r) * HD + c8 * 8]);
            }
            CP_COMMIT;
        }

        // S = Q * K^T  (log2-domain scores)
        float sc[8][4] = {};
#pragma unroll
        for (int ks = 0; ks < 4; ks++) {
#pragma unroll
            for (int snp = 0; snp < 4; snp++) {
                unsigned b0, b1, b2, b3;
                ldsm4(b0, b1, b2, b3,
                      &Ks[buf * 64 + snp * 16 + sb * 8 + mrow][ks * 16 + mb * 8]);
                unsigned bb0[2] = {b0, b1}, bb1[2] = {b2, b3};
                mma_f16(sc[snp * 2], qf[ks], bb0);
                mma_f16(sc[snp * 2 + 1], qf[ks], bb1);
            }
        }

        // causal mask on the diagonal tile
        if (itile == ntiles - 1) {
            int r0 = t0 + wq + g, r1 = r0 + 8;
#pragma unroll
            for (int sn = 0; sn < 8; sn++) {
                int c0 = s0 + sn * 8 + tq * 2, c1 = c0 + 1;
                if (c0 > r0) sc[sn][0] = -1e30f;
                if (c1 > r0) sc[sn][1] = -1e30f;
                if (c0 > r1) sc[sn][2] = -1e30f;
                if (c1 > r1) sc[sn][3] = -1e30f;
            }
        }

        // running max (fp32) with quad shfl reduce
        float rx0 = -1e30f, rx1 = -1e30f;
#pragma unroll
        for (int sn = 0; sn < 8; sn++) {
            rx0 = fmaxf(rx0, fmaxf(sc[sn][0], sc[sn][1]));
            rx1 = fmaxf(rx1, fmaxf(sc[sn][2], sc[sn][3]));
        }
        rx0 = fmaxf(rx0, __shfl_xor_sync(0xffffffffu, rx0, 1));
        rx0 = fmaxf(rx0, __shfl_xor_sync(0xffffffffu, rx0, 2));
        rx1 = fmaxf(rx1, __shfl_xor_sync(0xffffffffu, rx1, 1));
        rx1 = fmaxf(rx1, __shfl_xor_sync(0xffffffffu, rx1, 2));
        float mn0 = fmaxf(m0, rx0), mn1 = fmaxf(m1, rx1);
        float corr0 = ex2f(m0 - mn0), corr1 = ex2f(m1 - mn1);
        m0 = mn0; m1 = mn1;

        // p = 2^(s-m) in fp16x2, directly in PV A-fragment registers
        unsigned p0h[8], p1h[8];
#pragma unroll
        for (int sn = 0; sn < 8; sn++) {
            p0h[sn] = h2ex2(f2h2(sc[sn][0] - mn0, sc[sn][1] - mn0));
            p1h[sn] = h2ex2(f2h2(sc[sn][2] - mn1, sc[sn][3] - mn1));
        }

        // row sums via MMA against all-ones B fragment
        const unsigned ONE2 = 0x3C003C00u;
        unsigned onesb[2] = {ONE2, ONE2};
        float rsacc[4] = {0.f, 0.f, 0.f, 0.f};
#pragma unroll
        for (int kc = 0; kc < 4; kc++) {
            unsigned af[4] = {p0h[2 * kc], p1h[2 * kc], p0h[2 * kc + 1], p1h[2 * kc + 1]};
            mma_f16(rsacc, af, onesb);
        }
        l0 = l0 * corr0 + rsacc[0];
        l1 = l1 * corr1 + rsacc[2];
#pragma unroll
        for (int sn = 0; sn < 8; sn++) {
            accO[sn][0] *= corr0; accO[sn][1] *= corr0;
            accO[sn][2] *= corr1; accO[sn][3] *= corr1;
        }

        // O += P * V
#pragma unroll
        for (int kc = 0; kc < 4; kc++) {
            unsigned af[4] = {p0h[2 * kc], p1h[2 * kc], p0h[2 * kc + 1], p1h[2 * kc + 1]};
#pragma unroll
            for (int snp = 0; snp < 4; snp++) {
                unsigned b0, b1, b2, b3;
                ldsm4t(b0, b1, b2, b3,
                       &Vs[buf * 64 + kc * 16 + mb * 8 + mrow][(snp * 2 + sb) * 8]);
                unsigned bb0[2] = {b0, b1}, bb1[2] = {b2, b3};
                mma_f16(accO[snp * 2], af, bb0);
                mma_f16(accO[snp * 2 + 1], af, bb1);
            }
        }
    }

    // epilogue: normalize, write fp16 to [B,T,H*HD]
    float inv0 = 1.f / l0, inv1 = 1.f / l1;
    int b = bh >> 4, h = bh & 15;
    __half* o0 = g_oh + ((size_t)b * T + t0 + wq + g) * C + h * HD;
    __half* o1 = o0 + (size_t)8 * C;
#pragma unroll
    for (int sn = 0; sn < 8; sn++) {
        int cc = sn * 8 + tq * 2;
        *(unsigned*)&o0[cc] = f2h2(accO[sn][0] * inv0, accO[sn][1] * inv0);
        *(unsigned*)&o1[cc] = f2h2(accO[sn][2] * inv1, accO[sn][3] * inv1);
    }
}

// ---------------------------------------------------------------------------
// Kernel 3: output projection [4096 x 1024 x 1024], 3-stage, 128x128 tiles.
// ---------------------------------------------------------------------------
__global__ void __launch_bounds__(256) proj_kernel(
    const float* __restrict__ bo, float* __restrict__ Y)
{
    extern __shared__ __half smg[];
    __half (*As)[72]  = (__half(*)[72])smg;
    __half (*Bs)[136] = (__half(*)[136])(smg + GB_OFF);

    int n0 = blockIdx.x * 128;
    int m0 = blockIdx.y * 128;

    const __half* A = g_oh + (size_t)m0 * C;
    const __half* Bp = g_woth + n0;

    int tid = threadIdx.x;
    int lane = tid & 31, w = tid >> 5;
    int g = lane >> 2, tq = lane & 3;
    int wm = (w & 3) * 32, wn = (w >> 2) * 64;
    int mi = lane >> 3, mrow = lane & 7;
    int mb = mi & 1, kb = mi >> 1;

    float acc[2][8][4] = {};

    const int NC = C / 64;
#pragma unroll
    for (int pc = 0; pc < 2; pc++) {
        int k0 = pc * 64;
#pragma unroll
        for (int it = 0; it < 4; it++) {
            int f = tid + it * 256;
            int r = f >> 3, c8 = f & 7;
            cp16(&As[pc * 128 + r][c8 * 8], &A[(size_t)r * C + k0 + c8 * 8]);
        }
#pragma unroll
        for (int it = 0; it < 4; it++) {
            int f = tid + it * 256;
            int r = f >> 4, c8 = f & 15;
            cp16(&Bs[pc * 64 + r][c8 * 8], &Bp[(size_t)(k0 + r) * C + c8 * 8]);
        }
        CP_COMMIT;
    }

    for (int c = 0; c < NC; c++) {
        int st = c % 3;
        if (c + 1 < NC) CP_WAIT(1); else CP_WAIT(0);
        __syncthreads();
        if (c + 2 < NC) {
            int k0 = (c + 2) * 64, s2 = (c + 2) % 3;
#pragma unroll
            for (int it = 0; it < 4; it++) {
                int f = tid + it * 256;
                int r = f >> 3, c8 = f & 7;
                cp16(&As[s2 * 128 + r][c8 * 8], &A[(size_t)r * C + k0 + c8 * 8]);
            }
#pragma unroll
            for (int it = 0; it < 4; it++) {
                int f = tid + it * 256;
                int r = f >> 4, c8 = f & 15;
                cp16(&Bs[s2 * 64 + r][c8 * 8], &Bp[(size_t)(k0 + r) * C + c8 * 8]);
            }
            CP_COMMIT;
        }

#pragma unroll
        for (int ks = 0; ks < 4; ks++) {
            unsigned af[2][4], bf[8][2];
#pragma unroll
            for (int sm = 0; sm < 2; sm++)
                ldsm4(af[sm][0], af[sm][1], af[sm][2], af[sm][3],
                      &As[st * 128 + wm + sm * 16 + mb * 8 + mrow][ks * 16 + kb * 8]);
#pragma unroll
            for (int snp = 0; snp < 4; snp++)
                ldsm4t(bf[snp * 2][0], bf[snp * 2][1], bf[snp * 2 + 1][0], bf[snp * 2 + 1][1],
                       &Bs[st * 64 + ks * 16 + mb * 8 + mrow][wn + snp * 16 + kb * 8]);
#pragma unroll
            for (int sm = 0; sm < 2; sm++)
#pragma unroll
                for (int sn = 0; sn < 8; sn++)
                    mma_f16(acc[sm][sn], af[sm], bf[sn]);
        }
    }

#pragma unroll
    for (int sm = 0; sm < 2; sm++) {
        int r0 = m0 + wm + sm * 16 + g;
#pragma unroll
        for (int sn = 0; sn < 8; sn++) {
            int cc = n0 + wn + sn * 8 + tq * 2;
            float b0 = bo[cc], b1 = bo[cc + 1];
            *(float2*)&Y[(size_t)r0 * C + cc] =
                make_float2(acc[sm][sn][0] + b0, acc[sm][sn][1] + b1);
            *(float2*)&Y[(size_t)(r0 + 8) * C + cc] =
                make_float2(acc[sm][sn][2] + b0, acc[sm][sn][3] + b1);
        }
    }
}

// ---------------------------------------------------------------------------
extern "C" void kernel_launch(void* const* d_in, const int* in_sizes, int n_in,
                              void* d_out, int out_size)
{
    const float* x  = (const float*)d_in[0];
    const float* Wq = (const float*)d_in[1];
    const float* Wk = (const float*)d_in[2];
    const float* Wv = (const float*)d_in[3];
    const float* Wo = (const float*)d_in[4];
    const float* bo = (const float*)d_in[5];
    float* y = (float*)d_out;

    static bool attr_done = false;
    if (!attr_done) {
        cudaFuncSetAttribute(qkv_kernel,
                             cudaFuncAttributeMaxDynamicSharedMemorySize, GEMM_SMEM);
        cudaFuncSetAttribute(proj_kernel,
                             cudaFuncAttributeMaxDynamicSharedMemorySize, GEMM_SMEM);
        cudaFuncSetAttribute(attn_kernel,
                             cudaFuncAttributeMaxDynamicSharedMemorySize, ATTN_SMEM);
        attr_done = true;
    }

    prep_kernel<<<dim3(4096, 5), 256>>>(x, Wq, Wk, Wv, Wo);
    qkv_kernel<<<dim3(N3 / 128, (B * T) / 128), 256, GEMM_SMEM>>>();
    attn_kernel<<<dim3(T / AQ, BH), 128, ATTN_SMEM>>>();
    proj_kernel<<<dim3(C / 128, (B * T) / 128), 256, GEMM_SMEM>>>(bo, y);
}